// round 2
// baseline (speedup 1.0000x reference)
#include <cuda_runtime.h>
#include <math.h>

#define N_NODES 10000
#define N_EDGES 160000
#define HDIM 512
#define NREL 2
#define NBASES 30
#define KDIM 1536  // 2*H (relation messages) + H (root)

// ---------------- scratch (static device globals; no allocs) ----------------
__device__ float g_W[KDIM * HDIM];                  // concat weight, (K x N) row-major
__device__ float g_A[(size_t)N_NODES * KDIM];       // concat activations [S0 | S1 | x]
__device__ float g_H[(size_t)N_NODES * HDIM];       // layer-1 output (post relu)
__device__ float g_Gate[N_NODES * NREL];            // sigmoid gates per (node, rel)

// ---------------- kernel 1: W_cat[k,n] = att-combined bases + root ----------
__global__ void build_W_kernel(const float* __restrict__ basis,
                               const float* __restrict__ att,
                               const float* __restrict__ root) {
  int idx = blockIdx.x * blockDim.x + threadIdx.x;
  if (idx >= KDIM * HDIM) return;
  int k = idx >> 9;          // row in K
  int n = idx & (HDIM - 1);  // col in N
  float v;
  if (k < 2 * HDIM) {
    int r = k >> 9;
    int i = k & (HDIM - 1);
    float acc = 0.f;
#pragma unroll
    for (int b = 0; b < NBASES; b++)
      acc += att[r * NBASES + b] * basis[(size_t)b * HDIM * HDIM + i * HDIM + n];
    v = acc;
  } else {
    v = root[(k - 2 * HDIM) * HDIM + n];
  }
  g_W[idx] = v;
}

// ---------------- kernel 2: per-node gates for both relations ---------------
// x may be the external input (layer 1) or g_H (layer 2), selected by flag.
template <bool FROM_GH>
__global__ void gate_kernel(const float* __restrict__ xin,
                            const float* __restrict__ gw) {
  const float* x = FROM_GH ? g_H : xin;
  __shared__ float s_gw[NREL * HDIM];
  for (int i = threadIdx.x; i < NREL * HDIM; i += blockDim.x) s_gw[i] = gw[i];
  __syncthreads();
  int warp = (blockIdx.x * blockDim.x + threadIdx.x) >> 5;
  int lane = threadIdx.x & 31;
  if (warp >= N_NODES) return;
  const float4* xr = (const float4*)(x + (size_t)warp * HDIM);
  float d0 = 0.f, d1 = 0.f;
#pragma unroll
  for (int j = 0; j < 4; j++) {
    int c = lane + j * 32;
    float4 xv = xr[c];
    int base = c * 4;
    d0 += xv.x * s_gw[base] + xv.y * s_gw[base + 1] + xv.z * s_gw[base + 2] + xv.w * s_gw[base + 3];
    d1 += xv.x * s_gw[HDIM + base] + xv.y * s_gw[HDIM + base + 1] +
          xv.z * s_gw[HDIM + base + 2] + xv.w * s_gw[HDIM + base + 3];
  }
#pragma unroll
  for (int off = 16; off; off >>= 1) {
    d0 += __shfl_xor_sync(0xffffffffu, d0, off);
    d1 += __shfl_xor_sync(0xffffffffu, d1, off);
  }
  if (lane == 0) {
    g_Gate[warp * 2 + 0] = 1.f / (1.f + expf(-d0));
    g_Gate[warp * 2 + 1] = 1.f / (1.f + expf(-d1));
  }
}

// ---------------- kernel 3: A = [0 | 0 | x] -------------------------------
template <bool FROM_GH>
__global__ void init_A_kernel(const float* __restrict__ xin) {
  const float* x = FROM_GH ? g_H : xin;
  size_t idx = (size_t)blockIdx.x * blockDim.x + threadIdx.x;  // over float4s
  const size_t total = (size_t)N_NODES * (KDIM / 4);
  if (idx >= total) return;
  int n = (int)(idx / (KDIM / 4));
  int c = (int)(idx % (KDIM / 4));
  float4 v;
  if (c < 2 * HDIM / 4) v = make_float4(0.f, 0.f, 0.f, 0.f);
  else v = ((const float4*)x)[(size_t)n * (HDIM / 4) + (c - 2 * HDIM / 4)];
  ((float4*)g_A)[idx] = v;
}

// ---------------- kernel 4: edge scatter into A[:, 0:1024] ------------------
__device__ __forceinline__ void red_add_f4(float4* p, float4 v) {
  asm volatile("red.global.add.v4.f32 [%0], {%1, %2, %3, %4};"
               :: "l"(p), "f"(v.x), "f"(v.y), "f"(v.z), "f"(v.w)
               : "memory");
}

template <bool FROM_GH>
__global__ void scatter_kernel(const float* __restrict__ xin,
                               const int* __restrict__ edge_index,
                               const int* __restrict__ edge_type) {
  const float* x = FROM_GH ? g_H : xin;
  int e = blockIdx.x * (blockDim.x >> 5) + (threadIdx.x >> 5);
  int lane = threadIdx.x & 31;
  if (e >= N_EDGES) return;
  int row = edge_index[e];            // aggregate target
  int col = edge_index[N_EDGES + e];  // source node (x_j)
  int t = edge_type[e];
  float g = g_Gate[col * 2 + t];
  const float4* xs = (const float4*)(x + (size_t)col * HDIM);
  float4* dst = (float4*)(g_A + (size_t)row * KDIM + t * HDIM);
#pragma unroll
  for (int j = 0; j < 4; j++) {
    float4 v = xs[lane + j * 32];
    v.x *= g; v.y *= g; v.z *= g; v.w *= g;
    red_add_f4(dst + lane + j * 32, v);
  }
}

// ---------------- kernel 5: C = A (M x 1536) @ W (1536 x 512) + bias --------
// TO_GH: write relu(result) into g_H (layer 1). Otherwise write to C (layer 2).
template <bool TO_GH>
__global__ void sgemm_kernel(const float* __restrict__ bias, float* __restrict__ Cext) {
  constexpr int BM = 128, BN = 128, BK = 8, TM = 8, TN = 8;
  constexpr int K = KDIM, N = HDIM, M = N_NODES;
  float* C = TO_GH ? g_H : Cext;
  __shared__ float As[BK][BM];
  __shared__ float Bs[BK][BN];
  int tid = threadIdx.x;
  int cRow = blockIdx.y, cCol = blockIdx.x;
  int threadRow = tid / (BN / TN);   // 0..15
  int threadCol = tid % (BN / TN);   // 0..15
  int innerRowA = tid >> 1;          // 0..127
  int innerColA = (tid & 1) * 4;     // 0 or 4
  int innerRowB = tid >> 5;          // 0..7
  int innerColB = (tid & 31) * 4;    // 0..124
  int gRowA = cRow * BM + innerRowA;
  const float* Aptr = g_A + (size_t)gRowA * K;
  const float* Bptr = g_W + cCol * BN;
  float acc[TM][TN] = {};
  float regM[TM], regN[TN];
  for (int k0 = 0; k0 < K; k0 += BK) {
    float4 av = make_float4(0.f, 0.f, 0.f, 0.f);
    if (gRowA < M) av = *(const float4*)(Aptr + k0 + innerColA);
    As[innerColA + 0][innerRowA] = av.x;
    As[innerColA + 1][innerRowA] = av.y;
    As[innerColA + 2][innerRowA] = av.z;
    As[innerColA + 3][innerRowA] = av.w;
    *(float4*)&Bs[innerRowB][innerColB] =
        *(const float4*)(Bptr + (size_t)(k0 + innerRowB) * N + innerColB);
    __syncthreads();
#pragma unroll
    for (int k = 0; k < BK; k++) {
#pragma unroll
      for (int i = 0; i < TM; i++) regM[i] = As[k][threadRow * TM + i];
#pragma unroll
      for (int j = 0; j < TN; j++) regN[j] = Bs[k][threadCol * TN + j];
#pragma unroll
      for (int i = 0; i < TM; i++)
#pragma unroll
        for (int j = 0; j < TN; j++)
          acc[i][j] += regM[i] * regN[j];
    }
    __syncthreads();
  }
#pragma unroll
  for (int i = 0; i < TM; i++) {
    int m = cRow * BM + threadRow * TM + i;
    if (m >= M) break;
    float* crow = C + (size_t)m * N + cCol * BN + threadCol * TN;
    const float* brow = bias + cCol * BN + threadCol * TN;
#pragma unroll
    for (int j = 0; j < TN; j++) {
      float v = acc[i][j] + brow[j];
      if (TO_GH) v = fmaxf(v, 0.f);
      crow[j] = v;
    }
  }
}

// ---------------- launch ----------------------------------------------------
extern "C" void kernel_launch(void* const* d_in, const int* in_sizes, int n_in,
                              void* d_out, int out_size) {
  const float* x        = (const float*)d_in[0];
  const int* edge_index = (const int*)d_in[1];
  const int* edge_type  = (const int*)d_in[2];
  const float* basis1   = (const float*)d_in[3];
  const float* att1     = (const float*)d_in[4];
  const float* gw1      = (const float*)d_in[5];
  const float* root1    = (const float*)d_in[6];
  const float* bias1    = (const float*)d_in[7];
  const float* basis2   = (const float*)d_in[8];
  const float* att2     = (const float*)d_in[9];
  const float* gw2      = (const float*)d_in[10];
  const float* root2    = (const float*)d_in[11];
  const float* bias2    = (const float*)d_in[12];
  float* out = (float*)d_out;

  dim3 gemmGrid(HDIM / 128, (N_NODES + 127) / 128);
  int wBlocks = (KDIM * HDIM + 255) / 256;
  int gateBlocks = (N_NODES + 7) / 8;
  int aBlocks = (int)(((size_t)N_NODES * (KDIM / 4) + 255) / 256);
  int eBlocks = (N_EDGES + 7) / 8;

  // ---- layer 1 (source = x) ----
  build_W_kernel<<<wBlocks, 256>>>(basis1, att1, root1);
  gate_kernel<false><<<gateBlocks, 256>>>(x, gw1);
  init_A_kernel<false><<<aBlocks, 256>>>(x);
  scatter_kernel<false><<<eBlocks, 256>>>(x, edge_index, edge_type);
  sgemm_kernel<true><<<gemmGrid, 256>>>(bias1, nullptr);   // -> g_H (relu)

  // ---- layer 2 (source = g_H) ----
  build_W_kernel<<<wBlocks, 256>>>(basis2, att2, root2);
  gate_kernel<true><<<gateBlocks, 256>>>(nullptr, gw2);
  init_A_kernel<true><<<aBlocks, 256>>>(nullptr);
  scatter_kernel<true><<<eBlocks, 256>>>(nullptr, edge_index, edge_type);
  sgemm_kernel<false><<<gemmGrid, 256>>>(bias2, out);
}

// round 6
// speedup vs baseline: 2.3691x; 2.3691x over previous
#include <cuda_runtime.h>
#include <cuda_bf16.h>
#include <cstdint>
#include <math.h>

#define N_NODES 10000
#define N_EDGES 160000
#define HDIM 512
#define NREL 2
#define NBASES 30
#define KDIM 1536          // [S0 | S1 | x] fp32 activation width
#define KA 3072            // bf16 A cols: [hi(1536) | lo(1536)]
#define KB 4608            // bf16 Wt cols: [Wh | Wh | Wl]
#define MTILES 79
#define MPAD (MTILES * 128) // 10112

// ---------------- scratch (static device globals; no allocs) ----------------
__device__ float g_A[(size_t)N_NODES * KDIM];
__device__ float g_H[(size_t)N_NODES * HDIM];
__device__ float g_Gate[N_NODES * NREL];
__device__ __align__(256) __nv_bfloat16 g_Abf[(size_t)MPAD * KA];  // pad rows stay 0 (.bss)
__device__ __align__(256) __nv_bfloat16 g_Wt[(size_t)HDIM * KB];

// ============================ PTX helpers (sm_100 base ISA only) =============
__device__ __forceinline__ uint32_t smem_u32(const void* p) {
  uint32_t a;
  asm("{ .reg .u64 t; cvta.to.shared.u64 t, %1; cvt.u32.u64 %0, t; }" : "=r"(a) : "l"(p));
  return a;
}
__device__ __forceinline__ void cp_async16(uint32_t s, const void* g) {
  asm volatile("cp.async.cg.shared.global [%0], [%1], 16;" :: "r"(s), "l"(g));
}
#define CP_COMMIT() asm volatile("cp.async.commit_group;")
template <int N> __device__ __forceinline__ void cp_wait() {
  asm volatile("cp.async.wait_group %0;" :: "n"(N));
}

#define SWZ(o) ((o) ^ (((o) >> 3) & 0x70))

__device__ __forceinline__ void ldsm_x4(uint32_t* r, uint32_t addr) {
  asm volatile("ldmatrix.sync.aligned.m8n8.x4.shared.b16 {%0,%1,%2,%3}, [%4];"
               : "=r"(r[0]), "=r"(r[1]), "=r"(r[2]), "=r"(r[3]) : "r"(addr));
}
__device__ __forceinline__ void mma_bf16(float* c, const uint32_t* a, const uint32_t* b) {
  asm volatile(
      "mma.sync.aligned.m16n8k16.row.col.f32.bf16.bf16.f32 "
      "{%0,%1,%2,%3}, {%4,%5,%6,%7}, {%8,%9}, {%0,%1,%2,%3};"
      : "+f"(c[0]), "+f"(c[1]), "+f"(c[2]), "+f"(c[3])
      : "r"(a[0]), "r"(a[1]), "r"(a[2]), "r"(a[3]), "r"(b[0]), "r"(b[1]));
}

// ================== kernel 1: Wt = bf16-split combined weights ==============
// Wt[n][k']: k'<1536 -> Wh[k][n]; 1536..3071 -> Wh again; 3072.. -> Wl[k][n]
__global__ void build_Wt_kernel(const float* __restrict__ basis,
                                const float* __restrict__ att,
                                const float* __restrict__ root) {
  int idx = blockIdx.x * blockDim.x + threadIdx.x;
  if (idx >= KDIM * HDIM) return;
  int k = idx >> 9;
  int n = idx & (HDIM - 1);
  float v;
  if (k < NREL * HDIM) {
    int r = k >> 9;
    int i = k & (HDIM - 1);
    float acc = 0.f;
#pragma unroll
    for (int b = 0; b < NBASES; b++)
      acc += att[r * NBASES + b] * basis[(size_t)b * HDIM * HDIM + i * HDIM + n];
    v = acc;
  } else {
    v = root[(k - NREL * HDIM) * HDIM + n];
  }
  __nv_bfloat16 hi = __float2bfloat16(v);
  __nv_bfloat16 lo = __float2bfloat16(v - __bfloat162float(hi));
  size_t base = (size_t)n * KB + k;
  g_Wt[base] = hi;
  g_Wt[base + 1536] = hi;
  g_Wt[base + 3072] = lo;
}

// ================== kernel 2: per-node gates =================================
template <bool FROM_GH>
__global__ void gate_kernel(const float* __restrict__ xin,
                            const float* __restrict__ gw) {
  const float* x = FROM_GH ? g_H : xin;
  __shared__ float s_gw[NREL * HDIM];
  for (int i = threadIdx.x; i < NREL * HDIM; i += blockDim.x) s_gw[i] = gw[i];
  __syncthreads();
  int warp = (blockIdx.x * blockDim.x + threadIdx.x) >> 5;
  int lane = threadIdx.x & 31;
  if (warp >= N_NODES) return;
  const float4* xr = (const float4*)(x + (size_t)warp * HDIM);
  float d0 = 0.f, d1 = 0.f;
#pragma unroll
  for (int j = 0; j < 4; j++) {
    int c = lane + j * 32;
    float4 xv = xr[c];
    int base = c * 4;
    d0 += xv.x * s_gw[base] + xv.y * s_gw[base + 1] + xv.z * s_gw[base + 2] + xv.w * s_gw[base + 3];
    d1 += xv.x * s_gw[HDIM + base] + xv.y * s_gw[HDIM + base + 1] +
          xv.z * s_gw[HDIM + base + 2] + xv.w * s_gw[HDIM + base + 3];
  }
#pragma unroll
  for (int off = 16; off; off >>= 1) {
    d0 += __shfl_xor_sync(0xffffffffu, d0, off);
    d1 += __shfl_xor_sync(0xffffffffu, d1, off);
  }
  if (lane == 0) {
    g_Gate[warp * 2 + 0] = 1.f / (1.f + expf(-d0));
    g_Gate[warp * 2 + 1] = 1.f / (1.f + expf(-d1));
  }
}

// ================== kernel 3: A = [0 | 0 | x] ================================
template <bool FROM_GH>
__global__ void init_A_kernel(const float* __restrict__ xin) {
  const float* x = FROM_GH ? g_H : xin;
  size_t idx = (size_t)blockIdx.x * blockDim.x + threadIdx.x;
  const size_t total = (size_t)N_NODES * (KDIM / 4);
  if (idx >= total) return;
  int n = (int)(idx / (KDIM / 4));
  int c = (int)(idx % (KDIM / 4));
  float4 v;
  if (c < 2 * HDIM / 4) v = make_float4(0.f, 0.f, 0.f, 0.f);
  else v = ((const float4*)x)[(size_t)n * (HDIM / 4) + (c - 2 * HDIM / 4)];
  ((float4*)g_A)[idx] = v;
}

// ================== kernel 4: edge scatter (fp32 atomics) ====================
__device__ __forceinline__ void red_add_f4(float4* p, float4 v) {
  asm volatile("red.global.add.v4.f32 [%0], {%1, %2, %3, %4};"
               :: "l"(p), "f"(v.x), "f"(v.y), "f"(v.z), "f"(v.w)
               : "memory");
}

template <bool FROM_GH>
__global__ void scatter_kernel(const float* __restrict__ xin,
                               const int* __restrict__ edge_index,
                               const int* __restrict__ edge_type) {
  const float* x = FROM_GH ? g_H : xin;
  int e = blockIdx.x * (blockDim.x >> 5) + (threadIdx.x >> 5);
  int lane = threadIdx.x & 31;
  if (e >= N_EDGES) return;
  int row = edge_index[e];
  int col = edge_index[N_EDGES + e];
  int t = edge_type[e];
  float g = g_Gate[col * 2 + t];
  const float4* xs = (const float4*)(x + (size_t)col * HDIM);
  float4* dst = (float4*)(g_A + (size_t)row * KDIM + t * HDIM);
#pragma unroll
  for (int j = 0; j < 4; j++) {
    float4 v = xs[lane + j * 32];
    v.x *= g; v.y *= g; v.z *= g; v.w *= g;
    red_add_f4(dst + lane + j * 32, v);
  }
}

// ================== kernel 5: Abf = bf16 hi/lo split of A ====================
__global__ void convertA_kernel() {
  size_t t = (size_t)blockIdx.x * blockDim.x + threadIdx.x;
  const size_t total = (size_t)N_NODES * (KDIM / 4);
  if (t >= total) return;
  int m = (int)(t / (KDIM / 4));
  int c4 = (int)(t % (KDIM / 4));
  float4 v = ((const float4*)g_A)[t];
  __nv_bfloat16 h0 = __float2bfloat16(v.x), h1 = __float2bfloat16(v.y);
  __nv_bfloat16 h2 = __float2bfloat16(v.z), h3 = __float2bfloat16(v.w);
  __nv_bfloat16 l0 = __float2bfloat16(v.x - __bfloat162float(h0));
  __nv_bfloat16 l1 = __float2bfloat16(v.y - __bfloat162float(h1));
  __nv_bfloat16 l2 = __float2bfloat16(v.z - __bfloat162float(h2));
  __nv_bfloat16 l3 = __float2bfloat16(v.w - __bfloat162float(h3));
  size_t base = (size_t)m * KA + c4 * 4;
  *(__nv_bfloat162*)&g_Abf[base + 0] = __nv_bfloat162(h0, h1);
  *(__nv_bfloat162*)&g_Abf[base + 2] = __nv_bfloat162(h2, h3);
  *(__nv_bfloat162*)&g_Abf[base + 1536 + 0] = __nv_bfloat162(l0, l1);
  *(__nv_bfloat162*)&g_Abf[base + 1536 + 2] = __nv_bfloat162(l2, l3);
}

// ================== kernel 6: mma.sync bf16 GEMM =============================
// C[128 x 128 tile] = Abf' @ Wt^T over K'=4608, fp32 accum, + bias (+relu).
// 2-stage cp.async pipeline; stage = A(16KB) + B(16KB) = 32KB; BK=64 halves.
constexpr int STAGE_BYTES = 32768;
constexpr int B_OFF = 16384;
constexpr int SMEM_GEMM = 2 * STAGE_BYTES;   // 64 KB
constexpr int NCHUNK = KB / 64;              // 72

__device__ __forceinline__ void load_chunk(uint32_t sbase, int tid, int m0, int n0, int c) {
  int kA = (c < 48 ? c : c - 48) * 64;  // [0,24): hi  [24,48): lo  [48,72): hi again
  int kB = c * 64;
#pragma unroll
  for (int it = 0; it < 8; ++it) {
    int u = tid + it * 256;            // 0..2047
    int row = (u >> 3) & 127;
    int col16 = u & 7;
    const __nv_bfloat16* src;
    uint32_t dst;
    if (u < 1024) {
      src = g_Abf + (size_t)(m0 + row) * KA + kA + col16 * 8;
      dst = sbase + SWZ(row * 128 + col16 * 16);
    } else {
      src = g_Wt + (size_t)(n0 + row) * KB + kB + col16 * 8;
      dst = sbase + B_OFF + SWZ(row * 128 + col16 * 16);
    }
    cp_async16(dst, (const void*)src);
  }
  CP_COMMIT();
}

template <bool TO_GH>
__global__ void __launch_bounds__(256, 2)
gemm_kernel(const float* __restrict__ bias, float* __restrict__ Cext) {
  extern __shared__ __align__(1024) char smem[];
  float* Cbase = TO_GH ? g_H : Cext;
  uint32_t sb = smem_u32(smem);
  const int tid = threadIdx.x;
  const int lane = tid & 31, wid = tid >> 5;
  const int wm = (wid & 1) * 64;      // warp M offset in tile (2 warps)
  const int wn = (wid >> 1) * 32;     // warp N offset in tile (4 warps)
  const int m0 = blockIdx.y * 128;
  const int n0 = blockIdx.x * 128;

  const int r8 = lane & 7, grp = lane >> 3;
  // A ldmatrix lane map: g0:(m+r,k0) g1:(m+8+r,k0) g2:(m+r,k+16B) g3:(m+8+r,k+16B)
  const int a_row_off = r8 + (grp & 1) * 8;
  const int a_kb_off = (grp >> 1) * 16;
  // B ldmatrix lane map: g0:(n+r,k0) g1:(n+r,k+16B) g2:(n+8+r,k0) g3:(n+8+r,k+16B)
  const int b_row_off = r8 + (grp >> 1) * 8;
  const int b_kb_off = (grp & 1) * 16;

  float acc[4][4][4] = {};

  load_chunk(sb, tid, m0, n0, 0);
  load_chunk(sb + STAGE_BYTES, tid, m0, n0, 1);

  for (int c = 0; c < NCHUNK; ++c) {
    uint32_t sbase = sb + (c & 1) * STAGE_BYTES;
    if (c == NCHUNK - 1) cp_wait<0>(); else cp_wait<1>();
    __syncthreads();
#pragma unroll
    for (int kk = 0; kk < 4; ++kk) {
      uint32_t af[4][4], bf[4][2];
#pragma unroll
      for (int mi = 0; mi < 4; ++mi) {
        int row = wm + mi * 16 + a_row_off;
        ldsm_x4(af[mi], sbase + SWZ(row * 128 + kk * 32 + a_kb_off));
      }
#pragma unroll
      for (int p = 0; p < 2; ++p) {
        int rowb = wn + p * 16 + b_row_off;
        uint32_t t4[4];
        ldsm_x4(t4, sbase + B_OFF + SWZ(rowb * 128 + kk * 32 + b_kb_off));
        bf[p * 2][0] = t4[0]; bf[p * 2][1] = t4[1];
        bf[p * 2 + 1][0] = t4[2]; bf[p * 2 + 1][1] = t4[3];
      }
#pragma unroll
      for (int mi = 0; mi < 4; ++mi)
#pragma unroll
        for (int ni = 0; ni < 4; ++ni)
          mma_bf16(acc[mi][ni], af[mi], bf[ni]);
    }
    __syncthreads();
    if (c + 2 < NCHUNK) load_chunk(sbase, tid, m0, n0, c + 2);
  }

  // ---- epilogue: C += bias (+relu) ----
  const int crow0 = m0 + wm + (lane >> 2);
  const int ccol0 = n0 + wn + (lane & 3) * 2;
#pragma unroll
  for (int ni = 0; ni < 4; ++ni) {
    int coln = ccol0 + ni * 8;
    float b0 = bias[coln], b1 = bias[coln + 1];
#pragma unroll
    for (int mi = 0; mi < 4; ++mi) {
      int rA = crow0 + mi * 16;
      int rB = rA + 8;
      float v0 = acc[mi][ni][0] + b0, v1 = acc[mi][ni][1] + b1;
      float v2 = acc[mi][ni][2] + b0, v3 = acc[mi][ni][3] + b1;
      if (TO_GH) {
        v0 = fmaxf(v0, 0.f); v1 = fmaxf(v1, 0.f);
        v2 = fmaxf(v2, 0.f); v3 = fmaxf(v3, 0.f);
      }
      if (rA < N_NODES) *(float2*)(Cbase + (size_t)rA * HDIM + coln) = make_float2(v0, v1);
      if (rB < N_NODES) *(float2*)(Cbase + (size_t)rB * HDIM + coln) = make_float2(v2, v3);
    }
  }
}

// ================== launch ===================================================
extern "C" void kernel_launch(void* const* d_in, const int* in_sizes, int n_in,
                              void* d_out, int out_size) {
  const float* x        = (const float*)d_in[0];
  const int* edge_index = (const int*)d_in[1];
  const int* edge_type  = (const int*)d_in[2];
  const float* basis1   = (const float*)d_in[3];
  const float* att1     = (const float*)d_in[4];
  const float* gw1      = (const float*)d_in[5];
  const float* root1    = (const float*)d_in[6];
  const float* bias1    = (const float*)d_in[7];
  const float* basis2   = (const float*)d_in[8];
  const float* att2     = (const float*)d_in[9];
  const float* gw2      = (const float*)d_in[10];
  const float* root2    = (const float*)d_in[11];
  const float* bias2    = (const float*)d_in[12];
  float* out = (float*)d_out;

  cudaFuncSetAttribute(gemm_kernel<true>,  cudaFuncAttributeMaxDynamicSharedMemorySize, SMEM_GEMM);
  cudaFuncSetAttribute(gemm_kernel<false>, cudaFuncAttributeMaxDynamicSharedMemorySize, SMEM_GEMM);

  dim3 gemmGrid(HDIM / 128, MTILES);
  int wBlocks = (KDIM * HDIM + 255) / 256;
  int gateBlocks = (N_NODES + 7) / 8;
  int aBlocks = (int)(((size_t)N_NODES * (KDIM / 4) + 255) / 256);
  int eBlocks = (N_EDGES + 7) / 8;

  // ---- layer 1 (source = x) ----
  build_Wt_kernel<<<wBlocks, 256>>>(basis1, att1, root1);
  gate_kernel<false><<<gateBlocks, 256>>>(x, gw1);
  init_A_kernel<false><<<aBlocks, 256>>>(x);
  scatter_kernel<false><<<eBlocks, 256>>>(x, edge_index, edge_type);
  convertA_kernel<<<aBlocks, 256>>>();
  gemm_kernel<true><<<gemmGrid, 256, SMEM_GEMM>>>(bias1, nullptr);   // -> g_H (relu)

  // ---- layer 2 (source = g_H) ----
  build_Wt_kernel<<<wBlocks, 256>>>(basis2, att2, root2);
  gate_kernel<true><<<gateBlocks, 256>>>(nullptr, gw2);
  init_A_kernel<true><<<aBlocks, 256>>>(nullptr);
  scatter_kernel<true><<<eBlocks, 256>>>(nullptr, edge_index, edge_type);
  convertA_kernel<<<aBlocks, 256>>>();
  gemm_kernel<false><<<gemmGrid, 256, SMEM_GEMM>>>(bias2, out);
}

// round 7
// speedup vs baseline: 2.6392x; 1.1140x over previous
#include <cuda_runtime.h>
#include <cuda_bf16.h>
#include <cstdint>
#include <math.h>

#define N_NODES 10000
#define N_EDGES 160000
#define HDIM 512
#define NREL 2
#define NBASES 30
#define KDIM 1536          // logical fp32 activation width [S0 | S1 | x]
#define KA 3072            // bf16 A cols: [hi(1536) | lo(1536)]
#define KB 4608            // bf16 Wt cols: [Wh | Wh | Wl]
#define NSEG (N_NODES * NREL)
#define MTILES 79
#define MPAD (MTILES * 128) // 10112

// ---------------- scratch (static device globals; no allocs) ----------------
__device__ float g_H[(size_t)N_NODES * HDIM];
__device__ float g_Gate[N_NODES * NREL];
__device__ int g_Cnt[NSEG];
__device__ int g_Off[NSEG + 1];
__device__ int g_ECol[N_EDGES];
__device__ __align__(256) __nv_bfloat16 g_Abf[(size_t)MPAD * KA];  // pad rows stay 0 (.bss)
__device__ __align__(256) __nv_bfloat16 g_Wt[(size_t)HDIM * KB];

// ============================ PTX helpers (sm_100 base ISA only) =============
__device__ __forceinline__ uint32_t smem_u32(const void* p) {
  uint32_t a;
  asm("{ .reg .u64 t; cvta.to.shared.u64 t, %1; cvt.u32.u64 %0, t; }" : "=r"(a) : "l"(p));
  return a;
}
__device__ __forceinline__ void cp_async16(uint32_t s, const void* g) {
  asm volatile("cp.async.cg.shared.global [%0], [%1], 16;" :: "r"(s), "l"(g));
}
#define CP_COMMIT() asm volatile("cp.async.commit_group;")
template <int N> __device__ __forceinline__ void cp_wait() {
  asm volatile("cp.async.wait_group %0;" :: "n"(N));
}

#define SWZ(o) ((o) ^ (((o) >> 3) & 0x70))

__device__ __forceinline__ void ldsm_x4(uint32_t* r, uint32_t addr) {
  asm volatile("ldmatrix.sync.aligned.m8n8.x4.shared.b16 {%0,%1,%2,%3}, [%4];"
               : "=r"(r[0]), "=r"(r[1]), "=r"(r[2]), "=r"(r[3]) : "r"(addr));
}
__device__ __forceinline__ void mma_bf16(float* c, const uint32_t* a, const uint32_t* b) {
  asm volatile(
      "mma.sync.aligned.m16n8k16.row.col.f32.bf16.bf16.f32 "
      "{%0,%1,%2,%3}, {%4,%5,%6,%7}, {%8,%9}, {%0,%1,%2,%3};"
      : "+f"(c[0]), "+f"(c[1]), "+f"(c[2]), "+f"(c[3])
      : "r"(a[0]), "r"(a[1]), "r"(a[2]), "r"(a[3]), "r"(b[0]), "r"(b[1]));
}

// ================== CSR build (once per launch) ==============================
__global__ void zero_cnt_kernel() {
  int i = blockIdx.x * blockDim.x + threadIdx.x;
  if (i < NSEG) g_Cnt[i] = 0;
}
__global__ void count_kernel(const int* __restrict__ edge_index,
                             const int* __restrict__ edge_type) {
  int e = blockIdx.x * blockDim.x + threadIdx.x;
  if (e >= N_EDGES) return;
  int seg = edge_index[e] * 2 + edge_type[e];
  atomicAdd(&g_Cnt[seg], 1);
}
__global__ void scan_kernel() {  // single block of 256 threads
  __shared__ int part[256];
  const int t = threadIdx.x;
  const int CH = (NSEG + 255) / 256;  // 79
  int s = 0;
  for (int i = 0; i < CH; ++i) {
    int idx = t * CH + i;
    if (idx < NSEG) s += g_Cnt[idx];
  }
  part[t] = s;
  __syncthreads();
  for (int off = 1; off < 256; off <<= 1) {
    int u = (t >= off) ? part[t - off] : 0;
    __syncthreads();
    part[t] += u;
    __syncthreads();
  }
  int run = part[t] - s;  // exclusive base for this thread's chunk
  for (int i = 0; i < CH; ++i) {
    int idx = t * CH + i;
    if (idx < NSEG) {
      g_Off[idx] = run;
      run += g_Cnt[idx];
      g_Cnt[idx] = 0;  // reset cursor for fill
    }
  }
  if (t == 255) g_Off[NSEG] = run;
}
__global__ void fill_kernel(const int* __restrict__ edge_index,
                            const int* __restrict__ edge_type) {
  int e = blockIdx.x * blockDim.x + threadIdx.x;
  if (e >= N_EDGES) return;
  int seg = edge_index[e] * 2 + edge_type[e];
  int pos = g_Off[seg] + atomicAdd(&g_Cnt[seg], 1);
  g_ECol[pos] = edge_index[N_EDGES + e];
}

// ================== kernel: Wt = bf16-split combined weights ================
// Wt[n][k']: k'<1536 -> Wh[k][n]; 1536..3071 -> Wh again; 3072.. -> Wl[k][n]
__global__ void build_Wt_kernel(const float* __restrict__ basis,
                                const float* __restrict__ att,
                                const float* __restrict__ root) {
  int idx = blockIdx.x * blockDim.x + threadIdx.x;
  if (idx >= KDIM * HDIM) return;
  int k = idx >> 9;
  int n = idx & (HDIM - 1);
  float v;
  if (k < NREL * HDIM) {
    int r = k >> 9;
    int i = k & (HDIM - 1);
    float acc = 0.f;
#pragma unroll
    for (int b = 0; b < NBASES; b++)
      acc += att[r * NBASES + b] * basis[(size_t)b * HDIM * HDIM + i * HDIM + n];
    v = acc;
  } else {
    v = root[(k - NREL * HDIM) * HDIM + n];
  }
  __nv_bfloat16 hi = __float2bfloat16(v);
  __nv_bfloat16 lo = __float2bfloat16(v - __bfloat162float(hi));
  size_t base = (size_t)n * KB + k;
  g_Wt[base] = hi;
  g_Wt[base + 1536] = hi;
  g_Wt[base + 3072] = lo;
}

// ================== kernel: per-node gates ===================================
template <bool FROM_GH>
__global__ void gate_kernel(const float* __restrict__ xin,
                            const float* __restrict__ gw) {
  const float* x = FROM_GH ? g_H : xin;
  __shared__ float s_gw[NREL * HDIM];
  for (int i = threadIdx.x; i < NREL * HDIM; i += blockDim.x) s_gw[i] = gw[i];
  __syncthreads();
  int warp = (blockIdx.x * blockDim.x + threadIdx.x) >> 5;
  int lane = threadIdx.x & 31;
  if (warp >= N_NODES) return;
  const float4* xr = (const float4*)(x + (size_t)warp * HDIM);
  float d0 = 0.f, d1 = 0.f;
#pragma unroll
  for (int j = 0; j < 4; j++) {
    int c = lane + j * 32;
    float4 xv = xr[c];
    int base = c * 4;
    d0 += xv.x * s_gw[base] + xv.y * s_gw[base + 1] + xv.z * s_gw[base + 2] + xv.w * s_gw[base + 3];
    d1 += xv.x * s_gw[HDIM + base] + xv.y * s_gw[HDIM + base + 1] +
          xv.z * s_gw[HDIM + base + 2] + xv.w * s_gw[HDIM + base + 3];
  }
#pragma unroll
  for (int off = 16; off; off >>= 1) {
    d0 += __shfl_xor_sync(0xffffffffu, d0, off);
    d1 += __shfl_xor_sync(0xffffffffu, d1, off);
  }
  if (lane == 0) {
    g_Gate[warp * 2 + 0] = 1.f / (1.f + expf(-d0));
    g_Gate[warp * 2 + 1] = 1.f / (1.f + expf(-d1));
  }
}

// ================== kernel: CSR gather -> bf16 hi/lo S-segments ==============
// warp per segment (node, rel): acc = sum_e gate[col_e, rel] * x[col_e]
// writes hi -> Abf[node][rel*512 + c], lo -> Abf[node][1536 + rel*512 + c]
template <bool FROM_GH>
__global__ void gather_kernel(const float* __restrict__ xin) {
  const float* x = FROM_GH ? g_H : xin;
  int seg = blockIdx.x * (blockDim.x >> 5) + (threadIdx.x >> 5);
  int lane = threadIdx.x & 31;
  if (seg >= NSEG) return;
  int node = seg >> 1, rel = seg & 1;
  int p = g_Off[seg], pe = g_Off[seg + 1];
  float4 a0 = {0, 0, 0, 0}, a1 = a0, a2 = a0, a3 = a0;
  for (; p < pe; ++p) {
    int col = g_ECol[p];
    float g = g_Gate[col * 2 + rel];
    const float4* xr = (const float4*)(x + (size_t)col * HDIM);
    float4 v0 = xr[lane], v1 = xr[lane + 32], v2 = xr[lane + 64], v3 = xr[lane + 96];
    a0.x += g * v0.x; a0.y += g * v0.y; a0.z += g * v0.z; a0.w += g * v0.w;
    a1.x += g * v1.x; a1.y += g * v1.y; a1.z += g * v1.z; a1.w += g * v1.w;
    a2.x += g * v2.x; a2.y += g * v2.y; a2.z += g * v2.z; a2.w += g * v2.w;
    a3.x += g * v3.x; a3.y += g * v3.y; a3.z += g * v3.z; a3.w += g * v3.w;
  }
  size_t base = (size_t)node * KA + rel * 512 + 4 * lane;
  float4 av[4] = {a0, a1, a2, a3};
#pragma unroll
  for (int j = 0; j < 4; ++j) {
    float4 v = av[j];
    __nv_bfloat16 h0 = __float2bfloat16(v.x), h1 = __float2bfloat16(v.y);
    __nv_bfloat16 h2 = __float2bfloat16(v.z), h3 = __float2bfloat16(v.w);
    __nv_bfloat16 l0 = __float2bfloat16(v.x - __bfloat162float(h0));
    __nv_bfloat16 l1 = __float2bfloat16(v.y - __bfloat162float(h1));
    __nv_bfloat16 l2 = __float2bfloat16(v.z - __bfloat162float(h2));
    __nv_bfloat16 l3 = __float2bfloat16(v.w - __bfloat162float(h3));
    __nv_bfloat162 hp0(h0, h1), hp1(h2, h3), lp0(l0, l1), lp1(l2, l3);
    uint2 hw, lw;
    hw.x = *(uint32_t*)&hp0; hw.y = *(uint32_t*)&hp1;
    lw.x = *(uint32_t*)&lp0; lw.y = *(uint32_t*)&lp1;
    *(uint2*)&g_Abf[base + j * 128] = hw;
    *(uint2*)&g_Abf[base + 1536 + j * 128] = lw;
  }
}

// ================== kernel: x hi/lo split into Abf cols [1024,1536) ==========
template <bool FROM_GH>
__global__ void xsplit_kernel(const float* __restrict__ xin) {
  const float* x = FROM_GH ? g_H : xin;
  size_t t = (size_t)blockIdx.x * blockDim.x + threadIdx.x;
  const size_t total = (size_t)N_NODES * (HDIM / 4);
  if (t >= total) return;
  int n = (int)(t / (HDIM / 4));
  int c4 = (int)(t % (HDIM / 4));
  float4 v = ((const float4*)x)[t];
  __nv_bfloat16 h0 = __float2bfloat16(v.x), h1 = __float2bfloat16(v.y);
  __nv_bfloat16 h2 = __float2bfloat16(v.z), h3 = __float2bfloat16(v.w);
  __nv_bfloat16 l0 = __float2bfloat16(v.x - __bfloat162float(h0));
  __nv_bfloat16 l1 = __float2bfloat16(v.y - __bfloat162float(h1));
  __nv_bfloat16 l2 = __float2bfloat16(v.z - __bfloat162float(h2));
  __nv_bfloat16 l3 = __float2bfloat16(v.w - __bfloat162float(h3));
  size_t base = (size_t)n * KA + 1024 + 4 * c4;
  __nv_bfloat162 hp0(h0, h1), hp1(h2, h3), lp0(l0, l1), lp1(l2, l3);
  uint2 hw, lw;
  hw.x = *(uint32_t*)&hp0; hw.y = *(uint32_t*)&hp1;
  lw.x = *(uint32_t*)&lp0; lw.y = *(uint32_t*)&lp1;
  *(uint2*)&g_Abf[base] = hw;
  *(uint2*)&g_Abf[base + 1536] = lw;
}

// ================== kernel: mma.sync bf16 GEMM ===============================
// C[128 x 128 tile] = Abf' @ Wt^T over K'=4608, fp32 accum, + bias (+relu).
// 3-stage cp.async pipeline; stage = A(16KB) + B(16KB) = 32KB; BK=64.
constexpr int STAGE_BYTES = 32768;
constexpr int B_OFF = 16384;
constexpr int SMEM_GEMM = 3 * STAGE_BYTES;   // 96 KB
constexpr int NCHUNK = KB / 64;              // 72

__device__ __forceinline__ void load_chunk(uint32_t sbase, int tid, int m0, int n0, int c) {
  int kA = (c < 48 ? c : c - 48) * 64;  // [0,24): hi  [24,48): lo  [48,72): hi again
  int kB = c * 64;
#pragma unroll
  for (int it = 0; it < 8; ++it) {
    int u = tid + it * 256;            // 0..2047
    int row = (u >> 3) & 127;
    int col16 = u & 7;
    const __nv_bfloat16* src;
    uint32_t dst;
    if (u < 1024) {
      src = g_Abf + (size_t)(m0 + row) * KA + kA + col16 * 8;
      dst = sbase + SWZ(row * 128 + col16 * 16);
    } else {
      src = g_Wt + (size_t)(n0 + row) * KB + kB + col16 * 8;
      dst = sbase + B_OFF + SWZ(row * 128 + col16 * 16);
    }
    cp_async16(dst, (const void*)src);
  }
  CP_COMMIT();
}

template <bool TO_GH>
__global__ void __launch_bounds__(256, 2)
gemm_kernel(const float* __restrict__ bias, float* __restrict__ Cext) {
  extern __shared__ __align__(1024) char smem[];
  float* Cbase = TO_GH ? g_H : Cext;
  uint32_t sb = smem_u32(smem);
  const int tid = threadIdx.x;
  const int lane = tid & 31, wid = tid >> 5;
  const int wm = (wid & 1) * 64;      // warp M offset in tile (2 warps)
  const int wn = (wid >> 1) * 32;     // warp N offset in tile (4 warps)
  const int m0 = blockIdx.y * 128;
  const int n0 = blockIdx.x * 128;

  const int r8 = lane & 7, grp = lane >> 3;
  const int a_row_off = r8 + (grp & 1) * 8;
  const int a_kb_off = (grp >> 1) * 16;
  const int b_row_off = r8 + (grp >> 1) * 8;
  const int b_kb_off = (grp & 1) * 16;

  float acc[4][4][4] = {};

  load_chunk(sb, tid, m0, n0, 0);
  load_chunk(sb + STAGE_BYTES, tid, m0, n0, 1);
  load_chunk(sb + 2 * STAGE_BYTES, tid, m0, n0, 2);

  for (int c = 0; c < NCHUNK; ++c) {
    uint32_t sbase = sb + (c % 3) * STAGE_BYTES;
    if (c <= NCHUNK - 3)      cp_wait<2>();
    else if (c == NCHUNK - 2) cp_wait<1>();
    else                      cp_wait<0>();
    __syncthreads();
#pragma unroll
    for (int kk = 0; kk < 4; ++kk) {
      uint32_t af[4][4], bf[4][2];
#pragma unroll
      for (int mi = 0; mi < 4; ++mi) {
        int row = wm + mi * 16 + a_row_off;
        ldsm_x4(af[mi], sbase + SWZ(row * 128 + kk * 32 + a_kb_off));
      }
#pragma unroll
      for (int p = 0; p < 2; ++p) {
        int rowb = wn + p * 16 + b_row_off;
        uint32_t t4[4];
        ldsm_x4(t4, sbase + B_OFF + SWZ(rowb * 128 + kk * 32 + b_kb_off));
        bf[p * 2][0] = t4[0]; bf[p * 2][1] = t4[1];
        bf[p * 2 + 1][0] = t4[2]; bf[p * 2 + 1][1] = t4[3];
      }
#pragma unroll
      for (int mi = 0; mi < 4; ++mi)
#pragma unroll
        for (int ni = 0; ni < 4; ++ni)
          mma_bf16(acc[mi][ni], af[mi], bf[ni]);
    }
    __syncthreads();
    if (c + 3 < NCHUNK) load_chunk(sbase, tid, m0, n0, c + 3);
  }

  // ---- epilogue: C += bias (+relu) ----
  const int crow0 = m0 + wm + (lane >> 2);
  const int ccol0 = n0 + wn + (lane & 3) * 2;
#pragma unroll
  for (int ni = 0; ni < 4; ++ni) {
    int coln = ccol0 + ni * 8;
    float b0 = bias[coln], b1 = bias[coln + 1];
#pragma unroll
    for (int mi = 0; mi < 4; ++mi) {
      int rA = crow0 + mi * 16;
      int rB = rA + 8;
      float v0 = acc[mi][ni][0] + b0, v1 = acc[mi][ni][1] + b1;
      float v2 = acc[mi][ni][2] + b0, v3 = acc[mi][ni][3] + b1;
      if (TO_GH) {
        v0 = fmaxf(v0, 0.f); v1 = fmaxf(v1, 0.f);
        v2 = fmaxf(v2, 0.f); v3 = fmaxf(v3, 0.f);
      }
      if (rA < N_NODES) *(float2*)(Cbase + (size_t)rA * HDIM + coln) = make_float2(v0, v1);
      if (rB < N_NODES) *(float2*)(Cbase + (size_t)rB * HDIM + coln) = make_float2(v2, v3);
    }
  }
}

// ================== launch ===================================================
extern "C" void kernel_launch(void* const* d_in, const int* in_sizes, int n_in,
                              void* d_out, int out_size) {
  const float* x        = (const float*)d_in[0];
  const int* edge_index = (const int*)d_in[1];
  const int* edge_type  = (const int*)d_in[2];
  const float* basis1   = (const float*)d_in[3];
  const float* att1     = (const float*)d_in[4];
  const float* gw1      = (const float*)d_in[5];
  const float* root1    = (const float*)d_in[6];
  const float* bias1    = (const float*)d_in[7];
  const float* basis2   = (const float*)d_in[8];
  const float* att2     = (const float*)d_in[9];
  const float* gw2      = (const float*)d_in[10];
  const float* root2    = (const float*)d_in[11];
  const float* bias2    = (const float*)d_in[12];
  float* out = (float*)d_out;

  cudaFuncSetAttribute(gemm_kernel<true>,  cudaFuncAttributeMaxDynamicSharedMemorySize, SMEM_GEMM);
  cudaFuncSetAttribute(gemm_kernel<false>, cudaFuncAttributeMaxDynamicSharedMemorySize, SMEM_GEMM);

  dim3 gemmGrid(HDIM / 128, MTILES);
  int wBlocks = (KDIM * HDIM + 255) / 256;
  int gateBlocks = (N_NODES + 7) / 8;
  int segBlocks = (NSEG + 7) / 8;
  int eBlocks = (N_EDGES + 255) / 256;
  int xsBlocks = (int)(((size_t)N_NODES * (HDIM / 4) + 255) / 256);

  // ---- CSR build (graph constant across both layers) ----
  zero_cnt_kernel<<<(NSEG + 255) / 256, 256>>>();
  count_kernel<<<eBlocks, 256>>>(edge_index, edge_type);
  scan_kernel<<<1, 256>>>();
  fill_kernel<<<eBlocks, 256>>>(edge_index, edge_type);

  // ---- layer 1 (source = x) ----
  build_Wt_kernel<<<wBlocks, 256>>>(basis1, att1, root1);
  gate_kernel<false><<<gateBlocks, 256>>>(x, gw1);
  gather_kernel<false><<<segBlocks, 256>>>(x);
  xsplit_kernel<false><<<xsBlocks, 256>>>(x);
  gemm_kernel<true><<<gemmGrid, 256, SMEM_GEMM>>>(bias1, nullptr);   // -> g_H (relu)

  // ---- layer 2 (source = g_H) ----
  build_Wt_kernel<<<wBlocks, 256>>>(basis2, att2, root2);
  gate_kernel<true><<<gateBlocks, 256>>>(nullptr, gw2);
  gather_kernel<true><<<segBlocks, 256>>>(nullptr);
  xsplit_kernel<true><<<xsBlocks, 256>>>(nullptr);
  gemm_kernel<false><<<gemmGrid, 256, SMEM_GEMM>>>(bias2, out);
}

// round 10
// speedup vs baseline: 2.9790x; 1.1288x over previous
#include <cuda_runtime.h>
#include <cuda_bf16.h>
#include <cstdint>
#include <math.h>

#define N_NODES 10000
#define N_EDGES 160000
#define HDIM 512
#define NREL 2
#define NBASES 30
#define KDIM 1536          // logical fp32 activation width [S0 | S1 | x]
#define KA 3072            // bf16 A cols: [hi(1536) | lo(1536)]
#define KB 4608            // bf16 Wt cols: [Wh | Wh | Wl]
#define NSEG (N_NODES * NREL)
#define MTILE 144
#define MT_TILES 74
#define MPAD (MT_TILES * MTILE)  // 10656

// ---------------- scratch (static device globals; no allocs) ----------------
__device__ float g_H[(size_t)N_NODES * HDIM];
__device__ float g_Gate[N_NODES * NREL];
__device__ int g_Cnt[NSEG];
__device__ int g_Off[NSEG + 1];
__device__ int g_ECol[N_EDGES];
__device__ __align__(256) __nv_bfloat16 g_Abf[(size_t)MPAD * KA];  // pad rows stay 0 (.bss)
__device__ __align__(256) __nv_bfloat16 g_Wt[(size_t)HDIM * KB];

// ============================ PTX helpers (sm_100 base ISA only) =============
__device__ __forceinline__ uint32_t smem_u32(const void* p) {
  uint32_t a;
  asm("{ .reg .u64 t; cvta.to.shared.u64 t, %1; cvt.u32.u64 %0, t; }" : "=r"(a) : "l"(p));
  return a;
}
__device__ __forceinline__ void cp_async16(uint32_t s, const void* g) {
  asm volatile("cp.async.cg.shared.global [%0], [%1], 16;" :: "r"(s), "l"(g));
}
#define CP_COMMIT() asm volatile("cp.async.commit_group;")
template <int N> __device__ __forceinline__ void cp_wait() {
  asm volatile("cp.async.wait_group %0;" :: "n"(N));
}

#define SWZ(o) ((o) ^ (((o) >> 3) & 0x70))

__device__ __forceinline__ void ldsm_x4(uint32_t* r, uint32_t addr) {
  asm volatile("ldmatrix.sync.aligned.m8n8.x4.shared.b16 {%0,%1,%2,%3}, [%4];"
               : "=r"(r[0]), "=r"(r[1]), "=r"(r[2]), "=r"(r[3]) : "r"(addr));
}
__device__ __forceinline__ void mma_bf16(float* c, const uint32_t* a, const uint32_t* b) {
  asm volatile(
      "mma.sync.aligned.m16n8k16.row.col.f32.bf16.bf16.f32 "
      "{%0,%1,%2,%3}, {%4,%5,%6,%7}, {%8,%9}, {%0,%1,%2,%3};"
      : "+f"(c[0]), "+f"(c[1]), "+f"(c[2]), "+f"(c[3])
      : "r"(a[0]), "r"(a[1]), "r"(a[2]), "r"(a[3]), "r"(b[0]), "r"(b[1]));
}

// ================== CSR build (once per launch) ==============================
__global__ void zero_cnt_kernel() {
  int i = blockIdx.x * blockDim.x + threadIdx.x;
  if (i < NSEG) g_Cnt[i] = 0;
}
__global__ void count_kernel(const int* __restrict__ edge_index,
                             const int* __restrict__ edge_type) {
  int e = blockIdx.x * blockDim.x + threadIdx.x;
  if (e >= N_EDGES) return;
  int seg = edge_index[e] * 2 + edge_type[e];
  atomicAdd(&g_Cnt[seg], 1);
}
__global__ void scan_kernel() {  // single block of 256 threads
  __shared__ int part[256];
  const int t = threadIdx.x;
  const int CH = (NSEG + 255) / 256;  // 79
  int s = 0;
  for (int i = 0; i < CH; ++i) {
    int idx = t * CH + i;
    if (idx < NSEG) s += g_Cnt[idx];
  }
  part[t] = s;
  __syncthreads();
  for (int off = 1; off < 256; off <<= 1) {
    int u = (t >= off) ? part[t - off] : 0;
    __syncthreads();
    part[t] += u;
    __syncthreads();
  }
  int run = part[t] - s;  // exclusive base for this thread's chunk
  for (int i = 0; i < CH; ++i) {
    int idx = t * CH + i;
    if (idx < NSEG) {
      g_Off[idx] = run;
      run += g_Cnt[idx];
      g_Cnt[idx] = 0;  // reset cursor for fill
    }
  }
  if (t == 255) g_Off[NSEG] = run;
}
__global__ void fill_kernel(const int* __restrict__ edge_index,
                            const int* __restrict__ edge_type) {
  int e = blockIdx.x * blockDim.x + threadIdx.x;
  if (e >= N_EDGES) return;
  int seg = edge_index[e] * 2 + edge_type[e];
  int pos = g_Off[seg] + atomicAdd(&g_Cnt[seg], 1);
  g_ECol[pos] = edge_index[N_EDGES + e];
}

// ================== kernel: Wt = bf16-split combined weights ================
__global__ void build_Wt_kernel(const float* __restrict__ basis,
                                const float* __restrict__ att,
                                const float* __restrict__ root) {
  int idx = blockIdx.x * blockDim.x + threadIdx.x;
  if (idx >= KDIM * HDIM) return;
  int k = idx >> 9;
  int n = idx & (HDIM - 1);
  float v;
  if (k < NREL * HDIM) {
    int r = k >> 9;
    int i = k & (HDIM - 1);
    float acc = 0.f;
#pragma unroll
    for (int b = 0; b < NBASES; b++)
      acc += att[r * NBASES + b] * basis[(size_t)b * HDIM * HDIM + i * HDIM + n];
    v = acc;
  } else {
    v = root[(k - NREL * HDIM) * HDIM + n];
  }
  __nv_bfloat16 hi = __float2bfloat16(v);
  __nv_bfloat16 lo = __float2bfloat16(v - __bfloat162float(hi));
  size_t base = (size_t)n * KB + k;
  g_Wt[base] = hi;
  g_Wt[base + 1536] = hi;
  g_Wt[base + 3072] = lo;
}

// ================== kernel: per-node gates ===================================
template <bool FROM_GH>
__global__ void gate_kernel(const float* __restrict__ xin,
                            const float* __restrict__ gw) {
  const float* x = FROM_GH ? g_H : xin;
  __shared__ float s_gw[NREL * HDIM];
  for (int i = threadIdx.x; i < NREL * HDIM; i += blockDim.x) s_gw[i] = gw[i];
  __syncthreads();
  int warp = (blockIdx.x * blockDim.x + threadIdx.x) >> 5;
  int lane = threadIdx.x & 31;
  if (warp >= N_NODES) return;
  const float4* xr = (const float4*)(x + (size_t)warp * HDIM);
  float d0 = 0.f, d1 = 0.f;
#pragma unroll
  for (int j = 0; j < 4; j++) {
    int c = lane + j * 32;
    float4 xv = xr[c];
    int base = c * 4;
    d0 += xv.x * s_gw[base] + xv.y * s_gw[base + 1] + xv.z * s_gw[base + 2] + xv.w * s_gw[base + 3];
    d1 += xv.x * s_gw[HDIM + base] + xv.y * s_gw[HDIM + base + 1] +
          xv.z * s_gw[HDIM + base + 2] + xv.w * s_gw[HDIM + base + 3];
  }
#pragma unroll
  for (int off = 16; off; off >>= 1) {
    d0 += __shfl_xor_sync(0xffffffffu, d0, off);
    d1 += __shfl_xor_sync(0xffffffffu, d1, off);
  }
  if (lane == 0) {
    g_Gate[warp * 2 + 0] = 1.f / (1.f + expf(-d0));
    g_Gate[warp * 2 + 1] = 1.f / (1.f + expf(-d1));
  }
}

// ================== kernel: CSR gather -> bf16 hi/lo S-segments ==============
template <bool FROM_GH>
__global__ void gather_kernel(const float* __restrict__ xin) {
  const float* x = FROM_GH ? g_H : xin;
  int seg = blockIdx.x * (blockDim.x >> 5) + (threadIdx.x >> 5);
  int lane = threadIdx.x & 31;
  if (seg >= NSEG) return;
  int node = seg >> 1, rel = seg & 1;
  int p = g_Off[seg], pe = g_Off[seg + 1];
  float4 a0 = {0, 0, 0, 0}, a1 = a0, a2 = a0, a3 = a0;
  for (; p < pe; ++p) {
    int col = g_ECol[p];
    float g = g_Gate[col * 2 + rel];
    const float4* xr = (const float4*)(x + (size_t)col * HDIM);
    float4 v0 = xr[lane], v1 = xr[lane + 32], v2 = xr[lane + 64], v3 = xr[lane + 96];
    a0.x += g * v0.x; a0.y += g * v0.y; a0.z += g * v0.z; a0.w += g * v0.w;
    a1.x += g * v1.x; a1.y += g * v1.y; a1.z += g * v1.z; a1.w += g * v1.w;
    a2.x += g * v2.x; a2.y += g * v2.y; a2.z += g * v2.z; a2.w += g * v2.w;
    a3.x += g * v3.x; a3.y += g * v3.y; a3.z += g * v3.z; a3.w += g * v3.w;
  }
  size_t base = (size_t)node * KA + rel * 512 + 4 * lane;
  float4 av[4] = {a0, a1, a2, a3};
#pragma unroll
  for (int j = 0; j < 4; ++j) {
    float4 v = av[j];
    __nv_bfloat16 h0 = __float2bfloat16(v.x), h1 = __float2bfloat16(v.y);
    __nv_bfloat16 h2 = __float2bfloat16(v.z), h3 = __float2bfloat16(v.w);
    __nv_bfloat16 l0 = __float2bfloat16(v.x - __bfloat162float(h0));
    __nv_bfloat16 l1 = __float2bfloat16(v.y - __bfloat162float(h1));
    __nv_bfloat16 l2 = __float2bfloat16(v.z - __bfloat162float(h2));
    __nv_bfloat16 l3 = __float2bfloat16(v.w - __bfloat162float(h3));
    __nv_bfloat162 hp0(h0, h1), hp1(h2, h3), lp0(l0, l1), lp1(l2, l3);
    uint2 hw, lw;
    hw.x = *(uint32_t*)&hp0; hw.y = *(uint32_t*)&hp1;
    lw.x = *(uint32_t*)&lp0; lw.y = *(uint32_t*)&lp1;
    *(uint2*)&g_Abf[base + j * 128] = hw;
    *(uint2*)&g_Abf[base + 1536 + j * 128] = lw;
  }
}

// ================== kernel: x hi/lo split into Abf cols [1024,1536) ==========
template <bool FROM_GH>
__global__ void xsplit_kernel(const float* __restrict__ xin) {
  const float* x = FROM_GH ? g_H : xin;
  size_t t = (size_t)blockIdx.x * blockDim.x + threadIdx.x;
  const size_t total = (size_t)N_NODES * (HDIM / 4);
  if (t >= total) return;
  int n = (int)(t / (HDIM / 4));
  int c4 = (int)(t % (HDIM / 4));
  float4 v = ((const float4*)x)[t];
  __nv_bfloat16 h0 = __float2bfloat16(v.x), h1 = __float2bfloat16(v.y);
  __nv_bfloat16 h2 = __float2bfloat16(v.z), h3 = __float2bfloat16(v.w);
  __nv_bfloat16 l0 = __float2bfloat16(v.x - __bfloat162float(h0));
  __nv_bfloat16 l1 = __float2bfloat16(v.y - __bfloat162float(h1));
  __nv_bfloat16 l2 = __float2bfloat16(v.z - __bfloat162float(h2));
  __nv_bfloat16 l3 = __float2bfloat16(v.w - __bfloat162float(h3));
  size_t base = (size_t)n * KA + 1024 + 4 * c4;
  __nv_bfloat162 hp0(h0, h1), hp1(h2, h3), lp0(l0, l1), lp1(l2, l3);
  uint2 hw, lw;
  hw.x = *(uint32_t*)&hp0; hw.y = *(uint32_t*)&hp1;
  lw.x = *(uint32_t*)&lp0; lw.y = *(uint32_t*)&lp1;
  *(uint2*)&g_Abf[base] = hw;
  *(uint2*)&g_Abf[base + 1536] = lw;
}

// ================== kernel: mma.sync bf16 GEMM ===============================
// CTA tile 144(M) x 128(N), K'=4608. Grid = 74 x 4 = 296 CTAs = 148 SM x 2.
// 6 warps, warp tile 48x64. 2-stage cp.async; stage = A 18KB + B 16KB = 34KB.
constexpr int A_BYTES = MTILE * 128;          // 18432
constexpr int STAGE_BYTES = A_BYTES + 16384;  // 34816
constexpr int B_OFF = A_BYTES;
constexpr int SMEM_GEMM = 2 * STAGE_BYTES;    // 69632
constexpr int NCHUNK = KB / 64;               // 72
constexpr int A_UNITS = MTILE * 8;            // 1152 16B units
constexpr int TOT_UNITS = A_UNITS + 1024;     // 2176

__device__ __forceinline__ void load_chunk(uint32_t sbase, int tid, int m0, int n0, int c) {
  int kA = (c < 48 ? c : c - 48) * 64;  // [0,24): hi  [24,48): lo  [48,72): hi again
  int kB = c * 64;
#pragma unroll
  for (int it = 0; it < 12; ++it) {
    int u = tid + it * 192;
    if (u >= TOT_UNITS) break;
    const __nv_bfloat16* src;
    uint32_t dst;
    if (u < A_UNITS) {
      int row = u >> 3, col16 = u & 7;
      src = g_Abf + (size_t)(m0 + row) * KA + kA + col16 * 8;
      dst = sbase + SWZ(row * 128 + col16 * 16);
    } else {
      int v = u - A_UNITS;
      int row = v >> 3, col16 = v & 7;
      src = g_Wt + (size_t)(n0 + row) * KB + kB + col16 * 8;
      dst = sbase + B_OFF + SWZ(row * 128 + col16 * 16);
    }
    cp_async16(dst, (const void*)src);
  }
  CP_COMMIT();
}

template <bool TO_GH>
__global__ void __launch_bounds__(192, 2)
gemm_kernel(const float* __restrict__ bias, float* __restrict__ Cext) {
  extern __shared__ __align__(1024) char smem[];
  float* Cbase = TO_GH ? g_H : Cext;
  uint32_t sb = smem_u32(smem);
  const int tid = threadIdx.x;
  const int lane = tid & 31, wid = tid >> 5;           // wid 0..5
  const int wm = (wid % 3) * 48;                       // 3 M-warps
  const int wn = (wid / 3) * 64;                       // 2 N-warps
  const int m0 = blockIdx.y * MTILE;
  const int n0 = blockIdx.x * 128;

  const int r8 = lane & 7, grp = lane >> 3;
  const int a_row_off = r8 + (grp & 1) * 8;
  const int a_kb_off = (grp >> 1) * 16;
  const int b_row_off = r8 + (grp >> 1) * 8;
  const int b_kb_off = (grp & 1) * 16;

  float acc[3][8][4] = {};

  load_chunk(sb, tid, m0, n0, 0);
  load_chunk(sb + STAGE_BYTES, tid, m0, n0, 1);

  for (int c = 0; c < NCHUNK; ++c) {
    uint32_t sbase = sb + (c & 1) * STAGE_BYTES;
    if (c == NCHUNK - 1) cp_wait<0>(); else cp_wait<1>();
    __syncthreads();
#pragma unroll
    for (int kk = 0; kk < 4; ++kk) {
      uint32_t af[3][4], bf[8][2];
#pragma unroll
      for (int mi = 0; mi < 3; ++mi) {
        int row = wm + mi * 16 + a_row_off;
        ldsm_x4(af[mi], sbase + SWZ(row * 128 + kk * 32 + a_kb_off));
      }
#pragma unroll
      for (int p = 0; p < 4; ++p) {
        int rowb = wn + p * 16 + b_row_off;
        uint32_t t4[4];
        ldsm_x4(t4, sbase + B_OFF + SWZ(rowb * 128 + kk * 32 + b_kb_off));
        bf[p * 2][0] = t4[0]; bf[p * 2][1] = t4[1];
        bf[p * 2 + 1][0] = t4[2]; bf[p * 2 + 1][1] = t4[3];
      }
#pragma unroll
      for (int mi = 0; mi < 3; ++mi)
#pragma unroll
        for (int ni = 0; ni < 8; ++ni)
          mma_bf16(acc[mi][ni], af[mi], bf[ni]);
    }
    __syncthreads();
    if (c + 2 < NCHUNK) load_chunk(sbase, tid, m0, n0, c + 2);
  }

  // ---- epilogue: C += bias (+relu) ----
  const int crow0 = m0 + wm + (lane >> 2);
  const int ccol0 = n0 + wn + (lane & 3) * 2;
#pragma unroll
  for (int ni = 0; ni < 8; ++ni) {
    int coln = ccol0 + ni * 8;
    float b0 = bias[coln], b1 = bias[coln + 1];
#pragma unroll
    for (int mi = 0; mi < 3; ++mi) {
      int rA = crow0 + mi * 16;
      int rB = rA + 8;
      float v0 = acc[mi][ni][0] + b0, v1 = acc[mi][ni][1] + b1;
      float v2 = acc[mi][ni][2] + b0, v3 = acc[mi][ni][3] + b1;
      if (TO_GH) {
        v0 = fmaxf(v0, 0.f); v1 = fmaxf(v1, 0.f);
        v2 = fmaxf(v2, 0.f); v3 = fmaxf(v3, 0.f);
      }
      if (rA < N_NODES) *(float2*)(Cbase + (size_t)rA * HDIM + coln) = make_float2(v0, v1);
      if (rB < N_NODES) *(float2*)(Cbase + (size_t)rB * HDIM + coln) = make_float2(v2, v3);
    }
  }
}

// ================== launch ===================================================
extern "C" void kernel_launch(void* const* d_in, const int* in_sizes, int n_in,
                              void* d_out, int out_size) {
  const float* x        = (const float*)d_in[0];
  const int* edge_index = (const int*)d_in[1];
  const int* edge_type  = (const int*)d_in[2];
  const float* basis1   = (const float*)d_in[3];
  const float* att1     = (const float*)d_in[4];
  const float* gw1      = (const float*)d_in[5];
  const float* root1    = (const float*)d_in[6];
  const float* bias1    = (const float*)d_in[7];
  const float* basis2   = (const float*)d_in[8];
  const float* att2     = (const float*)d_in[9];
  const float* gw2      = (const float*)d_in[10];
  const float* root2    = (const float*)d_in[11];
  const float* bias2    = (const float*)d_in[12];
  float* out = (float*)d_out;

  cudaFuncSetAttribute(gemm_kernel<true>,  cudaFuncAttributeMaxDynamicSharedMemorySize, SMEM_GEMM);
  cudaFuncSetAttribute(gemm_kernel<false>, cudaFuncAttributeMaxDynamicSharedMemorySize, SMEM_GEMM);

  dim3 gemmGrid(HDIM / 128, MT_TILES);  // 4 x 74 = 296 CTAs
  int wBlocks = (KDIM * HDIM + 255) / 256;
  int gateBlocks = (N_NODES + 7) / 8;
  int segBlocks = (NSEG + 7) / 8;
  int eBlocks = (N_EDGES + 255) / 256;
  int xsBlocks = (int)(((size_t)N_NODES * (HDIM / 4) + 255) / 256);

  // ---- CSR build (graph constant across both layers) ----
  zero_cnt_kernel<<<(NSEG + 255) / 256, 256>>>();
  count_kernel<<<eBlocks, 256>>>(edge_index, edge_type);
  scan_kernel<<<1, 256>>>();
  fill_kernel<<<eBlocks, 256>>>(edge_index, edge_type);

  // ---- layer 1 (source = x) ----
  build_Wt_kernel<<<wBlocks, 256>>>(basis1, att1, root1);
  gate_kernel<false><<<gateBlocks, 256>>>(x, gw1);
  gather_kernel<false><<<segBlocks, 256>>>(x);
  xsplit_kernel<false><<<xsBlocks, 256>>>(x);
  gemm_kernel<true><<<gemmGrid, 192, SMEM_GEMM>>>(bias1, nullptr);   // -> g_H (relu)

  // ---- layer 2 (source = g_H) ----
  build_Wt_kernel<<<wBlocks, 256>>>(basis2, att2, root2);
  gate_kernel<true><<<gateBlocks, 256>>>(nullptr, gw2);
  gather_kernel<true><<<segBlocks, 256>>>(nullptr);
  xsplit_kernel<true><<<xsBlocks, 256>>>(nullptr);
  gemm_kernel<false><<<gemmGrid, 192, SMEM_GEMM>>>(bias2, out);
}

// round 11
// speedup vs baseline: 3.2195x; 1.0807x over previous
#include <cuda_runtime.h>
#include <cuda_bf16.h>
#include <cstdint>
#include <math.h>

#define N_NODES 10000
#define N_EDGES 160000
#define HDIM 512
#define NREL 2
#define NBASES 30
#define KDIM 1536          // logical fp32 activation width [S0 | S1 | x]
#define KA 3072            // bf16 A cols: [hi(1536) | lo(1536)]
#define KB 4608            // bf16 Wt cols: [Wh | Wh | Wl]
#define NSEG (N_NODES * NREL)
#define MTILE 144
#define MT_TILES 74
#define MPAD (MT_TILES * MTILE)  // 10656
#define NTILE 256

// ---------------- scratch (static device globals; no allocs) ----------------
__device__ float g_H[(size_t)N_NODES * HDIM];
__device__ float g_Gate[N_NODES * NREL];
__device__ int g_Cnt[NSEG];
__device__ int g_Off[NSEG + 1];
__device__ int g_ECol[N_EDGES];
__device__ __align__(256) __nv_bfloat16 g_Abf[(size_t)MPAD * KA];  // pad rows stay 0 (.bss)
__device__ __align__(256) __nv_bfloat16 g_Wt[(size_t)HDIM * KB];

// ============================ PTX helpers (sm_100 base ISA only) =============
__device__ __forceinline__ uint32_t smem_u32(const void* p) {
  uint32_t a;
  asm("{ .reg .u64 t; cvta.to.shared.u64 t, %1; cvt.u32.u64 %0, t; }" : "=r"(a) : "l"(p));
  return a;
}
__device__ __forceinline__ void cp_async16(uint32_t s, const void* g) {
  asm volatile("cp.async.cg.shared.global [%0], [%1], 16;" :: "r"(s), "l"(g));
}
#define CP_COMMIT() asm volatile("cp.async.commit_group;")
template <int N> __device__ __forceinline__ void cp_wait() {
  asm volatile("cp.async.wait_group %0;" :: "n"(N));
}

#define SWZ(o) ((o) ^ (((o) >> 3) & 0x70))

__device__ __forceinline__ void ldsm_x4(uint32_t* r, uint32_t addr) {
  asm volatile("ldmatrix.sync.aligned.m8n8.x4.shared.b16 {%0,%1,%2,%3}, [%4];"
               : "=r"(r[0]), "=r"(r[1]), "=r"(r[2]), "=r"(r[3]) : "r"(addr));
}
__device__ __forceinline__ void mma_bf16(float* c, const uint32_t* a, const uint32_t* b) {
  asm volatile(
      "mma.sync.aligned.m16n8k16.row.col.f32.bf16.bf16.f32 "
      "{%0,%1,%2,%3}, {%4,%5,%6,%7}, {%8,%9}, {%0,%1,%2,%3};"
      : "+f"(c[0]), "+f"(c[1]), "+f"(c[2]), "+f"(c[3])
      : "r"(a[0]), "r"(a[1]), "r"(a[2]), "r"(a[3]), "r"(b[0]), "r"(b[1]));
}

// ================== CSR build (once per launch) ==============================
__global__ void zero_cnt_kernel() {
  int i = blockIdx.x * blockDim.x + threadIdx.x;
  if (i < NSEG) g_Cnt[i] = 0;
}
__global__ void count_kernel(const int* __restrict__ edge_index,
                             const int* __restrict__ edge_type) {
  int e = blockIdx.x * blockDim.x + threadIdx.x;
  if (e >= N_EDGES) return;
  int seg = edge_index[e] * 2 + edge_type[e];
  atomicAdd(&g_Cnt[seg], 1);
}
__global__ void scan_kernel() {  // single block of 256 threads
  __shared__ int part[256];
  const int t = threadIdx.x;
  const int CH = (NSEG + 255) / 256;  // 79
  int s = 0;
  for (int i = 0; i < CH; ++i) {
    int idx = t * CH + i;
    if (idx < NSEG) s += g_Cnt[idx];
  }
  part[t] = s;
  __syncthreads();
  for (int off = 1; off < 256; off <<= 1) {
    int u = (t >= off) ? part[t - off] : 0;
    __syncthreads();
    part[t] += u;
    __syncthreads();
  }
  int run = part[t] - s;  // exclusive base for this thread's chunk
  for (int i = 0; i < CH; ++i) {
    int idx = t * CH + i;
    if (idx < NSEG) {
      g_Off[idx] = run;
      run += g_Cnt[idx];
      g_Cnt[idx] = 0;  // reset cursor for fill
    }
  }
  if (t == 255) g_Off[NSEG] = run;
}
__global__ void fill_kernel(const int* __restrict__ edge_index,
                            const int* __restrict__ edge_type) {
  int e = blockIdx.x * blockDim.x + threadIdx.x;
  if (e >= N_EDGES) return;
  int seg = edge_index[e] * 2 + edge_type[e];
  int pos = g_Off[seg] + atomicAdd(&g_Cnt[seg], 1);
  g_ECol[pos] = edge_index[N_EDGES + e];
}

// ================== kernel: Wt = bf16-split combined weights ================
__global__ void build_Wt_kernel(const float* __restrict__ basis,
                                const float* __restrict__ att,
                                const float* __restrict__ root) {
  int idx = blockIdx.x * blockDim.x + threadIdx.x;
  if (idx >= KDIM * HDIM) return;
  int k = idx >> 9;
  int n = idx & (HDIM - 1);
  float v;
  if (k < NREL * HDIM) {
    int r = k >> 9;
    int i = k & (HDIM - 1);
    float acc = 0.f;
#pragma unroll
    for (int b = 0; b < NBASES; b++)
      acc += att[r * NBASES + b] * basis[(size_t)b * HDIM * HDIM + i * HDIM + n];
    v = acc;
  } else {
    v = root[(k - NREL * HDIM) * HDIM + n];
  }
  __nv_bfloat16 hi = __float2bfloat16(v);
  __nv_bfloat16 lo = __float2bfloat16(v - __bfloat162float(hi));
  size_t base = (size_t)n * KB + k;
  g_Wt[base] = hi;
  g_Wt[base + 1536] = hi;
  g_Wt[base + 3072] = lo;
}

// ================== kernel: per-node gates ===================================
template <bool FROM_GH>
__global__ void gate_kernel(const float* __restrict__ xin,
                            const float* __restrict__ gw) {
  const float* x = FROM_GH ? g_H : xin;
  __shared__ float s_gw[NREL * HDIM];
  for (int i = threadIdx.x; i < NREL * HDIM; i += blockDim.x) s_gw[i] = gw[i];
  __syncthreads();
  int warp = (blockIdx.x * blockDim.x + threadIdx.x) >> 5;
  int lane = threadIdx.x & 31;
  if (warp >= N_NODES) return;
  const float4* xr = (const float4*)(x + (size_t)warp * HDIM);
  float d0 = 0.f, d1 = 0.f;
#pragma unroll
  for (int j = 0; j < 4; j++) {
    int c = lane + j * 32;
    float4 xv = xr[c];
    int base = c * 4;
    d0 += xv.x * s_gw[base] + xv.y * s_gw[base + 1] + xv.z * s_gw[base + 2] + xv.w * s_gw[base + 3];
    d1 += xv.x * s_gw[HDIM + base] + xv.y * s_gw[HDIM + base + 1] +
          xv.z * s_gw[HDIM + base + 2] + xv.w * s_gw[HDIM + base + 3];
  }
#pragma unroll
  for (int off = 16; off; off >>= 1) {
    d0 += __shfl_xor_sync(0xffffffffu, d0, off);
    d1 += __shfl_xor_sync(0xffffffffu, d1, off);
  }
  if (lane == 0) {
    g_Gate[warp * 2 + 0] = 1.f / (1.f + expf(-d0));
    g_Gate[warp * 2 + 1] = 1.f / (1.f + expf(-d1));
  }
}

// ================== kernel: CSR gather -> bf16 hi/lo S-segments ==============
template <bool FROM_GH>
__global__ void gather_kernel(const float* __restrict__ xin) {
  const float* x = FROM_GH ? g_H : xin;
  int seg = blockIdx.x * (blockDim.x >> 5) + (threadIdx.x >> 5);
  int lane = threadIdx.x & 31;
  if (seg >= NSEG) return;
  int node = seg >> 1, rel = seg & 1;
  int p = g_Off[seg], pe = g_Off[seg + 1];
  float4 a0 = {0, 0, 0, 0}, a1 = a0, a2 = a0, a3 = a0;
  for (; p < pe; ++p) {
    int col = g_ECol[p];
    float g = g_Gate[col * 2 + rel];
    const float4* xr = (const float4*)(x + (size_t)col * HDIM);
    float4 v0 = xr[lane], v1 = xr[lane + 32], v2 = xr[lane + 64], v3 = xr[lane + 96];
    a0.x += g * v0.x; a0.y += g * v0.y; a0.z += g * v0.z; a0.w += g * v0.w;
    a1.x += g * v1.x; a1.y += g * v1.y; a1.z += g * v1.z; a1.w += g * v1.w;
    a2.x += g * v2.x; a2.y += g * v2.y; a2.z += g * v2.z; a2.w += g * v2.w;
    a3.x += g * v3.x; a3.y += g * v3.y; a3.z += g * v3.z; a3.w += g * v3.w;
  }
  size_t base = (size_t)node * KA + rel * 512 + 4 * lane;
  float4 av[4] = {a0, a1, a2, a3};
#pragma unroll
  for (int j = 0; j < 4; ++j) {
    float4 v = av[j];
    __nv_bfloat16 h0 = __float2bfloat16(v.x), h1 = __float2bfloat16(v.y);
    __nv_bfloat16 h2 = __float2bfloat16(v.z), h3 = __float2bfloat16(v.w);
    __nv_bfloat16 l0 = __float2bfloat16(v.x - __bfloat162float(h0));
    __nv_bfloat16 l1 = __float2bfloat16(v.y - __bfloat162float(h1));
    __nv_bfloat16 l2 = __float2bfloat16(v.z - __bfloat162float(h2));
    __nv_bfloat16 l3 = __float2bfloat16(v.w - __bfloat162float(h3));
    __nv_bfloat162 hp0(h0, h1), hp1(h2, h3), lp0(l0, l1), lp1(l2, l3);
    uint2 hw, lw;
    hw.x = *(uint32_t*)&hp0; hw.y = *(uint32_t*)&hp1;
    lw.x = *(uint32_t*)&lp0; lw.y = *(uint32_t*)&lp1;
    *(uint2*)&g_Abf[base + j * 128] = hw;
    *(uint2*)&g_Abf[base + 1536 + j * 128] = lw;
  }
}

// ================== kernel: x hi/lo split into Abf cols [1024,1536) ==========
template <bool FROM_GH>
__global__ void xsplit_kernel(const float* __restrict__ xin) {
  const float* x = FROM_GH ? g_H : xin;
  size_t t = (size_t)blockIdx.x * blockDim.x + threadIdx.x;
  const size_t total = (size_t)N_NODES * (HDIM / 4);
  if (t >= total) return;
  int n = (int)(t / (HDIM / 4));
  int c4 = (int)(t % (HDIM / 4));
  float4 v = ((const float4*)x)[t];
  __nv_bfloat16 h0 = __float2bfloat16(v.x), h1 = __float2bfloat16(v.y);
  __nv_bfloat16 h2 = __float2bfloat16(v.z), h3 = __float2bfloat16(v.w);
  __nv_bfloat16 l0 = __float2bfloat16(v.x - __bfloat162float(h0));
  __nv_bfloat16 l1 = __float2bfloat16(v.y - __bfloat162float(h1));
  __nv_bfloat16 l2 = __float2bfloat16(v.z - __bfloat162float(h2));
  __nv_bfloat16 l3 = __float2bfloat16(v.w - __bfloat162float(h3));
  size_t base = (size_t)n * KA + 1024 + 4 * c4;
  __nv_bfloat162 hp0(h0, h1), hp1(h2, h3), lp0(l0, l1), lp1(l2, l3);
  uint2 hw, lw;
  hw.x = *(uint32_t*)&hp0; hw.y = *(uint32_t*)&hp1;
  lw.x = *(uint32_t*)&lp0; lw.y = *(uint32_t*)&lp1;
  *(uint2*)&g_Abf[base] = hw;
  *(uint2*)&g_Abf[base + 1536] = lw;
}

// ================== kernel: mma.sync bf16 GEMM ===============================
// CTA tile 144(M) x 256(N), K'=4608. Grid = 74 x 2 = 148 CTAs = 1 per SM.
// 12 warps (3M x 4N), warp tile 48x64. 3-stage cp.async;
// stage = A 18KB + B 32KB = 50KB; total smem 150KB.
constexpr int A_BYTES = MTILE * 128;          // 18432
constexpr int B_BYTES = NTILE * 128;          // 32768
constexpr int STAGE_BYTES = A_BYTES + B_BYTES;  // 51200
constexpr int B_OFF = A_BYTES;
constexpr int SMEM_GEMM = 3 * STAGE_BYTES;    // 153600
constexpr int NCHUNK = KB / 64;               // 72
constexpr int A_UNITS = MTILE * 8;            // 1152 16B units
constexpr int B_UNITS = NTILE * 8;            // 2048
constexpr int TOT_UNITS = A_UNITS + B_UNITS;  // 3200
constexpr int GTHREADS = 384;

__device__ __forceinline__ void load_chunk(uint32_t sbase, int tid, int m0, int n0, int c) {
  int kA = (c < 48 ? c : c - 48) * 64;  // [0,24): hi  [24,48): lo  [48,72): hi again
  int kB = c * 64;
#pragma unroll
  for (int it = 0; it < 9; ++it) {
    int u = tid + it * GTHREADS;
    if (u >= TOT_UNITS) break;
    const __nv_bfloat16* src;
    uint32_t dst;
    if (u < A_UNITS) {
      int row = u >> 3, col16 = u & 7;
      src = g_Abf + (size_t)(m0 + row) * KA + kA + col16 * 8;
      dst = sbase + SWZ(row * 128 + col16 * 16);
    } else {
      int v = u - A_UNITS;
      int row = v >> 3, col16 = v & 7;
      src = g_Wt + (size_t)(n0 + row) * KB + kB + col16 * 8;
      dst = sbase + B_OFF + SWZ(row * 128 + col16 * 16);
    }
    cp_async16(dst, (const void*)src);
  }
  CP_COMMIT();
}

template <bool TO_GH>
__global__ void __launch_bounds__(GTHREADS, 1)
gemm_kernel(const float* __restrict__ bias, float* __restrict__ Cext) {
  extern __shared__ __align__(1024) char smem[];
  float* Cbase = TO_GH ? g_H : Cext;
  uint32_t sb = smem_u32(smem);
  const int tid = threadIdx.x;
  const int lane = tid & 31, wid = tid >> 5;           // wid 0..11
  const int wm = (wid % 3) * 48;                       // 3 M-warps
  const int wn = (wid / 3) * 64;                       // 4 N-warps
  const int m0 = blockIdx.y * MTILE;
  const int n0 = blockIdx.x * NTILE;

  const int r8 = lane & 7, grp = lane >> 3;
  const int a_row_off = r8 + (grp & 1) * 8;
  const int a_kb_off = (grp >> 1) * 16;
  const int b_row_off = r8 + (grp >> 1) * 8;
  const int b_kb_off = (grp & 1) * 16;

  float acc[3][8][4] = {};

  load_chunk(sb, tid, m0, n0, 0);
  load_chunk(sb + STAGE_BYTES, tid, m0, n0, 1);
  load_chunk(sb + 2 * STAGE_BYTES, tid, m0, n0, 2);

  for (int c = 0; c < NCHUNK; ++c) {
    uint32_t sbase = sb + (c % 3) * STAGE_BYTES;
    if (c <= NCHUNK - 3)      cp_wait<2>();
    else if (c == NCHUNK - 2) cp_wait<1>();
    else                      cp_wait<0>();
    __syncthreads();
#pragma unroll
    for (int kk = 0; kk < 4; ++kk) {
      uint32_t af[3][4], bf[8][2];
#pragma unroll
      for (int mi = 0; mi < 3; ++mi) {
        int row = wm + mi * 16 + a_row_off;
        ldsm_x4(af[mi], sbase + SWZ(row * 128 + kk * 32 + a_kb_off));
      }
#pragma unroll
      for (int p = 0; p < 4; ++p) {
        int rowb = wn + p * 16 + b_row_off;
        uint32_t t4[4];
        ldsm_x4(t4, sbase + B_OFF + SWZ(rowb * 128 + kk * 32 + b_kb_off));
        bf[p * 2][0] = t4[0]; bf[p * 2][1] = t4[1];
        bf[p * 2 + 1][0] = t4[2]; bf[p * 2 + 1][1] = t4[3];
      }
#pragma unroll
      for (int mi = 0; mi < 3; ++mi)
#pragma unroll
        for (int ni = 0; ni < 8; ++ni)
          mma_bf16(acc[mi][ni], af[mi], bf[ni]);
    }
    __syncthreads();
    if (c + 3 < NCHUNK) load_chunk(sbase, tid, m0, n0, c + 3);
  }

  // ---- epilogue: C += bias (+relu) ----
  const int crow0 = m0 + wm + (lane >> 2);
  const int ccol0 = n0 + wn + (lane & 3) * 2;
#pragma unroll
  for (int ni = 0; ni < 8; ++ni) {
    int coln = ccol0 + ni * 8;
    float b0 = bias[coln], b1 = bias[coln + 1];
#pragma unroll
    for (int mi = 0; mi < 3; ++mi) {
      int rA = crow0 + mi * 16;
      int rB = rA + 8;
      float v0 = acc[mi][ni][0] + b0, v1 = acc[mi][ni][1] + b1;
      float v2 = acc[mi][ni][2] + b0, v3 = acc[mi][ni][3] + b1;
      if (TO_GH) {
        v0 = fmaxf(v0, 0.f); v1 = fmaxf(v1, 0.f);
        v2 = fmaxf(v2, 0.f); v3 = fmaxf(v3, 0.f);
      }
      if (rA < N_NODES) *(float2*)(Cbase + (size_t)rA * HDIM + coln) = make_float2(v0, v1);
      if (rB < N_NODES) *(float2*)(Cbase + (size_t)rB * HDIM + coln) = make_float2(v2, v3);
    }
  }
}

// ================== launch ===================================================
extern "C" void kernel_launch(void* const* d_in, const int* in_sizes, int n_in,
                              void* d_out, int out_size) {
  const float* x        = (const float*)d_in[0];
  const int* edge_index = (const int*)d_in[1];
  const int* edge_type  = (const int*)d_in[2];
  const float* basis1   = (const float*)d_in[3];
  const float* att1     = (const float*)d_in[4];
  const float* gw1      = (const float*)d_in[5];
  const float* root1    = (const float*)d_in[6];
  const float* bias1    = (const float*)d_in[7];
  const float* basis2   = (const float*)d_in[8];
  const float* att2     = (const float*)d_in[9];
  const float* gw2      = (const float*)d_in[10];
  const float* root2    = (const float*)d_in[11];
  const float* bias2    = (const float*)d_in[12];
  float* out = (float*)d_out;

  cudaFuncSetAttribute(gemm_kernel<true>,  cudaFuncAttributeMaxDynamicSharedMemorySize, SMEM_GEMM);
  cudaFuncSetAttribute(gemm_kernel<false>, cudaFuncAttributeMaxDynamicSharedMemorySize, SMEM_GEMM);

  dim3 gemmGrid(HDIM / NTILE, MT_TILES);  // 2 x 74 = 148 CTAs
  int wBlocks = (KDIM * HDIM + 255) / 256;
  int gateBlocks = (N_NODES + 7) / 8;
  int segBlocks = (NSEG + 7) / 8;
  int eBlocks = (N_EDGES + 255) / 256;
  int xsBlocks = (int)(((size_t)N_NODES * (HDIM / 4) + 255) / 256);

  // ---- CSR build (graph constant across both layers) ----
  zero_cnt_kernel<<<(NSEG + 255) / 256, 256>>>();
  count_kernel<<<eBlocks, 256>>>(edge_index, edge_type);
  scan_kernel<<<1, 256>>>();
  fill_kernel<<<eBlocks, 256>>>(edge_index, edge_type);

  // ---- layer 1 (source = x) ----
  build_Wt_kernel<<<wBlocks, 256>>>(basis1, att1, root1);
  gate_kernel<false><<<gateBlocks, 256>>>(x, gw1);
  gather_kernel<false><<<segBlocks, 256>>>(x);
  xsplit_kernel<false><<<xsBlocks, 256>>>(x);
  gemm_kernel<true><<<gemmGrid, GTHREADS, SMEM_GEMM>>>(bias1, nullptr);  // -> g_H (relu)

  // ---- layer 2 (source = g_H) ----
  build_Wt_kernel<<<wBlocks, 256>>>(basis2, att2, root2);
  gate_kernel<true><<<gateBlocks, 256>>>(nullptr, gw2);
  gather_kernel<true><<<segBlocks, 256>>>(nullptr);
  xsplit_kernel<true><<<xsBlocks, 256>>>(nullptr);
  gemm_kernel<false><<<gemmGrid, GTHREADS, SMEM_GEMM>>>(bias2, out);
}

// round 12
// speedup vs baseline: 3.4883x; 1.0835x over previous
#include <cuda_runtime.h>
#include <cuda_bf16.h>
#include <cstdint>
#include <math.h>

#define N_NODES 10000
#define N_EDGES 160000
#define HDIM 512
#define NREL 2
#define NBASES 30
#define KDIM 1536          // logical fp32 activation width [S0 | S1 | x]
#define KA 3072            // bf16 A cols: [hi(1536) | lo(1536)]
#define KB 4608            // bf16 Wt cols: [Wh | Wh | Wl]
#define NSEG (N_NODES * NREL)
#define MTILE 144
#define MT_TILES 74
#define MPAD (MT_TILES * MTILE)  // 10656
#define NTILE 256

// ---------------- scratch (static device globals; no allocs) ----------------
__device__ float g_H[(size_t)N_NODES * HDIM];
__device__ float g_Gate[N_NODES * NREL];
__device__ int g_Cnt[NSEG];
__device__ int g_Off[NSEG + 1];
__device__ int g_ECol[N_EDGES];
__device__ __align__(256) __nv_bfloat16 g_Abf[(size_t)MPAD * KA];  // pad rows stay 0 (.bss)
__device__ __align__(256) __nv_bfloat16 g_Wt[(size_t)HDIM * KB];

// ============================ PTX helpers (sm_100 base ISA only) =============
__device__ __forceinline__ uint32_t smem_u32(const void* p) {
  uint32_t a;
  asm("{ .reg .u64 t; cvta.to.shared.u64 t, %1; cvt.u32.u64 %0, t; }" : "=r"(a) : "l"(p));
  return a;
}
__device__ __forceinline__ void cp_async16(uint32_t s, const void* g) {
  asm volatile("cp.async.cg.shared.global [%0], [%1], 16;" :: "r"(s), "l"(g));
}
#define CP_COMMIT() asm volatile("cp.async.commit_group;")
template <int N> __device__ __forceinline__ void cp_wait() {
  asm volatile("cp.async.wait_group %0;" :: "n"(N));
}

#define SWZ(o) ((o) ^ (((o) >> 3) & 0x70))

__device__ __forceinline__ void ldsm_x4(uint32_t* r, uint32_t addr) {
  asm volatile("ldmatrix.sync.aligned.m8n8.x4.shared.b16 {%0,%1,%2,%3}, [%4];"
               : "=r"(r[0]), "=r"(r[1]), "=r"(r[2]), "=r"(r[3]) : "r"(addr));
}
__device__ __forceinline__ void mma_bf16(float* c, const uint32_t* a, const uint32_t* b) {
  asm volatile(
      "mma.sync.aligned.m16n8k16.row.col.f32.bf16.bf16.f32 "
      "{%0,%1,%2,%3}, {%4,%5,%6,%7}, {%8,%9}, {%0,%1,%2,%3};"
      : "+f"(c[0]), "+f"(c[1]), "+f"(c[2]), "+f"(c[3])
      : "r"(a[0]), "r"(a[1]), "r"(a[2]), "r"(a[3]), "r"(b[0]), "r"(b[1]));
}

// ================== CSR build (once per launch) ==============================
__global__ void zero_cnt_kernel() {
  int i = blockIdx.x * blockDim.x + threadIdx.x;
  if (i < NSEG) g_Cnt[i] = 0;
}
__global__ void count_kernel(const int* __restrict__ edge_index,
                             const int* __restrict__ edge_type) {
  int e = blockIdx.x * blockDim.x + threadIdx.x;
  if (e >= N_EDGES) return;
  int seg = edge_index[e] * 2 + edge_type[e];
  atomicAdd(&g_Cnt[seg], 1);
}
__global__ void scan_kernel() {  // single block of 256 threads
  __shared__ int part[256];
  const int t = threadIdx.x;
  const int CH = (NSEG + 255) / 256;  // 79
  int s = 0;
  for (int i = 0; i < CH; ++i) {
    int idx = t * CH + i;
    if (idx < NSEG) s += g_Cnt[idx];
  }
  part[t] = s;
  __syncthreads();
  for (int off = 1; off < 256; off <<= 1) {
    int u = (t >= off) ? part[t - off] : 0;
    __syncthreads();
    part[t] += u;
    __syncthreads();
  }
  int run = part[t] - s;  // exclusive base for this thread's chunk
  for (int i = 0; i < CH; ++i) {
    int idx = t * CH + i;
    if (idx < NSEG) {
      g_Off[idx] = run;
      run += g_Cnt[idx];
      g_Cnt[idx] = 0;  // reset cursor for fill
    }
  }
  if (t == 255) g_Off[NSEG] = run;
}
__global__ void fill_kernel(const int* __restrict__ edge_index,
                            const int* __restrict__ edge_type) {
  int e = blockIdx.x * blockDim.x + threadIdx.x;
  if (e >= N_EDGES) return;
  int seg = edge_index[e] * 2 + edge_type[e];
  int pos = g_Off[seg] + atomicAdd(&g_Cnt[seg], 1);
  g_ECol[pos] = edge_index[N_EDGES + e];
}

// ================== kernel: Wt = bf16-split combined weights ================
// Tile-transposed: coalesced basis reads (along n) + coalesced g_Wt writes
// (along k). Block computes a 32(k) x 32(n) tile via smem transpose.
__global__ void build_Wt_kernel(const float* __restrict__ basis,
                                const float* __restrict__ att,
                                const float* __restrict__ root) {
  __shared__ unsigned short sH[32][33];
  __shared__ unsigned short sL[32][33];
  __shared__ float s_att[NREL * NBASES];
  int k0 = blockIdx.x * 32;  // 0..1535
  int n0 = blockIdx.y * 32;  // 0..511
  int tx = threadIdx.x & 31, ty = threadIdx.x >> 5;  // 32 x 8
  if (threadIdx.x < NREL * NBASES) s_att[threadIdx.x] = att[threadIdx.x];
  __syncthreads();
#pragma unroll
  for (int pass = 0; pass < 4; ++pass) {
    int kr = ty + pass * 8;          // 0..31
    int k = k0 + kr;
    int n = n0 + tx;
    float v;
    if (k < NREL * HDIM) {
      int r = k >> 9, i = k & 511;
      float acc = 0.f;
#pragma unroll
      for (int b = 0; b < NBASES; b++)
        acc += s_att[r * NBASES + b] * basis[(size_t)b * HDIM * HDIM + (size_t)i * HDIM + n];
      v = acc;
    } else {
      v = root[(size_t)(k - NREL * HDIM) * HDIM + n];
    }
    __nv_bfloat16 hi = __float2bfloat16(v);
    __nv_bfloat16 lo = __float2bfloat16(v - __bfloat162float(hi));
    sH[kr][tx] = *(unsigned short*)&hi;
    sL[kr][tx] = *(unsigned short*)&lo;
  }
  __syncthreads();
#pragma unroll
  for (int pass = 0; pass < 4; ++pass) {
    int nr = ty + pass * 8;          // 0..31
    int n = n0 + nr;
    int k = k0 + tx;
    unsigned short h = sH[tx][nr];
    unsigned short l = sL[tx][nr];
    size_t base = (size_t)n * KB + k;
    *(unsigned short*)&g_Wt[base] = h;
    *(unsigned short*)&g_Wt[base + 1536] = h;
    *(unsigned short*)&g_Wt[base + 3072] = l;
  }
}

// ================== kernel: fused gates + x hi/lo split ======================
// warp per node: one pass over x row computes both gate dots AND writes the
// bf16 hi/lo split into Abf cols [1024,1536) / [2560,3072).
template <bool FROM_GH>
__global__ void gatesplit_kernel(const float* __restrict__ xin,
                                 const float* __restrict__ gw) {
  const float* x = FROM_GH ? g_H : xin;
  __shared__ float s_gw[NREL * HDIM];
  for (int i = threadIdx.x; i < NREL * HDIM; i += blockDim.x) s_gw[i] = gw[i];
  __syncthreads();
  int warp = (blockIdx.x * blockDim.x + threadIdx.x) >> 5;
  int lane = threadIdx.x & 31;
  if (warp >= N_NODES) return;
  const float4* xr = (const float4*)(x + (size_t)warp * HDIM);
  float d0 = 0.f, d1 = 0.f;
#pragma unroll
  for (int j = 0; j < 4; j++) {
    int c = lane + j * 32;
    float4 xv = xr[c];
    int base = c * 4;
    d0 += xv.x * s_gw[base] + xv.y * s_gw[base + 1] + xv.z * s_gw[base + 2] + xv.w * s_gw[base + 3];
    d1 += xv.x * s_gw[HDIM + base] + xv.y * s_gw[HDIM + base + 1] +
          xv.z * s_gw[HDIM + base + 2] + xv.w * s_gw[HDIM + base + 3];
    // bf16 hi/lo split from the same registers
    __nv_bfloat16 h0 = __float2bfloat16(xv.x), h1 = __float2bfloat16(xv.y);
    __nv_bfloat16 h2 = __float2bfloat16(xv.z), h3 = __float2bfloat16(xv.w);
    __nv_bfloat16 l0 = __float2bfloat16(xv.x - __bfloat162float(h0));
    __nv_bfloat16 l1 = __float2bfloat16(xv.y - __bfloat162float(h1));
    __nv_bfloat16 l2 = __float2bfloat16(xv.z - __bfloat162float(h2));
    __nv_bfloat16 l3 = __float2bfloat16(xv.w - __bfloat162float(h3));
    __nv_bfloat162 hp0(h0, h1), hp1(h2, h3), lp0(l0, l1), lp1(l2, l3);
    uint2 hw, lw;
    hw.x = *(uint32_t*)&hp0; hw.y = *(uint32_t*)&hp1;
    lw.x = *(uint32_t*)&lp0; lw.y = *(uint32_t*)&lp1;
    size_t base2 = (size_t)warp * KA + 1024 + 4 * c;
    *(uint2*)&g_Abf[base2] = hw;
    *(uint2*)&g_Abf[base2 + 1536] = lw;
  }
#pragma unroll
  for (int off = 16; off; off >>= 1) {
    d0 += __shfl_xor_sync(0xffffffffu, d0, off);
    d1 += __shfl_xor_sync(0xffffffffu, d1, off);
  }
  if (lane == 0) {
    g_Gate[warp * 2 + 0] = 1.f / (1.f + expf(-d0));
    g_Gate[warp * 2 + 1] = 1.f / (1.f + expf(-d1));
  }
}

// ================== kernel: CSR gather -> bf16 hi/lo S-segments ==============
template <bool FROM_GH>
__global__ void gather_kernel(const float* __restrict__ xin) {
  const float* x = FROM_GH ? g_H : xin;
  int seg = blockIdx.x * (blockDim.x >> 5) + (threadIdx.x >> 5);
  int lane = threadIdx.x & 31;
  if (seg >= NSEG) return;
  int node = seg >> 1, rel = seg & 1;
  int p = g_Off[seg], pe = g_Off[seg + 1];
  float4 a0 = {0, 0, 0, 0}, a1 = a0, a2 = a0, a3 = a0;
  if (p < pe) {
    int col = g_ECol[p];
    float g = g_Gate[col * 2 + rel];
    while (true) {
      const float4* xr = (const float4*)(x + (size_t)col * HDIM);
      float4 v0 = xr[lane], v1 = xr[lane + 32], v2 = xr[lane + 64], v3 = xr[lane + 96];
      ++p;
      bool more = (p < pe);
      int ncol = more ? g_ECol[p] : 0;
      float ng = more ? g_Gate[ncol * 2 + rel] : 0.f;
      a0.x += g * v0.x; a0.y += g * v0.y; a0.z += g * v0.z; a0.w += g * v0.w;
      a1.x += g * v1.x; a1.y += g * v1.y; a1.z += g * v1.z; a1.w += g * v1.w;
      a2.x += g * v2.x; a2.y += g * v2.y; a2.z += g * v2.z; a2.w += g * v2.w;
      a3.x += g * v3.x; a3.y += g * v3.y; a3.z += g * v3.z; a3.w += g * v3.w;
      if (!more) break;
      col = ncol;
      g = ng;
    }
  }
  size_t base = (size_t)node * KA + rel * 512 + 4 * lane;
  float4 av[4] = {a0, a1, a2, a3};
#pragma unroll
  for (int j = 0; j < 4; ++j) {
    float4 v = av[j];
    __nv_bfloat16 h0 = __float2bfloat16(v.x), h1 = __float2bfloat16(v.y);
    __nv_bfloat16 h2 = __float2bfloat16(v.z), h3 = __float2bfloat16(v.w);
    __nv_bfloat16 l0 = __float2bfloat16(v.x - __bfloat162float(h0));
    __nv_bfloat16 l1 = __float2bfloat16(v.y - __bfloat162float(h1));
    __nv_bfloat16 l2 = __float2bfloat16(v.z - __bfloat162float(h2));
    __nv_bfloat16 l3 = __float2bfloat16(v.w - __bfloat162float(h3));
    __nv_bfloat162 hp0(h0, h1), hp1(h2, h3), lp0(l0, l1), lp1(l2, l3);
    uint2 hw, lw;
    hw.x = *(uint32_t*)&hp0; hw.y = *(uint32_t*)&hp1;
    lw.x = *(uint32_t*)&lp0; lw.y = *(uint32_t*)&lp1;
    *(uint2*)&g_Abf[base + j * 128] = hw;
    *(uint2*)&g_Abf[base + 1536 + j * 128] = lw;
  }
}

// ================== kernel: mma.sync bf16 GEMM ===============================
// CTA tile 144(M) x 256(N), K'=4608. Grid = 74 x 2 = 148 CTAs = 1 per SM.
// 12 warps (3M x 4N), warp tile 48x64. 3-stage cp.async, ONE barrier/chunk.
constexpr int A_BYTES = MTILE * 128;          // 18432
constexpr int B_BYTES = NTILE * 128;          // 32768
constexpr int STAGE_BYTES = A_BYTES + B_BYTES;  // 51200
constexpr int B_OFF = A_BYTES;
constexpr int SMEM_GEMM = 3 * STAGE_BYTES;    // 153600
constexpr int NCHUNK = KB / 64;               // 72
constexpr int A_UNITS = MTILE * 8;            // 1152 16B units
constexpr int B_UNITS = NTILE * 8;            // 2048
constexpr int TOT_UNITS = A_UNITS + B_UNITS;  // 3200
constexpr int GTHREADS = 384;

__device__ __forceinline__ void load_chunk(uint32_t sbase, int tid, int m0, int n0, int c) {
  int kA = (c < 48 ? c : c - 48) * 64;  // [0,24): hi  [24,48): lo  [48,72): hi again
  int kB = c * 64;
#pragma unroll
  for (int it = 0; it < 9; ++it) {
    int u = tid + it * GTHREADS;
    if (u >= TOT_UNITS) break;
    const __nv_bfloat16* src;
    uint32_t dst;
    if (u < A_UNITS) {
      int row = u >> 3, col16 = u & 7;
      src = g_Abf + (size_t)(m0 + row) * KA + kA + col16 * 8;
      dst = sbase + SWZ(row * 128 + col16 * 16);
    } else {
      int v = u - A_UNITS;
      int row = v >> 3, col16 = v & 7;
      src = g_Wt + (size_t)(n0 + row) * KB + kB + col16 * 8;
      dst = sbase + B_OFF + SWZ(row * 128 + col16 * 16);
    }
    cp_async16(dst, (const void*)src);
  }
  CP_COMMIT();
}

template <bool TO_GH>
__global__ void __launch_bounds__(GTHREADS, 1)
gemm_kernel(const float* __restrict__ bias, float* __restrict__ Cext) {
  extern __shared__ __align__(1024) char smem[];
  float* Cbase = TO_GH ? g_H : Cext;
  uint32_t sb = smem_u32(smem);
  const int tid = threadIdx.x;
  const int lane = tid & 31, wid = tid >> 5;           // wid 0..11
  const int wm = (wid % 3) * 48;                       // 3 M-warps
  const int wn = (wid / 3) * 64;                       // 4 N-warps
  const int m0 = blockIdx.y * MTILE;
  const int n0 = blockIdx.x * NTILE;

  const int r8 = lane & 7, grp = lane >> 3;
  const int a_row_off = r8 + (grp & 1) * 8;
  const int a_kb_off = (grp >> 1) * 16;
  const int b_row_off = r8 + (grp >> 1) * 8;
  const int b_kb_off = (grp & 1) * 16;

  float acc[3][8][4] = {};

  load_chunk(sb, tid, m0, n0, 0);
  load_chunk(sb + STAGE_BYTES, tid, m0, n0, 1);

  for (int c = 0; c < NCHUNK; ++c) {
    uint32_t sbase = sb + (c % 3) * STAGE_BYTES;
    cp_wait<1>();          // chunk c complete (all but most recent group done)
    __syncthreads();       // data visible; buf (c+2)%3 == (c-1)%3 now free
    if (c + 2 < NCHUNK)
      load_chunk(sb + ((c + 2) % 3) * STAGE_BYTES, tid, m0, n0, c + 2);
    else
      CP_COMMIT();         // empty group keeps wait accounting uniform
#pragma unroll
    for (int kk = 0; kk < 4; ++kk) {
      uint32_t af[3][4], bf[8][2];
#pragma unroll
      for (int mi = 0; mi < 3; ++mi) {
        int row = wm + mi * 16 + a_row_off;
        ldsm_x4(af[mi], sbase + SWZ(row * 128 + kk * 32 + a_kb_off));
      }
#pragma unroll
      for (int p = 0; p < 4; ++p) {
        int rowb = wn + p * 16 + b_row_off;
        uint32_t t4[4];
        ldsm_x4(t4, sbase + B_OFF + SWZ(rowb * 128 + kk * 32 + b_kb_off));
        bf[p * 2][0] = t4[0]; bf[p * 2][1] = t4[1];
        bf[p * 2 + 1][0] = t4[2]; bf[p * 2 + 1][1] = t4[3];
      }
#pragma unroll
      for (int mi = 0; mi < 3; ++mi)
#pragma unroll
        for (int ni = 0; ni < 8; ++ni)
          mma_bf16(acc[mi][ni], af[mi], bf[ni]);
    }
  }

  // ---- epilogue: C += bias (+relu) ----
  const int crow0 = m0 + wm + (lane >> 2);
  const int ccol0 = n0 + wn + (lane & 3) * 2;
#pragma unroll
  for (int ni = 0; ni < 8; ++ni) {
    int coln = ccol0 + ni * 8;
    float b0 = bias[coln], b1 = bias[coln + 1];
#pragma unroll
    for (int mi = 0; mi < 3; ++mi) {
      int rA = crow0 + mi * 16;
      int rB = rA + 8;
      float v0 = acc[mi][ni][0] + b0, v1 = acc[mi][ni][1] + b1;
      float v2 = acc[mi][ni][2] + b0, v3 = acc[mi][ni][3] + b1;
      if (TO_GH) {
        v0 = fmaxf(v0, 0.f); v1 = fmaxf(v1, 0.f);
        v2 = fmaxf(v2, 0.f); v3 = fmaxf(v3, 0.f);
      }
      if (rA < N_NODES) *(float2*)(Cbase + (size_t)rA * HDIM + coln) = make_float2(v0, v1);
      if (rB < N_NODES) *(float2*)(Cbase + (size_t)rB * HDIM + coln) = make_float2(v2, v3);
    }
  }
}

// ================== launch ===================================================
extern "C" void kernel_launch(void* const* d_in, const int* in_sizes, int n_in,
                              void* d_out, int out_size) {
  const float* x        = (const float*)d_in[0];
  const int* edge_index = (const int*)d_in[1];
  const int* edge_type  = (const int*)d_in[2];
  const float* basis1   = (const float*)d_in[3];
  const float* att1     = (const float*)d_in[4];
  const float* gw1      = (const float*)d_in[5];
  const float* root1    = (const float*)d_in[6];
  const float* bias1    = (const float*)d_in[7];
  const float* basis2   = (const float*)d_in[8];
  const float* att2     = (const float*)d_in[9];
  const float* gw2      = (const float*)d_in[10];
  const float* root2    = (const float*)d_in[11];
  const float* bias2    = (const float*)d_in[12];
  float* out = (float*)d_out;

  cudaFuncSetAttribute(gemm_kernel<true>,  cudaFuncAttributeMaxDynamicSharedMemorySize, SMEM_GEMM);
  cudaFuncSetAttribute(gemm_kernel<false>, cudaFuncAttributeMaxDynamicSharedMemorySize, SMEM_GEMM);

  dim3 gemmGrid(HDIM / NTILE, MT_TILES);  // 2 x 74 = 148 CTAs
  dim3 wtGrid(KDIM / 32, HDIM / 32);      // 48 x 16
  int gateBlocks = (N_NODES + 7) / 8;
  int segBlocks = (NSEG + 7) / 8;
  int eBlocks = (N_EDGES + 255) / 256;

  // ---- CSR build (graph constant across both layers) ----
  zero_cnt_kernel<<<(NSEG + 255) / 256, 256>>>();
  count_kernel<<<eBlocks, 256>>>(edge_index, edge_type);
  scan_kernel<<<1, 256>>>();
  fill_kernel<<<eBlocks, 256>>>(edge_index, edge_type);

  // ---- layer 1 (source = x) ----
  build_Wt_kernel<<<wtGrid, 256>>>(basis1, att1, root1);
  gatesplit_kernel<false><<<gateBlocks, 256>>>(x, gw1);
  gather_kernel<false><<<segBlocks, 256>>>(x);
  gemm_kernel<true><<<gemmGrid, GTHREADS, SMEM_GEMM>>>(bias1, nullptr);  // -> g_H (relu)

  // ---- layer 2 (source = g_H) ----
  build_Wt_kernel<<<wtGrid, 256>>>(basis2, att2, root2);
  gatesplit_kernel<true><<<gateBlocks, 256>>>(nullptr, gw2);
  gather_kernel<true><<<segBlocks, 256>>>(nullptr);
  gemm_kernel<false><<<gemmGrid, GTHREADS, SMEM_GEMM>>>(bias2, out);
}

// round 13
// speedup vs baseline: 3.7035x; 1.0617x over previous
#include <cuda_runtime.h>
#include <cuda_bf16.h>
#include <cstdint>
#include <math.h>

#define N_NODES 10000
#define N_EDGES 160000
#define HDIM 512
#define NREL 2
#define NBASES 30
#define KDIM 1536          // logical fp32 activation width [S0 | S1 | x]
#define KA 3072            // bf16 A cols: [hi(1536) | lo(1536)]
#define KB 4608            // bf16 Wt cols: [Wh | Wh | Wl]
#define NSEG (N_NODES * NREL)
#define MTILE 144
#define MT_TILES 74
#define MPAD (MT_TILES * MTILE)  // 10656
#define NTILE 256

// ---------------- scratch (static device globals; no allocs) ----------------
__device__ float g_H[(size_t)N_NODES * HDIM];
__device__ float g_Gate[N_NODES * NREL];
__device__ int g_Cnt[NSEG];               // zero at rest (.bss + fill restores)
__device__ int g_Off[NSEG + 1];
__device__ int g_ECol[N_EDGES];
__device__ __align__(256) __nv_bfloat16 g_Abf[(size_t)MPAD * KA];  // pad rows stay 0 (.bss)
__device__ __align__(256) __nv_bfloat16 g_Wt[2][(size_t)HDIM * KB];  // double-buffered

// ============================ PTX helpers (sm_100 base ISA only) =============
__device__ __forceinline__ uint32_t smem_u32(const void* p) {
  uint32_t a;
  asm("{ .reg .u64 t; cvta.to.shared.u64 t, %1; cvt.u32.u64 %0, t; }" : "=r"(a) : "l"(p));
  return a;
}
__device__ __forceinline__ void cp_async16(uint32_t s, const void* g) {
  asm volatile("cp.async.cg.shared.global [%0], [%1], 16;" :: "r"(s), "l"(g));
}
#define CP_COMMIT() asm volatile("cp.async.commit_group;")
template <int N> __device__ __forceinline__ void cp_wait() {
  asm volatile("cp.async.wait_group %0;" :: "n"(N));
}

#define SWZ(o) ((o) ^ (((o) >> 3) & 0x70))

__device__ __forceinline__ void ldsm_x4(uint32_t* r, uint32_t addr) {
  asm volatile("ldmatrix.sync.aligned.m8n8.x4.shared.b16 {%0,%1,%2,%3}, [%4];"
               : "=r"(r[0]), "=r"(r[1]), "=r"(r[2]), "=r"(r[3]) : "r"(addr));
}
__device__ __forceinline__ void mma_bf16(float* c, const uint32_t* a, const uint32_t* b) {
  asm volatile(
      "mma.sync.aligned.m16n8k16.row.col.f32.bf16.bf16.f32 "
      "{%0,%1,%2,%3}, {%4,%5,%6,%7}, {%8,%9}, {%0,%1,%2,%3};"
      : "+f"(c[0]), "+f"(c[1]), "+f"(c[2]), "+f"(c[3])
      : "r"(a[0]), "r"(a[1]), "r"(a[2]), "r"(a[3]), "r"(b[0]), "r"(b[1]));
}

// ================== CSR build ==============================================
__global__ void count_kernel(const int* __restrict__ edge_index,
                             const int* __restrict__ edge_type) {
  int e = blockIdx.x * blockDim.x + threadIdx.x;
  if (e >= N_EDGES) return;
  int seg = edge_index[e] * 2 + edge_type[e];
  atomicAdd(&g_Cnt[seg], 1);
}
__global__ void scan_kernel() {  // single block of 256 threads; g_Cnt preserved
  __shared__ int part[256];
  const int t = threadIdx.x;
  const int CH = (NSEG + 255) / 256;  // 79
  int s = 0;
  for (int i = 0; i < CH; ++i) {
    int idx = t * CH + i;
    if (idx < NSEG) s += g_Cnt[idx];
  }
  part[t] = s;
  __syncthreads();
  for (int off = 1; off < 256; off <<= 1) {
    int u = (t >= off) ? part[t - off] : 0;
    __syncthreads();
    part[t] += u;
    __syncthreads();
  }
  int run = part[t] - s;  // exclusive base for this thread's chunk
  for (int i = 0; i < CH; ++i) {
    int idx = t * CH + i;
    if (idx < NSEG) {
      g_Off[idx] = run;
      run += g_Cnt[idx];
    }
  }
  if (t == 255) g_Off[NSEG] = run;
}
// atomicSub leaves g_Cnt at zero after fill -> no zero kernel needed,
// invariant holds across graph replays (first launch sees .bss zeros).
__global__ void fill_kernel(const int* __restrict__ edge_index,
                            const int* __restrict__ edge_type) {
  int e = blockIdx.x * blockDim.x + threadIdx.x;
  if (e >= N_EDGES) return;
  int seg = edge_index[e] * 2 + edge_type[e];
  int pos = g_Off[seg] + atomicSub(&g_Cnt[seg], 1) - 1;
  g_ECol[pos] = edge_index[N_EDGES + e];
}

// ================== kernel: Wt = bf16-split combined weights ================
// Tile-transposed: coalesced basis reads (along n) + coalesced g_Wt writes
// (along k). Block computes a 32(k) x 32(n) tile via smem transpose.
template <int WSEL>
__global__ void build_Wt_kernel(const float* __restrict__ basis,
                                const float* __restrict__ att,
                                const float* __restrict__ root) {
  __shared__ unsigned short sH[32][33];
  __shared__ unsigned short sL[32][33];
  __shared__ float s_att[NREL * NBASES];
  int k0 = blockIdx.x * 32;  // 0..1535
  int n0 = blockIdx.y * 32;  // 0..511
  int tx = threadIdx.x & 31, ty = threadIdx.x >> 5;  // 32 x 8
  if (threadIdx.x < NREL * NBASES) s_att[threadIdx.x] = att[threadIdx.x];
  __syncthreads();
#pragma unroll
  for (int pass = 0; pass < 4; ++pass) {
    int kr = ty + pass * 8;          // 0..31
    int k = k0 + kr;
    int n = n0 + tx;
    float v;
    if (k < NREL * HDIM) {
      int r = k >> 9, i = k & 511;
      float acc = 0.f;
#pragma unroll
      for (int b = 0; b < NBASES; b++)
        acc += s_att[r * NBASES + b] * basis[(size_t)b * HDIM * HDIM + (size_t)i * HDIM + n];
      v = acc;
    } else {
      v = root[(size_t)(k - NREL * HDIM) * HDIM + n];
    }
    __nv_bfloat16 hi = __float2bfloat16(v);
    __nv_bfloat16 lo = __float2bfloat16(v - __bfloat162float(hi));
    sH[kr][tx] = *(unsigned short*)&hi;
    sL[kr][tx] = *(unsigned short*)&lo;
  }
  __syncthreads();
#pragma unroll
  for (int pass = 0; pass < 4; ++pass) {
    int nr = ty + pass * 8;          // 0..31
    int n = n0 + nr;
    int k = k0 + tx;
    unsigned short h = sH[tx][nr];
    unsigned short l = sL[tx][nr];
    size_t base = (size_t)n * KB + k;
    *(unsigned short*)&g_Wt[WSEL][base] = h;
    *(unsigned short*)&g_Wt[WSEL][base + 1536] = h;
    *(unsigned short*)&g_Wt[WSEL][base + 3072] = l;
  }
}

// ================== kernel: fused gates + x hi/lo split ======================
template <bool FROM_GH>
__global__ void gatesplit_kernel(const float* __restrict__ xin,
                                 const float* __restrict__ gw) {
  const float* x = FROM_GH ? g_H : xin;
  __shared__ float s_gw[NREL * HDIM];
  for (int i = threadIdx.x; i < NREL * HDIM; i += blockDim.x) s_gw[i] = gw[i];
  __syncthreads();
  int warp = (blockIdx.x * blockDim.x + threadIdx.x) >> 5;
  int lane = threadIdx.x & 31;
  if (warp >= N_NODES) return;
  const float4* xr = (const float4*)(x + (size_t)warp * HDIM);
  float d0 = 0.f, d1 = 0.f;
#pragma unroll
  for (int j = 0; j < 4; j++) {
    int c = lane + j * 32;
    float4 xv = xr[c];
    int base = c * 4;
    d0 += xv.x * s_gw[base] + xv.y * s_gw[base + 1] + xv.z * s_gw[base + 2] + xv.w * s_gw[base + 3];
    d1 += xv.x * s_gw[HDIM + base] + xv.y * s_gw[HDIM + base + 1] +
          xv.z * s_gw[HDIM + base + 2] + xv.w * s_gw[HDIM + base + 3];
    __nv_bfloat16 h0 = __float2bfloat16(xv.x), h1 = __float2bfloat16(xv.y);
    __nv_bfloat16 h2 = __float2bfloat16(xv.z), h3 = __float2bfloat16(xv.w);
    __nv_bfloat16 l0 = __float2bfloat16(xv.x - __bfloat162float(h0));
    __nv_bfloat16 l1 = __float2bfloat16(xv.y - __bfloat162float(h1));
    __nv_bfloat16 l2 = __float2bfloat16(xv.z - __bfloat162float(h2));
    __nv_bfloat16 l3 = __float2bfloat16(xv.w - __bfloat162float(h3));
    __nv_bfloat162 hp0(h0, h1), hp1(h2, h3), lp0(l0, l1), lp1(l2, l3);
    uint2 hw, lw;
    hw.x = *(uint32_t*)&hp0; hw.y = *(uint32_t*)&hp1;
    lw.x = *(uint32_t*)&lp0; lw.y = *(uint32_t*)&lp1;
    size_t base2 = (size_t)warp * KA + 1024 + 4 * c;
    *(uint2*)&g_Abf[base2] = hw;
    *(uint2*)&g_Abf[base2 + 1536] = lw;
  }
#pragma unroll
  for (int off = 16; off; off >>= 1) {
    d0 += __shfl_xor_sync(0xffffffffu, d0, off);
    d1 += __shfl_xor_sync(0xffffffffu, d1, off);
  }
  if (lane == 0) {
    g_Gate[warp * 2 + 0] = 1.f / (1.f + expf(-d0));
    g_Gate[warp * 2 + 1] = 1.f / (1.f + expf(-d1));
  }
}

// ================== kernel: CSR gather -> bf16 hi/lo S-segments ==============
template <bool FROM_GH>
__global__ void gather_kernel(const float* __restrict__ xin) {
  const float* x = FROM_GH ? g_H : xin;
  int seg = blockIdx.x * (blockDim.x >> 5) + (threadIdx.x >> 5);
  int lane = threadIdx.x & 31;
  if (seg >= NSEG) return;
  int node = seg >> 1, rel = seg & 1;
  int p = g_Off[seg], pe = g_Off[seg + 1];
  float4 a0 = {0, 0, 0, 0}, a1 = a0, a2 = a0, a3 = a0;
  if (p < pe) {
    int col = g_ECol[p];
    float g = g_Gate[col * 2 + rel];
    while (true) {
      const float4* xr = (const float4*)(x + (size_t)col * HDIM);
      float4 v0 = xr[lane], v1 = xr[lane + 32], v2 = xr[lane + 64], v3 = xr[lane + 96];
      ++p;
      bool more = (p < pe);
      int ncol = more ? g_ECol[p] : 0;
      float ng = more ? g_Gate[ncol * 2 + rel] : 0.f;
      a0.x += g * v0.x; a0.y += g * v0.y; a0.z += g * v0.z; a0.w += g * v0.w;
      a1.x += g * v1.x; a1.y += g * v1.y; a1.z += g * v1.z; a1.w += g * v1.w;
      a2.x += g * v2.x; a2.y += g * v2.y; a2.z += g * v2.z; a2.w += g * v2.w;
      a3.x += g * v3.x; a3.y += g * v3.y; a3.z += g * v3.z; a3.w += g * v3.w;
      if (!more) break;
      col = ncol;
      g = ng;
    }
  }
  size_t base = (size_t)node * KA + rel * 512 + 4 * lane;
  float4 av[4] = {a0, a1, a2, a3};
#pragma unroll
  for (int j = 0; j < 4; ++j) {
    float4 v = av[j];
    __nv_bfloat16 h0 = __float2bfloat16(v.x), h1 = __float2bfloat16(v.y);
    __nv_bfloat16 h2 = __float2bfloat16(v.z), h3 = __float2bfloat16(v.w);
    __nv_bfloat16 l0 = __float2bfloat16(v.x - __bfloat162float(h0));
    __nv_bfloat16 l1 = __float2bfloat16(v.y - __bfloat162float(h1));
    __nv_bfloat16 l2 = __float2bfloat16(v.z - __bfloat162float(h2));
    __nv_bfloat16 l3 = __float2bfloat16(v.w - __bfloat162float(h3));
    __nv_bfloat162 hp0(h0, h1), hp1(h2, h3), lp0(l0, l1), lp1(l2, l3);
    uint2 hw, lw;
    hw.x = *(uint32_t*)&hp0; hw.y = *(uint32_t*)&hp1;
    lw.x = *(uint32_t*)&lp0; lw.y = *(uint32_t*)&lp1;
    *(uint2*)&g_Abf[base + j * 128] = hw;
    *(uint2*)&g_Abf[base + 1536 + j * 128] = lw;
  }
}

// ================== kernel: mma.sync bf16 GEMM ===============================
// CTA tile 144(M) x 256(N), K'=4608. Grid = 74 x 2 = 148 CTAs = 1 per SM.
// 12 warps (3M x 4N), warp tile 48x64. 3-stage cp.async, ONE barrier/chunk.
constexpr int A_BYTES = MTILE * 128;          // 18432
constexpr int B_BYTES = NTILE * 128;          // 32768
constexpr int STAGE_BYTES = A_BYTES + B_BYTES;  // 51200
constexpr int B_OFF = A_BYTES;
constexpr int SMEM_GEMM = 3 * STAGE_BYTES;    // 153600
constexpr int NCHUNK = KB / 64;               // 72
constexpr int A_UNITS = MTILE * 8;            // 1152 16B units
constexpr int B_UNITS = NTILE * 8;            // 2048
constexpr int TOT_UNITS = A_UNITS + B_UNITS;  // 3200
constexpr int GTHREADS = 384;

template <int WSEL>
__device__ __forceinline__ void load_chunk(uint32_t sbase, int tid, int m0, int n0, int c) {
  int kA = (c < 48 ? c : c - 48) * 64;  // [0,24): hi  [24,48): lo  [48,72): hi again
  int kB = c * 64;
#pragma unroll
  for (int it = 0; it < 9; ++it) {
    int u = tid + it * GTHREADS;
    if (u >= TOT_UNITS) break;
    const __nv_bfloat16* src;
    uint32_t dst;
    if (u < A_UNITS) {
      int row = u >> 3, col16 = u & 7;
      src = g_Abf + (size_t)(m0 + row) * KA + kA + col16 * 8;
      dst = sbase + SWZ(row * 128 + col16 * 16);
    } else {
      int v = u - A_UNITS;
      int row = v >> 3, col16 = v & 7;
      src = g_Wt[WSEL] + (size_t)(n0 + row) * KB + kB + col16 * 8;
      dst = sbase + B_OFF + SWZ(row * 128 + col16 * 16);
    }
    cp_async16(dst, (const void*)src);
  }
  CP_COMMIT();
}

template <bool TO_GH, int WSEL>
__global__ void __launch_bounds__(GTHREADS, 1)
gemm_kernel(const float* __restrict__ bias, float* __restrict__ Cext) {
  extern __shared__ __align__(1024) char smem[];
  float* Cbase = TO_GH ? g_H : Cext;
  uint32_t sb = smem_u32(smem);
  const int tid = threadIdx.x;
  const int lane = tid & 31, wid = tid >> 5;           // wid 0..11
  const int wm = (wid % 3) * 48;                       // 3 M-warps
  const int wn = (wid / 3) * 64;                       // 4 N-warps
  const int m0 = blockIdx.y * MTILE;
  const int n0 = blockIdx.x * NTILE;

  const int r8 = lane & 7, grp = lane >> 3;
  const int a_row_off = r8 + (grp & 1) * 8;
  const int a_kb_off = (grp >> 1) * 16;
  const int b_row_off = r8 + (grp >> 1) * 8;
  const int b_kb_off = (grp & 1) * 16;

  float acc[3][8][4] = {};

  load_chunk<WSEL>(sb, tid, m0, n0, 0);
  load_chunk<WSEL>(sb + STAGE_BYTES, tid, m0, n0, 1);

  for (int c = 0; c < NCHUNK; ++c) {
    uint32_t sbase = sb + (c % 3) * STAGE_BYTES;
    cp_wait<1>();          // chunk c complete (all but most recent group done)
    __syncthreads();       // data visible; buf (c+2)%3 == (c-1)%3 now free
    if (c + 2 < NCHUNK)
      load_chunk<WSEL>(sb + ((c + 2) % 3) * STAGE_BYTES, tid, m0, n0, c + 2);
    else
      CP_COMMIT();         // empty group keeps wait accounting uniform
#pragma unroll
    for (int kk = 0; kk < 4; ++kk) {
      uint32_t af[3][4], bf[8][2];
#pragma unroll
      for (int mi = 0; mi < 3; ++mi) {
        int row = wm + mi * 16 + a_row_off;
        ldsm_x4(af[mi], sbase + SWZ(row * 128 + kk * 32 + a_kb_off));
      }
#pragma unroll
      for (int p = 0; p < 4; ++p) {
        int rowb = wn + p * 16 + b_row_off;
        uint32_t t4[4];
        ldsm_x4(t4, sbase + B_OFF + SWZ(rowb * 128 + kk * 32 + b_kb_off));
        bf[p * 2][0] = t4[0]; bf[p * 2][1] = t4[1];
        bf[p * 2 + 1][0] = t4[2]; bf[p * 2 + 1][1] = t4[3];
      }
#pragma unroll
      for (int mi = 0; mi < 3; ++mi)
#pragma unroll
        for (int ni = 0; ni < 8; ++ni)
          mma_bf16(acc[mi][ni], af[mi], bf[ni]);
    }
  }

  // ---- epilogue: C += bias (+relu) ----
  const int crow0 = m0 + wm + (lane >> 2);
  const int ccol0 = n0 + wn + (lane & 3) * 2;
#pragma unroll
  for (int ni = 0; ni < 8; ++ni) {
    int coln = ccol0 + ni * 8;
    float b0 = bias[coln], b1 = bias[coln + 1];
#pragma unroll
    for (int mi = 0; mi < 3; ++mi) {
      int rA = crow0 + mi * 16;
      int rB = rA + 8;
      float v0 = acc[mi][ni][0] + b0, v1 = acc[mi][ni][1] + b1;
      float v2 = acc[mi][ni][2] + b0, v3 = acc[mi][ni][3] + b1;
      if (TO_GH) {
        v0 = fmaxf(v0, 0.f); v1 = fmaxf(v1, 0.f);
        v2 = fmaxf(v2, 0.f); v3 = fmaxf(v3, 0.f);
      }
      if (rA < N_NODES) *(float2*)(Cbase + (size_t)rA * HDIM + coln) = make_float2(v0, v1);
      if (rB < N_NODES) *(float2*)(Cbase + (size_t)rB * HDIM + coln) = make_float2(v2, v3);
    }
  }
}

// ================== launch ===================================================
extern "C" void kernel_launch(void* const* d_in, const int* in_sizes, int n_in,
                              void* d_out, int out_size) {
  const float* x        = (const float*)d_in[0];
  const int* edge_index = (const int*)d_in[1];
  const int* edge_type  = (const int*)d_in[2];
  const float* basis1   = (const float*)d_in[3];
  const float* att1     = (const float*)d_in[4];
  const float* gw1      = (const float*)d_in[5];
  const float* root1    = (const float*)d_in[6];
  const float* bias1    = (const float*)d_in[7];
  const float* basis2   = (const float*)d_in[8];
  const float* att2     = (const float*)d_in[9];
  const float* gw2      = (const float*)d_in[10];
  const float* root2    = (const float*)d_in[11];
  const float* bias2    = (const float*)d_in[12];
  float* out = (float*)d_out;

  // One-time creation of side stream + events (first call; before capture).
  static cudaStream_t s2 = nullptr;
  static cudaEvent_t evFork = nullptr, evCSR = nullptr, evW2 = nullptr;
  if (s2 == nullptr) {
    cudaStreamCreateWithFlags(&s2, cudaStreamNonBlocking);
    cudaEventCreateWithFlags(&evFork, cudaEventDisableTiming);
    cudaEventCreateWithFlags(&evCSR, cudaEventDisableTiming);
    cudaEventCreateWithFlags(&evW2, cudaEventDisableTiming);
    cudaFuncSetAttribute(gemm_kernel<true, 0>,  cudaFuncAttributeMaxDynamicSharedMemorySize, SMEM_GEMM);
    cudaFuncSetAttribute(gemm_kernel<false, 1>, cudaFuncAttributeMaxDynamicSharedMemorySize, SMEM_GEMM);
  }

  dim3 gemmGrid(HDIM / NTILE, MT_TILES);  // 2 x 74 = 148 CTAs
  dim3 wtGrid(KDIM / 32, HDIM / 32);      // 48 x 16
  int gateBlocks = (N_NODES + 7) / 8;
  int segBlocks = (NSEG + 7) / 8;
  int eBlocks = (N_EDGES + 255) / 256;

  // ---- fork side chain: Wt1, CSR, Wt2 (all depend only on external inputs) --
  cudaEventRecord(evFork, 0);
  cudaStreamWaitEvent(s2, evFork, 0);
  build_Wt_kernel<0><<<wtGrid, 256, 0, s2>>>(basis1, att1, root1);
  count_kernel<<<eBlocks, 256, 0, s2>>>(edge_index, edge_type);
  scan_kernel<<<1, 256, 0, s2>>>();
  fill_kernel<<<eBlocks, 256, 0, s2>>>(edge_index, edge_type);
  cudaEventRecord(evCSR, s2);             // covers Wt1 + CSR
  build_Wt_kernel<1><<<wtGrid, 256, 0, s2>>>(basis2, att2, root2);
  cudaEventRecord(evW2, s2);

  // ---- main chain (legacy stream) ----
  gatesplit_kernel<false><<<gateBlocks, 256>>>(x, gw1);
  cudaStreamWaitEvent(0, evCSR, 0);       // gather1 needs CSR (and gemm1 Wt1)
  gather_kernel<false><<<segBlocks, 256>>>(x);
  gemm_kernel<true, 0><<<gemmGrid, GTHREADS, SMEM_GEMM>>>(bias1, nullptr);  // -> g_H

  gatesplit_kernel<true><<<gateBlocks, 256>>>(nullptr, gw2);
  gather_kernel<true><<<segBlocks, 256>>>(nullptr);
  cudaStreamWaitEvent(0, evW2, 0);        // gemm2 needs Wt2
  gemm_kernel<false, 1><<<gemmGrid, GTHREADS, SMEM_GEMM>>>(bias2, out);
}

// round 14
// speedup vs baseline: 4.5665x; 1.2330x over previous
#include <cuda_runtime.h>
#include <cuda_fp16.h>
#include <cstdint>
#include <math.h>

#define N_NODES 10000
#define N_EDGES 160000
#define HDIM 512
#define NREL 2
#define NBASES 30
#define KDIM 1536          // logical fp32 activation width [S0 | S1 | x]
#define KA 3072            // fp16 A cols: [hi(1536) | lo(1536)]
#define KB 3072            // fp16 Wt cols: [Wh | Wh]
#define NSEG (N_NODES * NREL)
#define MTILE 144
#define MT_TILES 74
#define MPAD (MT_TILES * MTILE)  // 10656
#define NTILE 256

// ---------------- scratch (static device globals; no allocs) ----------------
__device__ float g_H[(size_t)N_NODES * HDIM];
__device__ float g_GateRaw1[NSEG];        // layer-1 raw gate dots (gatesplit)
__device__ float g_GateRaw2[NSEG];        // layer-2 raw gate dots (gemm1 epilogue atomics)
__device__ int g_Cnt[NSEG];               // zero at rest (.bss + fill restores)
__device__ int g_Off[NSEG + 1];
__device__ int g_ECol[N_EDGES];
__device__ __align__(256) __half g_A16[(size_t)MPAD * KA];   // pad rows stay 0 (.bss)
__device__ __align__(256) __half g_Wt[2][(size_t)HDIM * KB]; // double-buffered

// ============================ PTX helpers (sm_100 base ISA only) =============
__device__ __forceinline__ uint32_t smem_u32(const void* p) {
  uint32_t a;
  asm("{ .reg .u64 t; cvta.to.shared.u64 t, %1; cvt.u32.u64 %0, t; }" : "=r"(a) : "l"(p));
  return a;
}
__device__ __forceinline__ void cp_async16(uint32_t s, const void* g) {
  asm volatile("cp.async.cg.shared.global [%0], [%1], 16;" :: "r"(s), "l"(g));
}
#define CP_COMMIT() asm volatile("cp.async.commit_group;")
template <int N> __device__ __forceinline__ void cp_wait() {
  asm volatile("cp.async.wait_group %0;" :: "n"(N));
}

#define SWZ(o) ((o) ^ (((o) >> 3) & 0x70))

__device__ __forceinline__ void ldsm_x4(uint32_t* r, uint32_t addr) {
  asm volatile("ldmatrix.sync.aligned.m8n8.x4.shared.b16 {%0,%1,%2,%3}, [%4];"
               : "=r"(r[0]), "=r"(r[1]), "=r"(r[2]), "=r"(r[3]) : "r"(addr));
}
__device__ __forceinline__ void mma_f16(float* c, const uint32_t* a, const uint32_t* b) {
  asm volatile(
      "mma.sync.aligned.m16n8k16.row.col.f32.f16.f16.f32 "
      "{%0,%1,%2,%3}, {%4,%5,%6,%7}, {%8,%9}, {%0,%1,%2,%3};"
      : "+f"(c[0]), "+f"(c[1]), "+f"(c[2]), "+f"(c[3])
      : "r"(a[0]), "r"(a[1]), "r"(a[2]), "r"(a[3]), "r"(b[0]), "r"(b[1]));
}

__device__ __forceinline__ void split16(float v, __half& hi, __half& lo) {
  hi = __float2half_rn(v);
  lo = __float2half_rn(v - __half2float(hi));
}

// ================== CSR build ==============================================
__global__ void zeroraw2_kernel() {
  int i = blockIdx.x * blockDim.x + threadIdx.x;
  if (i < NSEG) g_GateRaw2[i] = 0.f;
}
__global__ void count_kernel(const int* __restrict__ edge_index,
                             const int* __restrict__ edge_type) {
  int e = blockIdx.x * blockDim.x + threadIdx.x;
  if (e >= N_EDGES) return;
  int seg = edge_index[e] * 2 + edge_type[e];
  atomicAdd(&g_Cnt[seg], 1);
}
__global__ void scan_kernel() {  // single block of 256 threads; g_Cnt preserved
  __shared__ int part[256];
  const int t = threadIdx.x;
  const int CH = (NSEG + 255) / 256;  // 79
  int s = 0;
  for (int i = 0; i < CH; ++i) {
    int idx = t * CH + i;
    if (idx < NSEG) s += g_Cnt[idx];
  }
  part[t] = s;
  __syncthreads();
  for (int off = 1; off < 256; off <<= 1) {
    int u = (t >= off) ? part[t - off] : 0;
    __syncthreads();
    part[t] += u;
    __syncthreads();
  }
  int run = part[t] - s;
  for (int i = 0; i < CH; ++i) {
    int idx = t * CH + i;
    if (idx < NSEG) {
      g_Off[idx] = run;
      run += g_Cnt[idx];
    }
  }
  if (t == 255) g_Off[NSEG] = run;
}
__global__ void fill_kernel(const int* __restrict__ edge_index,
                            const int* __restrict__ edge_type) {
  int e = blockIdx.x * blockDim.x + threadIdx.x;
  if (e >= N_EDGES) return;
  int seg = edge_index[e] * 2 + edge_type[e];
  int pos = g_Off[seg] + atomicSub(&g_Cnt[seg], 1) - 1;
  g_ECol[pos] = edge_index[N_EDGES + e];
}

// ================== kernel: Wt = fp16 combined weights [Wh|Wh] ==============
template <int WSEL>
__global__ void build_Wt_kernel(const float* __restrict__ basis,
                                const float* __restrict__ att,
                                const float* __restrict__ root) {
  __shared__ unsigned short sH[32][33];
  __shared__ float s_att[NREL * NBASES];
  int k0 = blockIdx.x * 32;  // 0..1535
  int n0 = blockIdx.y * 32;  // 0..511
  int tx = threadIdx.x & 31, ty = threadIdx.x >> 5;  // 32 x 8
  if (threadIdx.x < NREL * NBASES) s_att[threadIdx.x] = att[threadIdx.x];
  __syncthreads();
#pragma unroll
  for (int pass = 0; pass < 4; ++pass) {
    int kr = ty + pass * 8;
    int k = k0 + kr;
    int n = n0 + tx;
    float v;
    if (k < NREL * HDIM) {
      int r = k >> 9, i = k & 511;
      float acc = 0.f;
#pragma unroll
      for (int b = 0; b < NBASES; b++)
        acc += s_att[r * NBASES + b] * basis[(size_t)b * HDIM * HDIM + (size_t)i * HDIM + n];
      v = acc;
    } else {
      v = root[(size_t)(k - NREL * HDIM) * HDIM + n];
    }
    __half hi = __float2half_rn(v);
    sH[kr][tx] = *(unsigned short*)&hi;
  }
  __syncthreads();
#pragma unroll
  for (int pass = 0; pass < 4; ++pass) {
    int nr = ty + pass * 8;
    int n = n0 + nr;
    int k = k0 + tx;
    unsigned short h = sH[tx][nr];
    size_t base = (size_t)n * KB + k;
    *(unsigned short*)&g_Wt[WSEL][base] = h;
    *(unsigned short*)&g_Wt[WSEL][base + 1536] = h;
  }
}

// ================== kernel: layer-1 fused raw gates + x fp16 hi/lo split =====
__global__ void gatesplit_kernel(const float* __restrict__ x,
                                 const float* __restrict__ gw) {
  __shared__ float s_gw[NREL * HDIM];
  for (int i = threadIdx.x; i < NREL * HDIM; i += blockDim.x) s_gw[i] = gw[i];
  __syncthreads();
  int warp = (blockIdx.x * blockDim.x + threadIdx.x) >> 5;
  int lane = threadIdx.x & 31;
  if (warp >= N_NODES) return;
  const float4* xr = (const float4*)(x + (size_t)warp * HDIM);
  float d0 = 0.f, d1 = 0.f;
#pragma unroll
  for (int j = 0; j < 4; j++) {
    int c = lane + j * 32;
    float4 xv = xr[c];
    int base = c * 4;
    d0 += xv.x * s_gw[base] + xv.y * s_gw[base + 1] + xv.z * s_gw[base + 2] + xv.w * s_gw[base + 3];
    d1 += xv.x * s_gw[HDIM + base] + xv.y * s_gw[HDIM + base + 1] +
          xv.z * s_gw[HDIM + base + 2] + xv.w * s_gw[HDIM + base + 3];
    __half h0, h1, h2, h3, l0, l1, l2, l3;
    split16(xv.x, h0, l0); split16(xv.y, h1, l1);
    split16(xv.z, h2, l2); split16(xv.w, h3, l3);
    __half2 hp0(h0, h1), hp1(h2, h3), lp0(l0, l1), lp1(l2, l3);
    uint2 hw, lw;
    hw.x = *(uint32_t*)&hp0; hw.y = *(uint32_t*)&hp1;
    lw.x = *(uint32_t*)&lp0; lw.y = *(uint32_t*)&lp1;
    size_t base2 = (size_t)warp * KA + 1024 + 4 * c;
    *(uint2*)&g_A16[base2] = hw;
    *(uint2*)&g_A16[base2 + 1536] = lw;
  }
#pragma unroll
  for (int off = 16; off; off >>= 1) {
    d0 += __shfl_xor_sync(0xffffffffu, d0, off);
    d1 += __shfl_xor_sync(0xffffffffu, d1, off);
  }
  if (lane == 0) {
    g_GateRaw1[warp * 2 + 0] = d0;
    g_GateRaw1[warp * 2 + 1] = d1;
  }
}

// ================== kernel: CSR gather -> fp16 hi/lo S-segments ==============
// gate = sigmoid(raw) applied here.
template <bool FROM_GH, int GBUF>
__global__ void gather_kernel(const float* __restrict__ xin) {
  const float* x = FROM_GH ? g_H : xin;
  const float* graw = (GBUF == 1) ? g_GateRaw1 : g_GateRaw2;
  int seg = blockIdx.x * (blockDim.x >> 5) + (threadIdx.x >> 5);
  int lane = threadIdx.x & 31;
  if (seg >= NSEG) return;
  int node = seg >> 1, rel = seg & 1;
  int p = g_Off[seg], pe = g_Off[seg + 1];
  float4 a0 = {0, 0, 0, 0}, a1 = a0, a2 = a0, a3 = a0;
  if (p < pe) {
    int col = g_ECol[p];
    float g = 1.f / (1.f + expf(-graw[col * 2 + rel]));
    while (true) {
      const float4* xr = (const float4*)(x + (size_t)col * HDIM);
      float4 v0 = xr[lane], v1 = xr[lane + 32], v2 = xr[lane + 64], v3 = xr[lane + 96];
      ++p;
      bool more = (p < pe);
      int ncol = more ? g_ECol[p] : 0;
      float ng = more ? (1.f / (1.f + expf(-graw[ncol * 2 + rel]))) : 0.f;
      a0.x += g * v0.x; a0.y += g * v0.y; a0.z += g * v0.z; a0.w += g * v0.w;
      a1.x += g * v1.x; a1.y += g * v1.y; a1.z += g * v1.z; a1.w += g * v1.w;
      a2.x += g * v2.x; a2.y += g * v2.y; a2.z += g * v2.z; a2.w += g * v2.w;
      a3.x += g * v3.x; a3.y += g * v3.y; a3.z += g * v3.z; a3.w += g * v3.w;
      if (!more) break;
      col = ncol;
      g = ng;
    }
  }
  size_t base = (size_t)node * KA + rel * 512 + 4 * lane;
  float4 av[4] = {a0, a1, a2, a3};
#pragma unroll
  for (int j = 0; j < 4; ++j) {
    float4 v = av[j];
    __half h0, h1, h2, h3, l0, l1, l2, l3;
    split16(v.x, h0, l0); split16(v.y, h1, l1);
    split16(v.z, h2, l2); split16(v.w, h3, l3);
    __half2 hp0(h0, h1), hp1(h2, h3), lp0(l0, l1), lp1(l2, l3);
    uint2 hw, lw;
    hw.x = *(uint32_t*)&hp0; hw.y = *(uint32_t*)&hp1;
    lw.x = *(uint32_t*)&lp0; lw.y = *(uint32_t*)&lp1;
    *(uint2*)&g_A16[base + j * 128] = hw;
    *(uint2*)&g_A16[base + 1536 + j * 128] = lw;
  }
}

// ================== kernel: mma.sync fp16 GEMM ===============================
// CTA tile 144(M) x 256(N), K'=3072. Grid = 74 x 2 = 148 CTAs = 1 per SM.
// 12 warps (3M x 4N), warp tile 48x64. 3-stage cp.async, ONE barrier/chunk.
// TO_GH epilogue: writes g_H fp32 + fp16 hi/lo of h into g_A16 + raw layer-2
// gate partials via atomics.
constexpr int A_BYTES = MTILE * 128;            // 18432
constexpr int B_BYTES = NTILE * 128;            // 32768
constexpr int STAGE_BYTES = A_BYTES + B_BYTES;  // 51200
constexpr int B_OFF = A_BYTES;
constexpr int SMEM_GEMM = 3 * STAGE_BYTES;      // 153600
constexpr int NCHUNK = KB / 64;                 // 48
constexpr int A_UNITS = MTILE * 8;              // 1152 16B units
constexpr int B_UNITS = NTILE * 8;              // 2048
constexpr int TOT_UNITS = A_UNITS + B_UNITS;    // 3200
constexpr int GTHREADS = 384;

template <int WSEL>
__device__ __forceinline__ void load_chunk(uint32_t sbase, int tid, int m0, int n0, int c) {
  int kA = c * 64;
  int kB = c * 64;
#pragma unroll
  for (int it = 0; it < 9; ++it) {
    int u = tid + it * GTHREADS;
    if (u >= TOT_UNITS) break;
    const __half* src;
    uint32_t dst;
    if (u < A_UNITS) {
      int row = u >> 3, col16 = u & 7;
      src = g_A16 + (size_t)(m0 + row) * KA + kA + col16 * 8;
      dst = sbase + SWZ(row * 128 + col16 * 16);
    } else {
      int v = u - A_UNITS;
      int row = v >> 3, col16 = v & 7;
      src = g_Wt[WSEL] + (size_t)(n0 + row) * KB + kB + col16 * 8;
      dst = sbase + B_OFF + SWZ(row * 128 + col16 * 16);
    }
    cp_async16(dst, (const void*)src);
  }
  CP_COMMIT();
}

template <bool TO_GH, int WSEL>
__global__ void __launch_bounds__(GTHREADS, 1)
gemm_kernel(const float* __restrict__ bias, const float* __restrict__ gw_next,
            float* __restrict__ Cext) {
  extern __shared__ __align__(1024) char smem[];
  float* Cbase = TO_GH ? g_H : Cext;
  uint32_t sb = smem_u32(smem);
  const int tid = threadIdx.x;
  const int lane = tid & 31, wid = tid >> 5;           // wid 0..11
  const int wm = (wid % 3) * 48;                       // 3 M-warps
  const int wn = (wid / 3) * 64;                       // 4 N-warps
  const int m0 = blockIdx.y * MTILE;
  const int n0 = blockIdx.x * NTILE;

  const int r8 = lane & 7, grp = lane >> 3;
  const int a_row_off = r8 + (grp & 1) * 8;
  const int a_kb_off = (grp >> 1) * 16;
  const int b_row_off = r8 + (grp >> 1) * 8;
  const int b_kb_off = (grp & 1) * 16;

  float acc[3][8][4] = {};

  load_chunk<WSEL>(sb, tid, m0, n0, 0);
  load_chunk<WSEL>(sb + STAGE_BYTES, tid, m0, n0, 1);

  for (int c = 0; c < NCHUNK; ++c) {
    uint32_t sbase = sb + (c % 3) * STAGE_BYTES;
    cp_wait<1>();
    __syncthreads();
    if (c + 2 < NCHUNK)
      load_chunk<WSEL>(sb + ((c + 2) % 3) * STAGE_BYTES, tid, m0, n0, c + 2);
    else
      CP_COMMIT();         // empty group keeps wait accounting uniform
#pragma unroll
    for (int kk = 0; kk < 4; ++kk) {
      uint32_t af[3][4], bf[8][2];
#pragma unroll
      for (int mi = 0; mi < 3; ++mi) {
        int row = wm + mi * 16 + a_row_off;
        ldsm_x4(af[mi], sbase + SWZ(row * 128 + kk * 32 + a_kb_off));
      }
#pragma unroll
      for (int p = 0; p < 4; ++p) {
        int rowb = wn + p * 16 + b_row_off;
        uint32_t t4[4];
        ldsm_x4(t4, sbase + B_OFF + SWZ(rowb * 128 + kk * 32 + b_kb_off));
        bf[p * 2][0] = t4[0]; bf[p * 2][1] = t4[1];
        bf[p * 2 + 1][0] = t4[2]; bf[p * 2 + 1][1] = t4[3];
      }
#pragma unroll
      for (int mi = 0; mi < 3; ++mi)
#pragma unroll
        for (int ni = 0; ni < 8; ++ni)
          mma_f16(acc[mi][ni], af[mi], bf[ni]);
    }
  }

  // ---- epilogue ----
  const int crow0 = m0 + wm + (lane >> 2);
  const int ccol0 = n0 + wn + (lane & 3) * 2;
  float gwa0[8], gwa1[8], gwb0[8], gwb1[8];  // gw_next[rel][col] for our cols
  if (TO_GH) {
#pragma unroll
    for (int ni = 0; ni < 8; ++ni) {
      int coln = ccol0 + ni * 8;
      gwa0[ni] = gw_next[coln];
      gwa1[ni] = gw_next[coln + 1];
      gwb0[ni] = gw_next[HDIM + coln];
      gwb1[ni] = gw_next[HDIM + coln + 1];
    }
  }
#pragma unroll
  for (int mi = 0; mi < 3; ++mi) {
    int rA = crow0 + mi * 16;
    int rB = rA + 8;
    float pA0 = 0.f, pA1 = 0.f, pB0 = 0.f, pB1 = 0.f;
#pragma unroll
    for (int ni = 0; ni < 8; ++ni) {
      int coln = ccol0 + ni * 8;
      float b0 = bias[coln], b1 = bias[coln + 1];
      float v0 = acc[mi][ni][0] + b0, v1 = acc[mi][ni][1] + b1;
      float v2 = acc[mi][ni][2] + b0, v3 = acc[mi][ni][3] + b1;
      if (TO_GH) {
        v0 = fmaxf(v0, 0.f); v1 = fmaxf(v1, 0.f);
        v2 = fmaxf(v2, 0.f); v3 = fmaxf(v3, 0.f);
        pA0 += v0 * gwa0[ni] + v1 * gwa1[ni];
        pA1 += v0 * gwb0[ni] + v1 * gwb1[ni];
        pB0 += v2 * gwa0[ni] + v3 * gwa1[ni];
        pB1 += v2 * gwb0[ni] + v3 * gwb1[ni];
        // fp16 hi/lo split of h directly into A16 cols [1024,1536)/[2560,3072)
        __half h0, h1, l0, l1, h2, h3, l2, l3;
        split16(v0, h0, l0); split16(v1, h1, l1);
        split16(v2, h2, l2); split16(v3, h3, l3);
        __half2 hA(h0, h1), lA(l0, l1), hB(h2, h3), lB(l2, l3);
        if (rA < N_NODES) {
          *(__half2*)&g_A16[(size_t)rA * KA + 1024 + coln] = hA;
          *(__half2*)&g_A16[(size_t)rA * KA + 2560 + coln] = lA;
        }
        if (rB < N_NODES) {
          *(__half2*)&g_A16[(size_t)rB * KA + 1024 + coln] = hB;
          *(__half2*)&g_A16[(size_t)rB * KA + 2560 + coln] = lB;
        }
      }
      if (rA < N_NODES) *(float2*)(Cbase + (size_t)rA * HDIM + coln) = make_float2(v0, v1);
      if (rB < N_NODES) *(float2*)(Cbase + (size_t)rB * HDIM + coln) = make_float2(v2, v3);
    }
    if (TO_GH) {
      if (rA < N_NODES) {
        atomicAdd(&g_GateRaw2[rA * 2 + 0], pA0);
        atomicAdd(&g_GateRaw2[rA * 2 + 1], pA1);
      }
      if (rB < N_NODES) {
        atomicAdd(&g_GateRaw2[rB * 2 + 0], pB0);
        atomicAdd(&g_GateRaw2[rB * 2 + 1], pB1);
      }
    }
  }
}

// ================== launch ===================================================
extern "C" void kernel_launch(void* const* d_in, const int* in_sizes, int n_in,
                              void* d_out, int out_size) {
  const float* x        = (const float*)d_in[0];
  const int* edge_index = (const int*)d_in[1];
  const int* edge_type  = (const int*)d_in[2];
  const float* basis1   = (const float*)d_in[3];
  const float* att1     = (const float*)d_in[4];
  const float* gw1      = (const float*)d_in[5];
  const float* root1    = (const float*)d_in[6];
  const float* bias1    = (const float*)d_in[7];
  const float* basis2   = (const float*)d_in[8];
  const float* att2     = (const float*)d_in[9];
  const float* gw2      = (const float*)d_in[10];
  const float* root2    = (const float*)d_in[11];
  const float* bias2    = (const float*)d_in[12];
  float* out = (float*)d_out;

  static cudaStream_t s2 = nullptr;
  static cudaEvent_t evFork = nullptr, evCSR = nullptr, evW2 = nullptr;
  if (s2 == nullptr) {
    cudaStreamCreateWithFlags(&s2, cudaStreamNonBlocking);
    cudaEventCreateWithFlags(&evFork, cudaEventDisableTiming);
    cudaEventCreateWithFlags(&evCSR, cudaEventDisableTiming);
    cudaEventCreateWithFlags(&evW2, cudaEventDisableTiming);
    cudaFuncSetAttribute(gemm_kernel<true, 0>,  cudaFuncAttributeMaxDynamicSharedMemorySize, SMEM_GEMM);
    cudaFuncSetAttribute(gemm_kernel<false, 1>, cudaFuncAttributeMaxDynamicSharedMemorySize, SMEM_GEMM);
  }

  dim3 gemmGrid(HDIM / NTILE, MT_TILES);  // 2 x 74 = 148 CTAs
  dim3 wtGrid(KDIM / 32, HDIM / 32);      // 48 x 16
  int gateBlocks = (N_NODES + 7) / 8;
  int segBlocks = (NSEG + 7) / 8;
  int eBlocks = (N_EDGES + 255) / 256;

  // ---- fork side chain: zero raw2, Wt1, CSR, Wt2 ----
  cudaEventRecord(evFork, 0);
  cudaStreamWaitEvent(s2, evFork, 0);
  zeroraw2_kernel<<<(NSEG + 255) / 256, 256, 0, s2>>>();
  build_Wt_kernel<0><<<wtGrid, 256, 0, s2>>>(basis1, att1, root1);
  count_kernel<<<eBlocks, 256, 0, s2>>>(edge_index, edge_type);
  scan_kernel<<<1, 256, 0, s2>>>();
  fill_kernel<<<eBlocks, 256, 0, s2>>>(edge_index, edge_type);
  cudaEventRecord(evCSR, s2);             // covers zero + Wt1 + CSR
  build_Wt_kernel<1><<<wtGrid, 256, 0, s2>>>(basis2, att2, root2);
  cudaEventRecord(evW2, s2);

  // ---- main chain ----
  gatesplit_kernel<<<gateBlocks, 256>>>(x, gw1);
  cudaStreamWaitEvent(0, evCSR, 0);
  gather_kernel<false, 1><<<segBlocks, 256>>>(x);
  gemm_kernel<true, 0><<<gemmGrid, GTHREADS, SMEM_GEMM>>>(bias1, gw2, nullptr);  // -> g_H + split + raw gates

  gather_kernel<true, 2><<<segBlocks, 256>>>(nullptr);
  cudaStreamWaitEvent(0, evW2, 0);
  gemm_kernel<false, 1><<<gemmGrid, GTHREADS, SMEM_GEMM>>>(bias2, nullptr, out);
}

// round 15
// speedup vs baseline: 4.6884x; 1.0267x over previous
#include <cuda_runtime.h>
#include <cuda_fp16.h>
#include <cstdint>
#include <math.h>

#define N_NODES 10000
#define N_EDGES 160000
#define HDIM 512
#define NREL 2
#define NBASES 30
#define KDIM 1536          // logical fp32 activation width [S0 | S1 | x]
#define KA 3072            // fp16 A cols: [hi(1536) | lo(1536)]
#define KB 3072            // fp16 Wt cols: [Wh | Wh]
#define NSEG (N_NODES * NREL)
#define MTILE 144
#define MT_TILES 74
#define MPAD (MT_TILES * MTILE)  // 10656
#define NTILE 256

// ---------------- scratch (static device globals; no allocs) ----------------
__device__ float g_H[(size_t)N_NODES * HDIM];
__device__ float g_GateRaw1[NSEG];        // layer-1 raw gate dots (gatesplit)
__device__ float g_GateRaw2[NSEG];        // layer-2 raw gate dots (gemm1 epilogue atomics)
__device__ int g_Cnt[NSEG];               // zero at rest (.bss + fill restores)
__device__ int g_Off[NSEG + 1];
__device__ int g_ECol[N_EDGES];
__device__ __align__(256) __half g_A16[(size_t)MPAD * KA];   // pad rows stay 0 (.bss)
__device__ __align__(256) __half g_Wt[2][(size_t)HDIM * KB]; // double-buffered

// ============================ PTX helpers (sm_100 base ISA only) =============
__device__ __forceinline__ uint32_t smem_u32(const void* p) {
  uint32_t a;
  asm("{ .reg .u64 t; cvta.to.shared.u64 t, %1; cvt.u32.u64 %0, t; }" : "=r"(a) : "l"(p));
  return a;
}
__device__ __forceinline__ void cp_async16(uint32_t s, const void* g) {
  asm volatile("cp.async.cg.shared.global [%0], [%1], 16;" :: "r"(s), "l"(g));
}
#define CP_COMMIT() asm volatile("cp.async.commit_group;")
template <int N> __device__ __forceinline__ void cp_wait() {
  asm volatile("cp.async.wait_group %0;" :: "n"(N));
}

#define SWZ(o) ((o) ^ (((o) >> 3) & 0x70))

__device__ __forceinline__ void ldsm_x4(uint32_t* r, uint32_t addr) {
  asm volatile("ldmatrix.sync.aligned.m8n8.x4.shared.b16 {%0,%1,%2,%3}, [%4];"
               : "=r"(r[0]), "=r"(r[1]), "=r"(r[2]), "=r"(r[3]) : "r"(addr));
}
__device__ __forceinline__ void mma_f16(float* c, const uint32_t* a, const uint32_t* b) {
  asm volatile(
      "mma.sync.aligned.m16n8k16.row.col.f32.f16.f16.f32 "
      "{%0,%1,%2,%3}, {%4,%5,%6,%7}, {%8,%9}, {%0,%1,%2,%3};"
      : "+f"(c[0]), "+f"(c[1]), "+f"(c[2]), "+f"(c[3])
      : "r"(a[0]), "r"(a[1]), "r"(a[2]), "r"(a[3]), "r"(b[0]), "r"(b[1]));
}

__device__ __forceinline__ void split16(float v, __half& hi, __half& lo) {
  hi = __float2half_rn(v);
  lo = __float2half_rn(v - __half2float(hi));
}

// ================== CSR build ==============================================
__global__ void zeroraw2_kernel() {
  int i = blockIdx.x * blockDim.x + threadIdx.x;
  if (i < NSEG) g_GateRaw2[i] = 0.f;
}
__global__ void count_kernel(const int* __restrict__ edge_index,
                             const int* __restrict__ edge_type) {
  int e = blockIdx.x * blockDim.x + threadIdx.x;
  if (e >= N_EDGES) return;
  int seg = edge_index[e] * 2 + edge_type[e];
  atomicAdd(&g_Cnt[seg], 1);
}
__global__ void scan_kernel() {  // single block, 1024 threads; g_Cnt preserved
  __shared__ int part[1024];
  const int t = threadIdx.x;
  const int CH = (NSEG + 1023) / 1024;  // 20
  int s = 0;
#pragma unroll
  for (int i = 0; i < CH; ++i) {
    int idx = t * CH + i;
    if (idx < NSEG) s += g_Cnt[idx];
  }
  part[t] = s;
  __syncthreads();
  for (int off = 1; off < 1024; off <<= 1) {
    int u = (t >= off) ? part[t - off] : 0;
    __syncthreads();
    part[t] += u;
    __syncthreads();
  }
  int run = part[t] - s;
#pragma unroll
  for (int i = 0; i < CH; ++i) {
    int idx = t * CH + i;
    if (idx < NSEG) {
      g_Off[idx] = run;
      run += g_Cnt[idx];
    }
  }
  if (t == 1023) g_Off[NSEG] = run;
}
__global__ void fill_kernel(const int* __restrict__ edge_index,
                            const int* __restrict__ edge_type) {
  int e = blockIdx.x * blockDim.x + threadIdx.x;
  if (e >= N_EDGES) return;
  int seg = edge_index[e] * 2 + edge_type[e];
  int pos = g_Off[seg] + atomicSub(&g_Cnt[seg], 1) - 1;
  g_ECol[pos] = edge_index[N_EDGES + e];
}

// ================== kernel: Wt = fp16 combined weights [Wh|Wh] ==============
template <int WSEL>
__global__ void build_Wt_kernel(const float* __restrict__ basis,
                                const float* __restrict__ att,
                                const float* __restrict__ root) {
  __shared__ unsigned short sH[32][33];
  __shared__ float s_att[NREL * NBASES];
  int k0 = blockIdx.x * 32;  // 0..1535
  int n0 = blockIdx.y * 32;  // 0..511
  int tx = threadIdx.x & 31, ty = threadIdx.x >> 5;  // 32 x 8
  if (threadIdx.x < NREL * NBASES) s_att[threadIdx.x] = att[threadIdx.x];
  __syncthreads();
#pragma unroll
  for (int pass = 0; pass < 4; ++pass) {
    int kr = ty + pass * 8;
    int k = k0 + kr;
    int n = n0 + tx;
    float v;
    if (k < NREL * HDIM) {
      int r = k >> 9, i = k & 511;
      float acc = 0.f;
#pragma unroll
      for (int b = 0; b < NBASES; b++)
        acc += s_att[r * NBASES + b] * basis[(size_t)b * HDIM * HDIM + (size_t)i * HDIM + n];
      v = acc;
    } else {
      v = root[(size_t)(k - NREL * HDIM) * HDIM + n];
    }
    __half hi = __float2half_rn(v);
    sH[kr][tx] = *(unsigned short*)&hi;
  }
  __syncthreads();
#pragma unroll
  for (int pass = 0; pass < 4; ++pass) {
    int nr = ty + pass * 8;
    int n = n0 + nr;
    int k = k0 + tx;
    unsigned short h = sH[tx][nr];
    size_t base = (size_t)n * KB + k;
    *(unsigned short*)&g_Wt[WSEL][base] = h;
    *(unsigned short*)&g_Wt[WSEL][base + 1536] = h;
  }
}

// ================== kernel: layer-1 fused raw gates + x fp16 hi/lo split =====
__global__ void gatesplit_kernel(const float* __restrict__ x,
                                 const float* __restrict__ gw) {
  __shared__ float s_gw[NREL * HDIM];
  for (int i = threadIdx.x; i < NREL * HDIM; i += blockDim.x) s_gw[i] = gw[i];
  __syncthreads();
  int warp = (blockIdx.x * blockDim.x + threadIdx.x) >> 5;
  int lane = threadIdx.x & 31;
  if (warp >= N_NODES) return;
  const float4* xr = (const float4*)(x + (size_t)warp * HDIM);
  float d0 = 0.f, d1 = 0.f;
#pragma unroll
  for (int j = 0; j < 4; j++) {
    int c = lane + j * 32;
    float4 xv = xr[c];
    int base = c * 4;
    d0 += xv.x * s_gw[base] + xv.y * s_gw[base + 1] + xv.z * s_gw[base + 2] + xv.w * s_gw[base + 3];
    d1 += xv.x * s_gw[HDIM + base] + xv.y * s_gw[HDIM + base + 1] +
          xv.z * s_gw[HDIM + base + 2] + xv.w * s_gw[HDIM + base + 3];
    __half h0, h1, h2, h3, l0, l1, l2, l3;
    split16(xv.x, h0, l0); split16(xv.y, h1, l1);
    split16(xv.z, h2, l2); split16(xv.w, h3, l3);
    __half2 hp0(h0, h1), hp1(h2, h3), lp0(l0, l1), lp1(l2, l3);
    uint2 hw, lw;
    hw.x = *(uint32_t*)&hp0; hw.y = *(uint32_t*)&hp1;
    lw.x = *(uint32_t*)&lp0; lw.y = *(uint32_t*)&lp1;
    size_t base2 = (size_t)warp * KA + 1024 + 4 * c;
    *(uint2*)&g_A16[base2] = hw;
    *(uint2*)&g_A16[base2 + 1536] = lw;
  }
#pragma unroll
  for (int off = 16; off; off >>= 1) {
    d0 += __shfl_xor_sync(0xffffffffu, d0, off);
    d1 += __shfl_xor_sync(0xffffffffu, d1, off);
  }
  if (lane == 0) {
    g_GateRaw1[warp * 2 + 0] = d0;
    g_GateRaw1[warp * 2 + 1] = d1;
  }
}

// ================== kernel: CSR gather (unroll x2) -> fp16 hi/lo =============
template <bool FROM_GH, int GBUF>
__global__ void gather_kernel(const float* __restrict__ xin) {
  const float* x = FROM_GH ? g_H : xin;
  const float* graw = (GBUF == 1) ? g_GateRaw1 : g_GateRaw2;
  int seg = blockIdx.x * (blockDim.x >> 5) + (threadIdx.x >> 5);
  int lane = threadIdx.x & 31;
  if (seg >= NSEG) return;
  int node = seg >> 1, rel = seg & 1;
  int p = g_Off[seg], pe = g_Off[seg + 1];
  float4 a0 = {0, 0, 0, 0}, a1 = a0, a2 = a0, a3 = a0;
  float4 b0 = a0, b1 = a0, b2 = a0, b3 = a0;
  for (; p + 1 < pe; p += 2) {
    int c0 = g_ECol[p], c1 = g_ECol[p + 1];
    float gA = 1.f / (1.f + expf(-graw[c0 * 2 + rel]));
    float gB = 1.f / (1.f + expf(-graw[c1 * 2 + rel]));
    const float4* xr0 = (const float4*)(x + (size_t)c0 * HDIM);
    const float4* xr1 = (const float4*)(x + (size_t)c1 * HDIM);
    float4 v0 = xr0[lane], v1 = xr0[lane + 32], v2 = xr0[lane + 64], v3 = xr0[lane + 96];
    float4 w0 = xr1[lane], w1 = xr1[lane + 32], w2 = xr1[lane + 64], w3 = xr1[lane + 96];
    a0.x += gA * v0.x; a0.y += gA * v0.y; a0.z += gA * v0.z; a0.w += gA * v0.w;
    a1.x += gA * v1.x; a1.y += gA * v1.y; a1.z += gA * v1.z; a1.w += gA * v1.w;
    a2.x += gA * v2.x; a2.y += gA * v2.y; a2.z += gA * v2.z; a2.w += gA * v2.w;
    a3.x += gA * v3.x; a3.y += gA * v3.y; a3.z += gA * v3.z; a3.w += gA * v3.w;
    b0.x += gB * w0.x; b0.y += gB * w0.y; b0.z += gB * w0.z; b0.w += gB * w0.w;
    b1.x += gB * w1.x; b1.y += gB * w1.y; b1.z += gB * w1.z; b1.w += gB * w1.w;
    b2.x += gB * w2.x; b2.y += gB * w2.y; b2.z += gB * w2.z; b2.w += gB * w2.w;
    b3.x += gB * w3.x; b3.y += gB * w3.y; b3.z += gB * w3.z; b3.w += gB * w3.w;
  }
  if (p < pe) {
    int c0 = g_ECol[p];
    float gA = 1.f / (1.f + expf(-graw[c0 * 2 + rel]));
    const float4* xr0 = (const float4*)(x + (size_t)c0 * HDIM);
    float4 v0 = xr0[lane], v1 = xr0[lane + 32], v2 = xr0[lane + 64], v3 = xr0[lane + 96];
    a0.x += gA * v0.x; a0.y += gA * v0.y; a0.z += gA * v0.z; a0.w += gA * v0.w;
    a1.x += gA * v1.x; a1.y += gA * v1.y; a1.z += gA * v1.z; a1.w += gA * v1.w;
    a2.x += gA * v2.x; a2.y += gA * v2.y; a2.z += gA * v2.z; a2.w += gA * v2.w;
    a3.x += gA * v3.x; a3.y += gA * v3.y; a3.z += gA * v3.z; a3.w += gA * v3.w;
  }
  a0.x += b0.x; a0.y += b0.y; a0.z += b0.z; a0.w += b0.w;
  a1.x += b1.x; a1.y += b1.y; a1.z += b1.z; a1.w += b1.w;
  a2.x += b2.x; a2.y += b2.y; a2.z += b2.z; a2.w += b2.w;
  a3.x += b3.x; a3.y += b3.y; a3.z += b3.z; a3.w += b3.w;
  size_t base = (size_t)node * KA + rel * 512 + 4 * lane;
  float4 av[4] = {a0, a1, a2, a3};
#pragma unroll
  for (int j = 0; j < 4; ++j) {
    float4 v = av[j];
    __half h0, h1, h2, h3, l0, l1, l2, l3;
    split16(v.x, h0, l0); split16(v.y, h1, l1);
    split16(v.z, h2, l2); split16(v.w, h3, l3);
    __half2 hp0(h0, h1), hp1(h2, h3), lp0(l0, l1), lp1(l2, l3);
    uint2 hw, lw;
    hw.x = *(uint32_t*)&hp0; hw.y = *(uint32_t*)&hp1;
    lw.x = *(uint32_t*)&lp0; lw.y = *(uint32_t*)&lp1;
    *(uint2*)&g_A16[base + j * 128] = hw;
    *(uint2*)&g_A16[base + 1536 + j * 128] = lw;
  }
}

// ================== kernel: mma.sync fp16 GEMM ===============================
// CTA tile 144(M) x 256(N), K'=3072. Grid = 74 x 2 = 148 CTAs = 1 per SM.
// 12 warps (3M x 4N), warp tile 48x64. 3-stage cp.async, ONE barrier/chunk.
constexpr int A_BYTES = MTILE * 128;            // 18432
constexpr int B_BYTES = NTILE * 128;            // 32768
constexpr int STAGE_BYTES = A_BYTES + B_BYTES;  // 51200
constexpr int B_OFF = A_BYTES;
constexpr int SMEM_GEMM = 3 * STAGE_BYTES;      // 153600
constexpr int NCHUNK = KB / 64;                 // 48
constexpr int A_UNITS = MTILE * 8;              // 1152 16B units
constexpr int B_UNITS = NTILE * 8;              // 2048
constexpr int TOT_UNITS = A_UNITS + B_UNITS;    // 3200
constexpr int GTHREADS = 384;

template <int WSEL>
__device__ __forceinline__ void load_chunk(uint32_t sbase, int tid, int m0, int n0, int c) {
  int kA = c * 64;
  int kB = c * 64;
#pragma unroll
  for (int it = 0; it < 9; ++it) {
    int u = tid + it * GTHREADS;
    if (u >= TOT_UNITS) break;
    const __half* src;
    uint32_t dst;
    if (u < A_UNITS) {
      int row = u >> 3, col16 = u & 7;
      src = g_A16 + (size_t)(m0 + row) * KA + kA + col16 * 8;
      dst = sbase + SWZ(row * 128 + col16 * 16);
    } else {
      int v = u - A_UNITS;
      int row = v >> 3, col16 = v & 7;
      src = g_Wt[WSEL] + (size_t)(n0 + row) * KB + kB + col16 * 8;
      dst = sbase + B_OFF + SWZ(row * 128 + col16 * 16);
    }
    cp_async16(dst, (const void*)src);
  }
  CP_COMMIT();
}

template <bool TO_GH, int WSEL>
__global__ void __launch_bounds__(GTHREADS, 1)
gemm_kernel(const float* __restrict__ bias, const float* __restrict__ gw_next,
            float* __restrict__ Cext) {
  extern __shared__ __align__(1024) char smem[];
  float* Cbase = TO_GH ? g_H : Cext;
  uint32_t sb = smem_u32(smem);
  const int tid = threadIdx.x;
  const int lane = tid & 31, wid = tid >> 5;           // wid 0..11
  const int wm = (wid % 3) * 48;                       // 3 M-warps
  const int wn = (wid / 3) * 64;                       // 4 N-warps
  const int m0 = blockIdx.y * MTILE;
  const int n0 = blockIdx.x * NTILE;

  const int r8 = lane & 7, grp = lane >> 3;
  const int a_row_off = r8 + (grp & 1) * 8;
  const int a_kb_off = (grp >> 1) * 16;
  const int b_row_off = r8 + (grp >> 1) * 8;
  const int b_kb_off = (grp & 1) * 16;

  float acc[3][8][4] = {};

  load_chunk<WSEL>(sb, tid, m0, n0, 0);
  load_chunk<WSEL>(sb + STAGE_BYTES, tid, m0, n0, 1);

  for (int c = 0; c < NCHUNK; ++c) {
    uint32_t sbase = sb + (c % 3) * STAGE_BYTES;
    cp_wait<1>();
    __syncthreads();
    if (c + 2 < NCHUNK)
      load_chunk<WSEL>(sb + ((c + 2) % 3) * STAGE_BYTES, tid, m0, n0, c + 2);
    else
      CP_COMMIT();         // empty group keeps wait accounting uniform
#pragma unroll
    for (int kk = 0; kk < 4; ++kk) {
      uint32_t af[3][4], bf[8][2];
#pragma unroll
      for (int mi = 0; mi < 3; ++mi) {
        int row = wm + mi * 16 + a_row_off;
        ldsm_x4(af[mi], sbase + SWZ(row * 128 + kk * 32 + a_kb_off));
      }
#pragma unroll
      for (int p = 0; p < 4; ++p) {
        int rowb = wn + p * 16 + b_row_off;
        uint32_t t4[4];
        ldsm_x4(t4, sbase + B_OFF + SWZ(rowb * 128 + kk * 32 + b_kb_off));
        bf[p * 2][0] = t4[0]; bf[p * 2][1] = t4[1];
        bf[p * 2 + 1][0] = t4[2]; bf[p * 2 + 1][1] = t4[3];
      }
#pragma unroll
      for (int mi = 0; mi < 3; ++mi)
#pragma unroll
        for (int ni = 0; ni < 8; ++ni)
          mma_f16(acc[mi][ni], af[mi], bf[ni]);
    }
  }

  // ---- epilogue ----
  const int crow0 = m0 + wm + (lane >> 2);
  const int ccol0 = n0 + wn + (lane & 3) * 2;
  float gwa0[8], gwa1[8], gwb0[8], gwb1[8];
  if (TO_GH) {
#pragma unroll
    for (int ni = 0; ni < 8; ++ni) {
      int coln = ccol0 + ni * 8;
      gwa0[ni] = gw_next[coln];
      gwa1[ni] = gw_next[coln + 1];
      gwb0[ni] = gw_next[HDIM + coln];
      gwb1[ni] = gw_next[HDIM + coln + 1];
    }
  }
#pragma unroll
  for (int mi = 0; mi < 3; ++mi) {
    int rA = crow0 + mi * 16;
    int rB = rA + 8;
    float pA0 = 0.f, pA1 = 0.f, pB0 = 0.f, pB1 = 0.f;
#pragma unroll
    for (int ni = 0; ni < 8; ++ni) {
      int coln = ccol0 + ni * 8;
      float b0 = bias[coln], b1 = bias[coln + 1];
      float v0 = acc[mi][ni][0] + b0, v1 = acc[mi][ni][1] + b1;
      float v2 = acc[mi][ni][2] + b0, v3 = acc[mi][ni][3] + b1;
      if (TO_GH) {
        v0 = fmaxf(v0, 0.f); v1 = fmaxf(v1, 0.f);
        v2 = fmaxf(v2, 0.f); v3 = fmaxf(v3, 0.f);
        pA0 += v0 * gwa0[ni] + v1 * gwa1[ni];
        pA1 += v0 * gwb0[ni] + v1 * gwb1[ni];
        pB0 += v2 * gwa0[ni] + v3 * gwa1[ni];
        pB1 += v2 * gwb0[ni] + v3 * gwb1[ni];
        __half h0, h1, l0, l1, h2, h3, l2, l3;
        split16(v0, h0, l0); split16(v1, h1, l1);
        split16(v2, h2, l2); split16(v3, h3, l3);
        __half2 hA(h0, h1), lA(l0, l1), hB(h2, h3), lB(l2, l3);
        if (rA < N_NODES) {
          *(__half2*)&g_A16[(size_t)rA * KA + 1024 + coln] = hA;
          *(__half2*)&g_A16[(size_t)rA * KA + 2560 + coln] = lA;
        }
        if (rB < N_NODES) {
          *(__half2*)&g_A16[(size_t)rB * KA + 1024 + coln] = hB;
          *(__half2*)&g_A16[(size_t)rB * KA + 2560 + coln] = lB;
        }
      }
      if (rA < N_NODES) *(float2*)(Cbase + (size_t)rA * HDIM + coln) = make_float2(v0, v1);
      if (rB < N_NODES) *(float2*)(Cbase + (size_t)rB * HDIM + coln) = make_float2(v2, v3);
    }
    if (TO_GH) {
      if (rA < N_NODES) {
        atomicAdd(&g_GateRaw2[rA * 2 + 0], pA0);
        atomicAdd(&g_GateRaw2[rA * 2 + 1], pA1);
      }
      if (rB < N_NODES) {
        atomicAdd(&g_GateRaw2[rB * 2 + 0], pB0);
        atomicAdd(&g_GateRaw2[rB * 2 + 1], pB1);
      }
    }
  }
}

// ================== launch ===================================================
extern "C" void kernel_launch(void* const* d_in, const int* in_sizes, int n_in,
                              void* d_out, int out_size) {
  const float* x        = (const float*)d_in[0];
  const int* edge_index = (const int*)d_in[1];
  const int* edge_type  = (const int*)d_in[2];
  const float* basis1   = (const float*)d_in[3];
  const float* att1     = (const float*)d_in[4];
  const float* gw1      = (const float*)d_in[5];
  const float* root1    = (const float*)d_in[6];
  const float* bias1    = (const float*)d_in[7];
  const float* basis2   = (const float*)d_in[8];
  const float* att2     = (const float*)d_in[9];
  const float* gw2      = (const float*)d_in[10];
  const float* root2    = (const float*)d_in[11];
  const float* bias2    = (const float*)d_in[12];
  float* out = (float*)d_out;

  static cudaStream_t s2 = nullptr;
  static cudaEvent_t evFork = nullptr, evCSR = nullptr, evW1 = nullptr, evW2 = nullptr;
  if (s2 == nullptr) {
    cudaStreamCreateWithFlags(&s2, cudaStreamNonBlocking);
    cudaEventCreateWithFlags(&evFork, cudaEventDisableTiming);
    cudaEventCreateWithFlags(&evCSR, cudaEventDisableTiming);
    cudaEventCreateWithFlags(&evW1, cudaEventDisableTiming);
    cudaEventCreateWithFlags(&evW2, cudaEventDisableTiming);
    cudaFuncSetAttribute(gemm_kernel<true, 0>,  cudaFuncAttributeMaxDynamicSharedMemorySize, SMEM_GEMM);
    cudaFuncSetAttribute(gemm_kernel<false, 1>, cudaFuncAttributeMaxDynamicSharedMemorySize, SMEM_GEMM);
  }

  dim3 gemmGrid(HDIM / NTILE, MT_TILES);  // 2 x 74 = 148 CTAs
  dim3 wtGrid(KDIM / 32, HDIM / 32);      // 48 x 16
  int gateBlocks = (N_NODES + 7) / 8;
  int segBlocks = (NSEG + 7) / 8;
  int eBlocks = (N_EDGES + 255) / 256;

  // ---- fork side chain: CSR first (gates gather1), then Wt1, Wt2 ----
  cudaEventRecord(evFork, 0);
  cudaStreamWaitEvent(s2, evFork, 0);
  zeroraw2_kernel<<<(NSEG + 255) / 256, 256, 0, s2>>>();
  count_kernel<<<eBlocks, 256, 0, s2>>>(edge_index, edge_type);
  scan_kernel<<<1, 1024, 0, s2>>>();
  fill_kernel<<<eBlocks, 256, 0, s2>>>(edge_index, edge_type);
  cudaEventRecord(evCSR, s2);             // covers zero + CSR
  build_Wt_kernel<0><<<wtGrid, 256, 0, s2>>>(basis1, att1, root1);
  cudaEventRecord(evW1, s2);
  build_Wt_kernel<1><<<wtGrid, 256, 0, s2>>>(basis2, att2, root2);
  cudaEventRecord(evW2, s2);

  // ---- main chain ----
  gatesplit_kernel<<<gateBlocks, 256>>>(x, gw1);
  cudaStreamWaitEvent(0, evCSR, 0);
  gather_kernel<false, 1><<<segBlocks, 256>>>(x);
  cudaStreamWaitEvent(0, evW1, 0);
  gemm_kernel<true, 0><<<gemmGrid, GTHREADS, SMEM_GEMM>>>(bias1, gw2, nullptr);  // -> g_H + split + raw gates

  gather_kernel<true, 2><<<segBlocks, 256>>>(nullptr);
  cudaStreamWaitEvent(0, evW2, 0);
  gemm_kernel<false, 1><<<gemmGrid, GTHREADS, SMEM_GEMM>>>(bias2, nullptr, out);
}

// round 17
// speedup vs baseline: 6.5753x; 1.4025x over previous
#include <cuda_runtime.h>
#include <cuda_fp16.h>
#include <cstdint>
#include <math.h>

#define N_NODES 10000
#define N_EDGES 160000
#define HDIM 512
#define NREL 2
#define NBASES 30
#define KA 1536            // fp16 A cols: [S0 | S1 | x]  (hi only)
#define KB 1536            // fp16 Wt cols: [Wh]
#define NSEG (N_NODES * NREL)
#define MTILE 144
#define MT_TILES 74
#define MPAD (MT_TILES * MTILE)  // 10656
#define NTILE 256

// ---------------- scratch (static device globals; no allocs) ----------------
__device__ float g_H[(size_t)N_NODES * HDIM];
__device__ float g_GateRaw1[NSEG];        // layer-1 raw gate dots (gatesplit)
__device__ float g_GateRaw2[NSEG];        // layer-2 raw gate dots (gemm1 epilogue atomics)
__device__ int g_Cnt[NSEG];               // zero at rest (.bss + fill restores)
__device__ int g_Off[NSEG + 1];
__device__ int g_ECol[N_EDGES];
__device__ __align__(256) __half g_A16[(size_t)MPAD * KA];   // pad rows stay 0 (.bss)
__device__ __align__(256) __half g_Wt[2][(size_t)HDIM * KB]; // double-buffered

// ============================ PTX helpers (sm_100 base ISA only) =============
__device__ __forceinline__ uint32_t smem_u32(const void* p) {
  uint32_t a;
  asm("{ .reg .u64 t; cvta.to.shared.u64 t, %1; cvt.u32.u64 %0, t; }" : "=r"(a) : "l"(p));
  return a;
}
__device__ __forceinline__ void cp_async16(uint32_t s, const void* g) {
  asm volatile("cp.async.cg.shared.global [%0], [%1], 16;" :: "r"(s), "l"(g));
}
#define CP_COMMIT() asm volatile("cp.async.commit_group;")
template <int N> __device__ __forceinline__ void cp_wait() {
  asm volatile("cp.async.wait_group %0;" :: "n"(N));
}

#define SWZ(o) ((o) ^ (((o) >> 3) & 0x70))

__device__ __forceinline__ void ldsm_x4(uint32_t* r, uint32_t addr) {
  asm volatile("ldmatrix.sync.aligned.m8n8.x4.shared.b16 {%0,%1,%2,%3}, [%4];"
               : "=r"(r[0]), "=r"(r[1]), "=r"(r[2]), "=r"(r[3]) : "r"(addr));
}
__device__ __forceinline__ void mma_f16(float* c, const uint32_t* a, const uint32_t* b) {
  asm volatile(
      "mma.sync.aligned.m16n8k16.row.col.f32.f16.f16.f32 "
      "{%0,%1,%2,%3}, {%4,%5,%6,%7}, {%8,%9}, {%0,%1,%2,%3};"
      : "+f"(c[0]), "+f"(c[1]), "+f"(c[2]), "+f"(c[3])
      : "r"(a[0]), "r"(a[1]), "r"(a[2]), "r"(a[3]), "r"(b[0]), "r"(b[1]));
}

// ================== CSR build ==============================================
__global__ void zeroraw2_kernel() {
  int i = blockIdx.x * blockDim.x + threadIdx.x;
  if (i < NSEG) g_GateRaw2[i] = 0.f;
}
__global__ void count_kernel(const int* __restrict__ edge_index,
                             const int* __restrict__ edge_type) {
  int e = blockIdx.x * blockDim.x + threadIdx.x;
  if (e >= N_EDGES) return;
  int seg = edge_index[e] * 2 + edge_type[e];
  atomicAdd(&g_Cnt[seg], 1);
}
__global__ void scan_kernel() {  // single block, 1024 threads; g_Cnt preserved
  __shared__ int part[1024];
  const int t = threadIdx.x;
  const int CH = (NSEG + 1023) / 1024;  // 20
  int s = 0;
#pragma unroll
  for (int i = 0; i < CH; ++i) {
    int idx = t * CH + i;
    if (idx < NSEG) s += g_Cnt[idx];
  }
  part[t] = s;
  __syncthreads();
  for (int off = 1; off < 1024; off <<= 1) {
    int u = (t >= off) ? part[t - off] : 0;
    __syncthreads();
    part[t] += u;
    __syncthreads();
  }
  int run = part[t] - s;
#pragma unroll
  for (int i = 0; i < CH; ++i) {
    int idx = t * CH + i;
    if (idx < NSEG) {
      g_Off[idx] = run;
      run += g_Cnt[idx];
    }
  }
  if (t == 1023) g_Off[NSEG] = run;
}
__global__ void fill_kernel(const int* __restrict__ edge_index,
                            const int* __restrict__ edge_type) {
  int e = blockIdx.x * blockDim.x + threadIdx.x;
  if (e >= N_EDGES) return;
  int seg = edge_index[e] * 2 + edge_type[e];
  int pos = g_Off[seg] + atomicSub(&g_Cnt[seg], 1) - 1;
  g_ECol[pos] = edge_index[N_EDGES + e];
}

// ================== kernel: Wt = fp16 combined weights [Wh] =================
template <int WSEL>
__global__ void build_Wt_kernel(const float* __restrict__ basis,
                                const float* __restrict__ att,
                                const float* __restrict__ root) {
  __shared__ unsigned short sH[32][33];
  __shared__ float s_att[NREL * NBASES];
  int k0 = blockIdx.x * 32;  // 0..1535
  int n0 = blockIdx.y * 32;  // 0..511
  int tx = threadIdx.x & 31, ty = threadIdx.x >> 5;  // 32 x 8
  if (threadIdx.x < NREL * NBASES) s_att[threadIdx.x] = att[threadIdx.x];
  __syncthreads();
#pragma unroll
  for (int pass = 0; pass < 4; ++pass) {
    int kr = ty + pass * 8;
    int k = k0 + kr;
    int n = n0 + tx;
    float v;
    if (k < NREL * HDIM) {
      int r = k >> 9, i = k & 511;
      float acc = 0.f;
#pragma unroll
      for (int b = 0; b < NBASES; b++)
        acc += s_att[r * NBASES + b] * basis[(size_t)b * HDIM * HDIM + (size_t)i * HDIM + n];
      v = acc;
    } else {
      v = root[(size_t)(k - NREL * HDIM) * HDIM + n];
    }
    __half hi = __float2half_rn(v);
    sH[kr][tx] = *(unsigned short*)&hi;
  }
  __syncthreads();
#pragma unroll
  for (int pass = 0; pass < 4; ++pass) {
    int nr = ty + pass * 8;
    int n = n0 + nr;
    int k = k0 + tx;
    *(unsigned short*)&g_Wt[WSEL][(size_t)n * KB + k] = sH[tx][nr];
  }
}

// ================== kernel: layer-1 fused raw gates + x fp16 =================
__global__ void gatesplit_kernel(const float* __restrict__ x,
                                 const float* __restrict__ gw) {
  __shared__ float s_gw[NREL * HDIM];
  for (int i = threadIdx.x; i < NREL * HDIM; i += blockDim.x) s_gw[i] = gw[i];
  __syncthreads();
  int warp = (blockIdx.x * blockDim.x + threadIdx.x) >> 5;
  int lane = threadIdx.x & 31;
  if (warp >= N_NODES) return;
  const float4* xr = (const float4*)(x + (size_t)warp * HDIM);
  float d0 = 0.f, d1 = 0.f;
#pragma unroll
  for (int j = 0; j < 4; j++) {
    int c = lane + j * 32;
    float4 xv = xr[c];
    int base = c * 4;
    d0 += xv.x * s_gw[base] + xv.y * s_gw[base + 1] + xv.z * s_gw[base + 2] + xv.w * s_gw[base + 3];
    d1 += xv.x * s_gw[HDIM + base] + xv.y * s_gw[HDIM + base + 1] +
          xv.z * s_gw[HDIM + base + 2] + xv.w * s_gw[HDIM + base + 3];
    __half2 hp0(__float2half_rn(xv.x), __float2half_rn(xv.y));
    __half2 hp1(__float2half_rn(xv.z), __float2half_rn(xv.w));
    uint2 hw;
    hw.x = *(uint32_t*)&hp0; hw.y = *(uint32_t*)&hp1;
    *(uint2*)&g_A16[(size_t)warp * KA + 1024 + 4 * c] = hw;
  }
#pragma unroll
  for (int off = 16; off; off >>= 1) {
    d0 += __shfl_xor_sync(0xffffffffu, d0, off);
    d1 += __shfl_xor_sync(0xffffffffu, d1, off);
  }
  if (lane == 0) {
    g_GateRaw1[warp * 2 + 0] = d0;
    g_GateRaw1[warp * 2 + 1] = d1;
  }
}

// ================== kernel: CSR gather (unroll x2) -> fp16 ===================
template <bool FROM_GH, int GBUF>
__global__ void gather_kernel(const float* __restrict__ xin) {
  const float* x = FROM_GH ? g_H : xin;
  const float* graw = (GBUF == 1) ? g_GateRaw1 : g_GateRaw2;
  int seg = blockIdx.x * (blockDim.x >> 5) + (threadIdx.x >> 5);
  int lane = threadIdx.x & 31;
  if (seg >= NSEG) return;
  int node = seg >> 1, rel = seg & 1;
  int p = g_Off[seg], pe = g_Off[seg + 1];
  float4 a0 = {0, 0, 0, 0}, a1 = a0, a2 = a0, a3 = a0;
  float4 b0 = a0, b1 = a0, b2 = a0, b3 = a0;
  for (; p + 1 < pe; p += 2) {
    int c0 = g_ECol[p], c1 = g_ECol[p + 1];
    float gA = 1.f / (1.f + expf(-graw[c0 * 2 + rel]));
    float gB = 1.f / (1.f + expf(-graw[c1 * 2 + rel]));
    const float4* xr0 = (const float4*)(x + (size_t)c0 * HDIM);
    const float4* xr1 = (const float4*)(x + (size_t)c1 * HDIM);
    float4 v0 = xr0[lane], v1 = xr0[lane + 32], v2 = xr0[lane + 64], v3 = xr0[lane + 96];
    float4 w0 = xr1[lane], w1 = xr1[lane + 32], w2 = xr1[lane + 64], w3 = xr1[lane + 96];
    a0.x += gA * v0.x; a0.y += gA * v0.y; a0.z += gA * v0.z; a0.w += gA * v0.w;
    a1.x += gA * v1.x; a1.y += gA * v1.y; a1.z += gA * v1.z; a1.w += gA * v1.w;
    a2.x += gA * v2.x; a2.y += gA * v2.y; a2.z += gA * v2.z; a2.w += gA * v2.w;
    a3.x += gA * v3.x; a3.y += gA * v3.y; a3.z += gA * v3.z; a3.w += gA * v3.w;
    b0.x += gB * w0.x; b0.y += gB * w0.y; b0.z += gB * w0.z; b0.w += gB * w0.w;
    b1.x += gB * w1.x; b1.y += gB * w1.y; b1.z += gB * w1.z; b1.w += gB * w1.w;
    b2.x += gB * w2.x; b2.y += gB * w2.y; b2.z += gB * w2.z; b2.w += gB * w2.w;
    b3.x += gB * w3.x; b3.y += gB * w3.y; b3.z += gB * w3.z; b3.w += gB * w3.w;
  }
  if (p < pe) {
    int c0 = g_ECol[p];
    float gA = 1.f / (1.f + expf(-graw[c0 * 2 + rel]));
    const float4* xr0 = (const float4*)(x + (size_t)c0 * HDIM);
    float4 v0 = xr0[lane], v1 = xr0[lane + 32], v2 = xr0[lane + 64], v3 = xr0[lane + 96];
    a0.x += gA * v0.x; a0.y += gA * v0.y; a0.z += gA * v0.z; a0.w += gA * v0.w;
    a1.x += gA * v1.x; a1.y += gA * v1.y; a1.z += gA * v1.z; a1.w += gA * v1.w;
    a2.x += gA * v2.x; a2.y += gA * v2.y; a2.z += gA * v2.z; a2.w += gA * v2.w;
    a3.x += gA * v3.x; a3.y += gA * v3.y; a3.z += gA * v3.z; a3.w += gA * v3.w;
  }
  a0.x += b0.x; a0.y += b0.y; a0.z += b0.z; a0.w += b0.w;
  a1.x += b1.x; a1.y += b1.y; a1.z += b1.z; a1.w += b1.w;
  a2.x += b2.x; a2.y += b2.y; a2.z += b2.z; a2.w += b2.w;
  a3.x += b3.x; a3.y += b3.y; a3.z += b3.z; a3.w += b3.w;
  size_t base = (size_t)node * KA + rel * 512 + 4 * lane;
  float4 av[4] = {a0, a1, a2, a3};
#pragma unroll
  for (int j = 0; j < 4; ++j) {
    float4 v = av[j];
    __half2 hp0(__float2half_rn(v.x), __float2half_rn(v.y));
    __half2 hp1(__float2half_rn(v.z), __float2half_rn(v.w));
    uint2 hw;
    hw.x = *(uint32_t*)&hp0; hw.y = *(uint32_t*)&hp1;
    *(uint2*)&g_A16[base + j * 128] = hw;
  }
}

// ================== kernel: mma.sync fp16 GEMM ===============================
// CTA tile 144(M) x 256(N), K'=1536. Grid = 74 x 2 = 148 CTAs = 1 per SM.
// 12 warps (3M x 4N), warp tile 48x64. 3-stage cp.async, ONE barrier/chunk.
constexpr int A_BYTES = MTILE * 128;            // 18432
constexpr int B_BYTES = NTILE * 128;            // 32768
constexpr int STAGE_BYTES = A_BYTES + B_BYTES;  // 51200
constexpr int B_OFF = A_BYTES;
constexpr int SMEM_GEMM = 3 * STAGE_BYTES;      // 153600
constexpr int NCHUNK = KB / 64;                 // 24
constexpr int A_UNITS = MTILE * 8;              // 1152 16B units
constexpr int B_UNITS = NTILE * 8;              // 2048
constexpr int TOT_UNITS = A_UNITS + B_UNITS;    // 3200
constexpr int GTHREADS = 384;

template <int WSEL>
__device__ __forceinline__ void load_chunk(uint32_t sbase, int tid, int m0, int n0, int c) {
  int kA = c * 64;
  int kB = c * 64;
#pragma unroll
  for (int it = 0; it < 9; ++it) {
    int u = tid + it * GTHREADS;
    if (u >= TOT_UNITS) break;
    const __half* src;
    uint32_t dst;
    if (u < A_UNITS) {
      int row = u >> 3, col16 = u & 7;
      src = g_A16 + (size_t)(m0 + row) * KA + kA + col16 * 8;
      dst = sbase + SWZ(row * 128 + col16 * 16);
    } else {
      int v = u - A_UNITS;
      int row = v >> 3, col16 = v & 7;
      src = g_Wt[WSEL] + (size_t)(n0 + row) * KB + kB + col16 * 8;
      dst = sbase + B_OFF + SWZ(row * 128 + col16 * 16);
    }
    cp_async16(dst, (const void*)src);
  }
  CP_COMMIT();
}

template <bool TO_GH, int WSEL>
__global__ void __launch_bounds__(GTHREADS, 1)
gemm_kernel(const float* __restrict__ bias, const float* __restrict__ gw_next,
            float* __restrict__ Cext) {
  extern __shared__ __align__(1024) char smem[];
  float* Cbase = TO_GH ? g_H : Cext;
  uint32_t sb = smem_u32(smem);
  const int tid = threadIdx.x;
  const int lane = tid & 31, wid = tid >> 5;           // wid 0..11
  const int wm = (wid % 3) * 48;                       // 3 M-warps
  const int wn = (wid / 3) * 64;                       // 4 N-warps
  const int m0 = blockIdx.y * MTILE;
  const int n0 = blockIdx.x * NTILE;

  const int r8 = lane & 7, grp = lane >> 3;
  const int a_row_off = r8 + (grp & 1) * 8;
  const int a_kb_off = (grp >> 1) * 16;
  const int b_row_off = r8 + (grp >> 1) * 8;
  const int b_kb_off = (grp & 1) * 16;

  float acc[3][8][4] = {};

  load_chunk<WSEL>(sb, tid, m0, n0, 0);
  load_chunk<WSEL>(sb + STAGE_BYTES, tid, m0, n0, 1);

  for (int c = 0; c < NCHUNK; ++c) {
    uint32_t sbase = sb + (c % 3) * STAGE_BYTES;
    cp_wait<1>();
    __syncthreads();
    if (c + 2 < NCHUNK)
      load_chunk<WSEL>(sb + ((c + 2) % 3) * STAGE_BYTES, tid, m0, n0, c + 2);
    else
      CP_COMMIT();         // empty group keeps wait accounting uniform
#pragma unroll
    for (int kk = 0; kk < 4; ++kk) {
      uint32_t af[3][4], bf[8][2];
#pragma unroll
      for (int mi = 0; mi < 3; ++mi) {
        int row = wm + mi * 16 + a_row_off;
        ldsm_x4(af[mi], sbase + SWZ(row * 128 + kk * 32 + a_kb_off));
      }
#pragma unroll
      for (int p = 0; p < 4; ++p) {
        int rowb = wn + p * 16 + b_row_off;
        uint32_t t4[4];
        ldsm_x4(t4, sbase + B_OFF + SWZ(rowb * 128 + kk * 32 + b_kb_off));
        bf[p * 2][0] = t4[0]; bf[p * 2][1] = t4[1];
        bf[p * 2 + 1][0] = t4[2]; bf[p * 2 + 1][1] = t4[3];
      }
#pragma unroll
      for (int mi = 0; mi < 3; ++mi)
#pragma unroll
        for (int ni = 0; ni < 8; ++ni)
          mma_f16(acc[mi][ni], af[mi], bf[ni]);
    }
  }

  // ---- epilogue ----
  const int crow0 = m0 + wm + (lane >> 2);
  const int ccol0 = n0 + wn + (lane & 3) * 2;
  float gwa0[8], gwa1[8], gwb0[8], gwb1[8];
  if (TO_GH) {
#pragma unroll
    for (int ni = 0; ni < 8; ++ni) {
      int coln = ccol0 + ni * 8;
      gwa0[ni] = gw_next[coln];
      gwa1[ni] = gw_next[coln + 1];
      gwb0[ni] = gw_next[HDIM + coln];
      gwb1[ni] = gw_next[HDIM + coln + 1];
    }
  }
#pragma unroll
  for (int mi = 0; mi < 3; ++mi) {
    int rA = crow0 + mi * 16;
    int rB = rA + 8;
    float pA0 = 0.f, pA1 = 0.f, pB0 = 0.f, pB1 = 0.f;
#pragma unroll
    for (int ni = 0; ni < 8; ++ni) {
      int coln = ccol0 + ni * 8;
      float b0 = bias[coln], b1 = bias[coln + 1];
      float v0 = acc[mi][ni][0] + b0, v1 = acc[mi][ni][1] + b1;
      float v2 = acc[mi][ni][2] + b0, v3 = acc[mi][ni][3] + b1;
      if (TO_GH) {
        v0 = fmaxf(v0, 0.f); v1 = fmaxf(v1, 0.f);
        v2 = fmaxf(v2, 0.f); v3 = fmaxf(v3, 0.f);
        pA0 += v0 * gwa0[ni] + v1 * gwa1[ni];
        pA1 += v0 * gwb0[ni] + v1 * gwb1[ni];
        pB0 += v2 * gwa0[ni] + v3 * gwa1[ni];
        pB1 += v2 * gwb0[ni] + v3 * gwb1[ni];
        __half2 hA(__float2half_rn(v0), __float2half_rn(v1));
        __half2 hB(__float2half_rn(v2), __float2half_rn(v3));
        if (rA < N_NODES) *(__half2*)&g_A16[(size_t)rA * KA + 1024 + coln] = hA;
        if (rB < N_NODES) *(__half2*)&g_A16[(size_t)rB * KA + 1024 + coln] = hB;
      }
      if (rA < N_NODES) *(float2*)(Cbase + (size_t)rA * HDIM + coln) = make_float2(v0, v1);
      if (rB < N_NODES) *(float2*)(Cbase + (size_t)rB * HDIM + coln) = make_float2(v2, v3);
    }
    if (TO_GH) {
      if (rA < N_NODES) {
        atomicAdd(&g_GateRaw2[rA * 2 + 0], pA0);
        atomicAdd(&g_GateRaw2[rA * 2 + 1], pA1);
      }
      if (rB < N_NODES) {
        atomicAdd(&g_GateRaw2[rB * 2 + 0], pB0);
        atomicAdd(&g_GateRaw2[rB * 2 + 1], pB1);
      }
    }
  }
}

// ================== launch ===================================================
extern "C" void kernel_launch(void* const* d_in, const int* in_sizes, int n_in,
                              void* d_out, int out_size) {
  const float* x        = (const float*)d_in[0];
  const int* edge_index = (const int*)d_in[1];
  const int* edge_type  = (const int*)d_in[2];
  const float* basis1   = (const float*)d_in[3];
  const float* att1     = (const float*)d_in[4];
  const float* gw1      = (const float*)d_in[5];
  const float* root1    = (const float*)d_in[6];
  const float* bias1    = (const float*)d_in[7];
  const float* basis2   = (const float*)d_in[8];
  const float* att2     = (const float*)d_in[9];
  const float* gw2      = (const float*)d_in[10];
  const float* root2    = (const float*)d_in[11];
  const float* bias2    = (const float*)d_in[12];
  float* out = (float*)d_out;

  static cudaStream_t s2 = nullptr;
  static cudaEvent_t evFork = nullptr, evCSR = nullptr, evW1 = nullptr, evW2 = nullptr;
  if (s2 == nullptr) {
    cudaStreamCreateWithFlags(&s2, cudaStreamNonBlocking);
    cudaEventCreateWithFlags(&evFork, cudaEventDisableTiming);
    cudaEventCreateWithFlags(&evCSR, cudaEventDisableTiming);
    cudaEventCreateWithFlags(&evW1, cudaEventDisableTiming);
    cudaEventCreateWithFlags(&evW2, cudaEventDisableTiming);
    cudaFuncSetAttribute(gemm_kernel<true, 0>,  cudaFuncAttributeMaxDynamicSharedMemorySize, SMEM_GEMM);
    cudaFuncSetAttribute(gemm_kernel<false, 1>, cudaFuncAttributeMaxDynamicSharedMemorySize, SMEM_GEMM);
  }

  dim3 gemmGrid(HDIM / NTILE, MT_TILES);  // 2 x 74 = 148 CTAs
  dim3 wtGrid(KB / 32, HDIM / 32);        // 48 x 16
  int gateBlocks = (N_NODES + 7) / 8;
  int segBlocks = (NSEG + 7) / 8;
  int eBlocks = (N_EDGES + 255) / 256;

  // ---- fork side chain: CSR first (gates gather1), then Wt1, Wt2 ----
  cudaEventRecord(evFork, 0);
  cudaStreamWaitEvent(s2, evFork, 0);
  zeroraw2_kernel<<<(NSEG + 255) / 256, 256, 0, s2>>>();
  count_kernel<<<eBlocks, 256, 0, s2>>>(edge_index, edge_type);
  scan_kernel<<<1, 1024, 0, s2>>>();
  fill_kernel<<<eBlocks, 256, 0, s2>>>(edge_index, edge_type);
  cudaEventRecord(evCSR, s2);             // covers zero + CSR
  build_Wt_kernel<0><<<wtGrid, 256, 0, s2>>>(basis1, att1, root1);
  cudaEventRecord(evW1, s2);
  build_Wt_kernel<1><<<wtGrid, 256, 0, s2>>>(basis2, att2, root2);
  cudaEventRecord(evW2, s2);

  // ---- main chain ----
  gatesplit_kernel<<<gateBlocks, 256>>>(x, gw1);
  cudaStreamWaitEvent(0, evCSR, 0);
  gather_kernel<false, 1><<<segBlocks, 256>>>(x);
  cudaStreamWaitEvent(0, evW1, 0);
  gemm_kernel<true, 0><<<gemmGrid, GTHREADS, SMEM_GEMM>>>(bias1, gw2, nullptr);  // -> g_H + h16 + raw gates

  gather_kernel<true, 2><<<segBlocks, 256>>>(nullptr);
  cudaStreamWaitEvent(0, evW2, 0);
  gemm_kernel<false, 1><<<gemmGrid, GTHREADS, SMEM_GEMM>>>(bias2, nullptr, out);
}